// round 1
// baseline (speedup 1.0000x reference)
#include <cuda_runtime.h>
#include <math.h>

#define LSEQ 2048
#define DM 768
#define DI 1536
#define DS 16
#define DTR 48
#define DCONV 4
#define OUTD 128
#define PROJW (DTR + 2*DS)   // 80
#define NLAYER 2

// ---------------- scratch (device globals; no allocation allowed) ----------------
__device__ float g_x[LSEQ*DM];        // residual stream
__device__ float g_xn[LSEQ*DM];       // normed
__device__ float g_xz[LSEQ*2*DI];     // in_proj output (xin | res)
__device__ float g_xc[LSEQ*DI];       // conv+silu output (u)
__device__ float g_proj[LSEQ*PROJW];  // x_proj output (delta_r | B | C)
__device__ float g_delta[LSEQ*DI];    // softplus(dt_proj)
__device__ float g_y[LSEQ*DI];        // scan output * silu(res)

// ---------------- small kernels ----------------
__global__ void copy_kernel(const float* __restrict__ in, float* __restrict__ out, int n) {
    int i = blockIdx.x * blockDim.x + threadIdx.x;
    if (i < n) out[i] = in[i];
}

__global__ void rmsnorm_kernel(const float* __restrict__ x, const float* __restrict__ w,
                               float* __restrict__ out) {
    int l = blockIdx.x;
    const float* xr = x + (size_t)l * DM;
    __shared__ float red[8];
    __shared__ float s_r;
    float ss = 0.f;
    for (int i = threadIdx.x; i < DM; i += 256) { float v = xr[i]; ss += v * v; }
    #pragma unroll
    for (int o = 16; o; o >>= 1) ss += __shfl_xor_sync(0xffffffffu, ss, o);
    if ((threadIdx.x & 31) == 0) red[threadIdx.x >> 5] = ss;
    __syncthreads();
    if (threadIdx.x == 0) {
        float t = 0.f;
        #pragma unroll
        for (int i = 0; i < 8; i++) t += red[i];
        s_r = rsqrtf(t / DM + 1e-5f);
    }
    __syncthreads();
    float r = s_r;
    for (int i = threadIdx.x; i < DM; i += 256) out[(size_t)l * DM + i] = xr[i] * r * w[i];
}

__global__ void conv_silu_kernel(const float* __restrict__ xz, const float* __restrict__ w,
                                 const float* __restrict__ b, float* __restrict__ out) {
    int idx = blockIdx.x * blockDim.x + threadIdx.x;
    if (idx >= LSEQ * DI) return;
    int l = idx / DI, c = idx % DI;
    float acc = b[c];
    #pragma unroll
    for (int j = 0; j < DCONV; j++) {
        int ls = l - (DCONV - 1) + j;
        if (ls >= 0) acc += w[c * DCONV + j] * xz[(size_t)ls * (2 * DI) + c];
    }
    out[idx] = acc / (1.f + expf(-acc));   // silu
}

// selective scan: 16 lanes per channel (one per state), sequential over L
__global__ void scan_kernel(const float* __restrict__ delta, const float* __restrict__ u,
                            const float* __restrict__ proj, const float* __restrict__ xz,
                            const float* __restrict__ A_log, const float* __restrict__ Dv,
                            float* __restrict__ y) {
    int gid = blockIdx.x * blockDim.x + threadIdx.x;
    int d = gid >> 4;
    int n = gid & 15;
    if (d >= DI) return;
    float A = -expf(A_log[d * DS + n]);
    float Dd = Dv[d];
    float s = 0.f;
    for (int l = 0; l < LSEQ; l++) {
        float dl = delta[(size_t)l * DI + d];
        float ul = u[(size_t)l * DI + d];
        float Bn = proj[l * PROJW + DTR + n];
        float Cn = proj[l * PROJW + DTR + DS + n];
        float dA = expf(dl * A);
        s = dA * s + (dl * ul) * Bn;
        float v = s * Cn;
        v += __shfl_xor_sync(0xffffffffu, v, 8, 16);
        v += __shfl_xor_sync(0xffffffffu, v, 4, 16);
        v += __shfl_xor_sync(0xffffffffu, v, 2, 16);
        v += __shfl_xor_sync(0xffffffffu, v, 1, 16);
        if (n == 0) {
            float res = xz[(size_t)l * (2 * DI) + DI + d];
            float g = res / (1.f + expf(-res));
            y[(size_t)l * DI + d] = (v + ul * Dd) * g;
        }
    }
}

// ---------------- generic NT GEMM: C[M,N] = A[M,K] * B[N,K]^T (+ epilogue) ----------------
// mode 0: plain; mode 1: softplus(acc + bias[n]); mode 2: residual add (C += acc)
__global__ void __launch_bounds__(256)
gemm_nt(const float* __restrict__ A, int lda,
        const float* __restrict__ B, int ldb,
        float* __restrict__ C, int ldc,
        int M, int N, int K,
        const float* __restrict__ bias, int mode) {
    __shared__ float As[16][68];
    __shared__ float Bs[16][68];
    int t = threadIdx.x;
    int m0 = blockIdx.y * 64, n0 = blockIdx.x * 64;
    int tx = t & 15, ty = t >> 4;
    int lr = t >> 2;          // 0..63 tile row
    int lk = (t & 3) * 4;     // 0,4,8,12
    float acc[4][4] = {};
    for (int k0 = 0; k0 < K; k0 += 16) {
        float4 av = make_float4(0.f, 0.f, 0.f, 0.f);
        float4 bv = make_float4(0.f, 0.f, 0.f, 0.f);
        if (m0 + lr < M) av = *(const float4*)(A + (size_t)(m0 + lr) * lda + k0 + lk);
        if (n0 + lr < N) bv = *(const float4*)(B + (size_t)(n0 + lr) * ldb + k0 + lk);
        __syncthreads();
        As[lk + 0][lr] = av.x; As[lk + 1][lr] = av.y; As[lk + 2][lr] = av.z; As[lk + 3][lr] = av.w;
        Bs[lk + 0][lr] = bv.x; Bs[lk + 1][lr] = bv.y; Bs[lk + 2][lr] = bv.z; Bs[lk + 3][lr] = bv.w;
        __syncthreads();
        #pragma unroll
        for (int k = 0; k < 16; k++) {
            float4 a = *(const float4*)(&As[k][ty * 4]);
            float4 b = *(const float4*)(&Bs[k][tx * 4]);
            float avv[4] = {a.x, a.y, a.z, a.w};
            float bvv[4] = {b.x, b.y, b.z, b.w};
            #pragma unroll
            for (int i = 0; i < 4; i++)
                #pragma unroll
                for (int j = 0; j < 4; j++)
                    acc[i][j] += avv[i] * bvv[j];
        }
    }
    #pragma unroll
    for (int i = 0; i < 4; i++) {
        int m = m0 + ty * 4 + i;
        if (m >= M) continue;
        #pragma unroll
        for (int j = 0; j < 4; j++) {
            int n = n0 + tx * 4 + j;
            if (n >= N) continue;
            float v = acc[i][j];
            if (mode == 1) {
                v += bias[n];
                v = (v > 20.f) ? v : log1pf(expf(v));
            } else if (mode == 2) {
                v += C[(size_t)m * ldc + n];
            }
            C[(size_t)m * ldc + n] = v;
        }
    }
}

// ---------------- host orchestration ----------------
extern "C" void kernel_launch(void* const* d_in, const int* in_sizes, int n_in,
                              void* d_out, int out_size) {
    const float* x_in      = (const float*)d_in[0];
    const float* in_proj_w = (const float*)d_in[1];
    const float* conv_w    = (const float*)d_in[2];
    const float* conv_b    = (const float*)d_in[3];
    const float* x_proj_w  = (const float*)d_in[4];
    const float* dt_proj_w = (const float*)d_in[5];
    const float* dt_proj_b = (const float*)d_in[6];
    const float* A_log     = (const float*)d_in[7];
    const float* Dv        = (const float*)d_in[8];
    const float* out_proj_w= (const float*)d_in[9];
    const float* norm_w    = (const float*)d_in[10];
    const float* norm_f_w  = (const float*)d_in[11];
    const float* head_w    = (const float*)d_in[12];
    float* out = (float*)d_out;

    float *gx, *gxn, *gxz, *gxc, *gproj, *gdelta, *gy;
    cudaGetSymbolAddress((void**)&gx,     g_x);
    cudaGetSymbolAddress((void**)&gxn,    g_xn);
    cudaGetSymbolAddress((void**)&gxz,    g_xz);
    cudaGetSymbolAddress((void**)&gxc,    g_xc);
    cudaGetSymbolAddress((void**)&gproj,  g_proj);
    cudaGetSymbolAddress((void**)&gdelta, g_delta);
    cudaGetSymbolAddress((void**)&gy,     g_y);

    copy_kernel<<<(LSEQ * DM + 255) / 256, 256>>>(x_in, gx, LSEQ * DM);

    for (int i = 0; i < NLAYER; i++) {
        const float* ipw = in_proj_w  + (size_t)i * 2 * DI * DM;
        const float* cw  = conv_w     + (size_t)i * DI * DCONV;
        const float* cb  = conv_b     + (size_t)i * DI;
        const float* xpw = x_proj_w   + (size_t)i * PROJW * DI;
        const float* dtw = dt_proj_w  + (size_t)i * DI * DTR;
        const float* dtb = dt_proj_b  + (size_t)i * DI;
        const float* al  = A_log      + (size_t)i * DI * DS;
        const float* dv  = Dv         + (size_t)i * DI;
        const float* opw = out_proj_w + (size_t)i * DM * DI;
        const float* nw  = norm_w     + (size_t)i * DM;

        rmsnorm_kernel<<<LSEQ, 256>>>(gx, nw, gxn);

        // in_proj: (2048x768) x (3072x768)^T -> (2048x3072)
        gemm_nt<<<dim3(2 * DI / 64, LSEQ / 64), 256>>>(gxn, DM, ipw, DM, gxz, 2 * DI,
                                                       LSEQ, 2 * DI, DM, nullptr, 0);
        // conv + silu on xin half
        conv_silu_kernel<<<(LSEQ * DI + 255) / 256, 256>>>(gxz, cw, cb, gxc);

        // x_proj: (2048x1536) x (80x1536)^T -> (2048x80)
        gemm_nt<<<dim3((PROJW + 63) / 64, LSEQ / 64), 256>>>(gxc, DI, xpw, DI, gproj, PROJW,
                                                             LSEQ, PROJW, DI, nullptr, 0);
        // dt_proj + bias + softplus: (2048x48) x (1536x48)^T -> (2048x1536)
        gemm_nt<<<dim3(DI / 64, LSEQ / 64), 256>>>(gproj, PROJW, dtw, DTR, gdelta, DI,
                                                   LSEQ, DI, DTR, dtb, 1);
        // selective scan + gate
        scan_kernel<<<(DI * DS) / 256, 256>>>(gdelta, gxc, gproj, gxz, al, dv, gy);

        // out_proj + residual add into gx
        gemm_nt<<<dim3(DM / 64, LSEQ / 64), 256>>>(gy, DI, opw, DI, gx, DM,
                                                   LSEQ, DM, DI, nullptr, 2);
    }

    rmsnorm_kernel<<<LSEQ, 256>>>(gx, norm_f_w, gxn);
    // head: (2048x768) x (128x768)^T -> (2048x128)
    gemm_nt<<<dim3(OUTD / 64, LSEQ / 64), 256>>>(gxn, DM, head_w, DM, out, OUTD,
                                                 LSEQ, OUTD, DM, nullptr, 0);
}

// round 2
// speedup vs baseline: 1.1382x; 1.1382x over previous
#include <cuda_runtime.h>
#include <math.h>
#include <stdint.h>

#define LSEQ 2048
#define DM 768
#define DI 1536
#define DS 16
#define DTR 48
#define DCONV 4
#define OUTD 128
#define PROJW (DTR + 2*DS)   // 80
#define NLAYER 2

// ---------------- scratch ----------------
__device__ float g_x[LSEQ*DM];
__device__ float g_xn[LSEQ*DM];
__device__ float g_xz[LSEQ*2*DI];
__device__ float g_xc[LSEQ*DI];
__device__ float g_proj[LSEQ*PROJW];
__device__ float g_delta[LSEQ*DI];
__device__ float g_y[LSEQ*DI];

// ---------------- small kernels ----------------
__global__ void copy_kernel(const float* __restrict__ in, float* __restrict__ out, int n) {
    int i = blockIdx.x * blockDim.x + threadIdx.x;
    if (i < n) out[i] = in[i];
}

__global__ void rmsnorm_kernel(const float* __restrict__ x, const float* __restrict__ w,
                               float* __restrict__ out) {
    int l = blockIdx.x;
    const float* xr = x + (size_t)l * DM;
    __shared__ float red[8];
    __shared__ float s_r;
    float ss = 0.f;
    for (int i = threadIdx.x; i < DM; i += 256) { float v = xr[i]; ss += v * v; }
    #pragma unroll
    for (int o = 16; o; o >>= 1) ss += __shfl_xor_sync(0xffffffffu, ss, o);
    if ((threadIdx.x & 31) == 0) red[threadIdx.x >> 5] = ss;
    __syncthreads();
    if (threadIdx.x == 0) {
        float t = 0.f;
        #pragma unroll
        for (int i = 0; i < 8; i++) t += red[i];
        s_r = rsqrtf(t / DM + 1e-5f);
    }
    __syncthreads();
    float r = s_r;
    for (int i = threadIdx.x; i < DM; i += 256) out[(size_t)l * DM + i] = xr[i] * r * w[i];
}

__global__ void conv_silu_kernel(const float* __restrict__ xz, const float* __restrict__ w,
                                 const float* __restrict__ b, float* __restrict__ out) {
    int idx = blockIdx.x * blockDim.x + threadIdx.x;
    if (idx >= LSEQ * DI) return;
    int l = idx / DI, c = idx % DI;
    float acc = b[c];
    #pragma unroll
    for (int j = 0; j < DCONV; j++) {
        int ls = l - (DCONV - 1) + j;
        if (ls >= 0) acc += w[c * DCONV + j] * xz[(size_t)ls * (2 * DI) + c];
    }
    out[idx] = acc / (1.f + expf(-acc));
}

// selective scan: 16 lanes per channel (one per state), sequential over L
__global__ void scan_kernel(const float* __restrict__ delta, const float* __restrict__ u,
                            const float* __restrict__ proj, const float* __restrict__ xz,
                            const float* __restrict__ A_log, const float* __restrict__ Dv,
                            float* __restrict__ y) {
    int gid = blockIdx.x * blockDim.x + threadIdx.x;
    int d = gid >> 4;
    int n = gid & 15;
    if (d >= DI) return;
    float A = -expf(A_log[d * DS + n]);
    float Dd = Dv[d];
    float s = 0.f;
    #pragma unroll 4
    for (int l = 0; l < LSEQ; l++) {
        float dl = delta[(size_t)l * DI + d];
        float ul = u[(size_t)l * DI + d];
        float Bn = proj[l * PROJW + DTR + n];
        float Cn = proj[l * PROJW + DTR + DS + n];
        float dA = __expf(dl * A);
        s = dA * s + (dl * ul) * Bn;
        float v = s * Cn;
        v += __shfl_xor_sync(0xffffffffu, v, 8, 16);
        v += __shfl_xor_sync(0xffffffffu, v, 4, 16);
        v += __shfl_xor_sync(0xffffffffu, v, 2, 16);
        v += __shfl_xor_sync(0xffffffffu, v, 1, 16);
        if (n == 0) {
            float res = xz[(size_t)l * (2 * DI) + DI + d];
            float g = res / (1.f + expf(-res));
            y[(size_t)l * DI + d] = (v + ul * Dd) * g;
        }
    }
}

// ---------------- tf32 tensor-core GEMM ----------------
// C[M,N] = A[M,K] * B[N,K]^T (+ epilogue)
// mode 0: plain; mode 1: softplus(acc + bias[n]); mode 2: residual add
#define BM 128
#define BN 64
#define BKT 16

__device__ __forceinline__ uint32_t f2tf32(float x) {
    uint32_t r;
    asm("cvt.rna.tf32.f32 %0, %1;" : "=r"(r) : "f"(x));
    return r;
}

__device__ __forceinline__ void mma_tf32(float* d, const uint32_t* a, const uint32_t* b) {
    asm volatile(
        "mma.sync.aligned.m16n8k8.row.col.f32.tf32.tf32.f32 "
        "{%0,%1,%2,%3}, {%4,%5,%6,%7}, {%8,%9}, {%0,%1,%2,%3};"
        : "+f"(d[0]), "+f"(d[1]), "+f"(d[2]), "+f"(d[3])
        : "r"(a[0]), "r"(a[1]), "r"(a[2]), "r"(a[3]), "r"(b[0]), "r"(b[1]));
}

__global__ void __launch_bounds__(256)
gemm_tf32(const float* __restrict__ A, int lda,
          const float* __restrict__ B, int ldb,
          float* __restrict__ C, int ldc,
          int M, int N, int K,
          const float* __restrict__ bias, int mode) {
    // k-major smem, stride padded so stride % 32 == 4 -> conflict-free frag LDS
    __shared__ uint32_t As[2][BKT][BM + 4];
    __shared__ uint32_t Bs[2][BKT][BN + 4];

    int t = threadIdx.x;
    int m0 = blockIdx.y * BM, n0 = blockIdx.x * BN;

    // loaders
    int ar = t >> 2;            // 0..63
    int ak = (t & 3) * 4;       // 0,4,8,12

    // warps: 4 (m) x 2 (n)
    int wid = t >> 5;
    int wm = (wid & 3) * 32;
    int wn = (wid >> 2) * 32;
    int lane = t & 31;
    int g = lane >> 2;          // 0..7
    int tg = lane & 3;          // 0..3

    float acc[2][4][4];
    #pragma unroll
    for (int i = 0; i < 2; i++)
        #pragma unroll
        for (int j = 0; j < 4; j++)
            #pragma unroll
            for (int q = 0; q < 4; q++) acc[i][j][q] = 0.f;

    int nk = K / BKT;

    float4 av0, av1, bv;
    // prologue load k-tile 0
    {
        av0 = *(const float4*)(A + (size_t)(m0 + ar) * lda + ak);
        av1 = *(const float4*)(A + (size_t)(m0 + ar + 64) * lda + ak);
        bv = make_float4(0.f, 0.f, 0.f, 0.f);
        if (n0 + ar < N) bv = *(const float4*)(B + (size_t)(n0 + ar) * ldb + ak);
        As[0][ak + 0][ar] = f2tf32(av0.x); As[0][ak + 1][ar] = f2tf32(av0.y);
        As[0][ak + 2][ar] = f2tf32(av0.z); As[0][ak + 3][ar] = f2tf32(av0.w);
        As[0][ak + 0][ar + 64] = f2tf32(av1.x); As[0][ak + 1][ar + 64] = f2tf32(av1.y);
        As[0][ak + 2][ar + 64] = f2tf32(av1.z); As[0][ak + 3][ar + 64] = f2tf32(av1.w);
        Bs[0][ak + 0][ar] = f2tf32(bv.x); Bs[0][ak + 1][ar] = f2tf32(bv.y);
        Bs[0][ak + 2][ar] = f2tf32(bv.z); Bs[0][ak + 3][ar] = f2tf32(bv.w);
    }
    __syncthreads();

    for (int kt = 0; kt < nk; kt++) {
        int buf = kt & 1;
        bool has_next = (kt + 1 < nk);
        if (has_next) {
            int k0 = (kt + 1) * BKT;
            av0 = *(const float4*)(A + (size_t)(m0 + ar) * lda + k0 + ak);
            av1 = *(const float4*)(A + (size_t)(m0 + ar + 64) * lda + k0 + ak);
            bv = make_float4(0.f, 0.f, 0.f, 0.f);
            if (n0 + ar < N) bv = *(const float4*)(B + (size_t)(n0 + ar) * ldb + k0 + ak);
        }
        // compute 2 k8 sub-steps
        #pragma unroll
        for (int kk = 0; kk < BKT; kk += 8) {
            uint32_t af[2][4], bf[4][2];
            #pragma unroll
            for (int mt = 0; mt < 2; mt++) {
                int rm = wm + mt * 16;
                af[mt][0] = As[buf][kk + tg][rm + g];
                af[mt][1] = As[buf][kk + tg][rm + g + 8];
                af[mt][2] = As[buf][kk + tg + 4][rm + g];
                af[mt][3] = As[buf][kk + tg + 4][rm + g + 8];
            }
            #pragma unroll
            for (int nt = 0; nt < 4; nt++) {
                int nb = wn + nt * 8 + g;
                bf[nt][0] = Bs[buf][kk + tg][nb];
                bf[nt][1] = Bs[buf][kk + tg + 4][nb];
            }
            #pragma unroll
            for (int mt = 0; mt < 2; mt++)
                #pragma unroll
                for (int nt = 0; nt < 4; nt++)
                    mma_tf32(acc[mt][nt], af[mt], bf[nt]);
        }
        if (has_next) {
            int nb2 = buf ^ 1;
            As[nb2][ak + 0][ar] = f2tf32(av0.x); As[nb2][ak + 1][ar] = f2tf32(av0.y);
            As[nb2][ak + 2][ar] = f2tf32(av0.z); As[nb2][ak + 3][ar] = f2tf32(av0.w);
            As[nb2][ak + 0][ar + 64] = f2tf32(av1.x); As[nb2][ak + 1][ar + 64] = f2tf32(av1.y);
            As[nb2][ak + 2][ar + 64] = f2tf32(av1.z); As[nb2][ak + 3][ar + 64] = f2tf32(av1.w);
            Bs[nb2][ak + 0][ar] = f2tf32(bv.x); Bs[nb2][ak + 1][ar] = f2tf32(bv.y);
            Bs[nb2][ak + 2][ar] = f2tf32(bv.z); Bs[nb2][ak + 3][ar] = f2tf32(bv.w);
        }
        __syncthreads();
    }

    // epilogue
    #pragma unroll
    for (int mt = 0; mt < 2; mt++) {
        int rm = m0 + wm + mt * 16 + g;
        #pragma unroll
        for (int nt = 0; nt < 4; nt++) {
            int cn = n0 + wn + nt * 8 + 2 * tg;
            #pragma unroll
            for (int half = 0; half < 2; half++) {
                int r = rm + half * 8;
                #pragma unroll
                for (int c = 0; c < 2; c++) {
                    int n = cn + c;
                    if (n >= N) continue;
                    float v = acc[mt][nt][half * 2 + c];
                    if (mode == 1) {
                        v += bias[n];
                        v = (v > 20.f) ? v : log1pf(expf(v));
                    } else if (mode == 2) {
                        v += C[(size_t)r * ldc + n];
                    }
                    C[(size_t)r * ldc + n] = v;
                }
            }
        }
    }
}

// ---------------- host orchestration ----------------
extern "C" void kernel_launch(void* const* d_in, const int* in_sizes, int n_in,
                              void* d_out, int out_size) {
    const float* x_in      = (const float*)d_in[0];
    const float* in_proj_w = (const float*)d_in[1];
    const float* conv_w    = (const float*)d_in[2];
    const float* conv_b    = (const float*)d_in[3];
    const float* x_proj_w  = (const float*)d_in[4];
    const float* dt_proj_w = (const float*)d_in[5];
    const float* dt_proj_b = (const float*)d_in[6];
    const float* A_log     = (const float*)d_in[7];
    const float* Dv        = (const float*)d_in[8];
    const float* out_proj_w= (const float*)d_in[9];
    const float* norm_w    = (const float*)d_in[10];
    const float* norm_f_w  = (const float*)d_in[11];
    const float* head_w    = (const float*)d_in[12];
    float* out = (float*)d_out;

    float *gx, *gxn, *gxz, *gxc, *gproj, *gdelta, *gy;
    cudaGetSymbolAddress((void**)&gx,     g_x);
    cudaGetSymbolAddress((void**)&gxn,    g_xn);
    cudaGetSymbolAddress((void**)&gxz,    g_xz);
    cudaGetSymbolAddress((void**)&gxc,    g_xc);
    cudaGetSymbolAddress((void**)&gproj,  g_proj);
    cudaGetSymbolAddress((void**)&gdelta, g_delta);
    cudaGetSymbolAddress((void**)&gy,     g_y);

    copy_kernel<<<(LSEQ * DM + 255) / 256, 256>>>(x_in, gx, LSEQ * DM);

    for (int i = 0; i < NLAYER; i++) {
        const float* ipw = in_proj_w  + (size_t)i * 2 * DI * DM;
        const float* cw  = conv_w     + (size_t)i * DI * DCONV;
        const float* cb  = conv_b     + (size_t)i * DI;
        const float* xpw = x_proj_w   + (size_t)i * PROJW * DI;
        const float* dtw = dt_proj_w  + (size_t)i * DI * DTR;
        const float* dtb = dt_proj_b  + (size_t)i * DI;
        const float* al  = A_log      + (size_t)i * DI * DS;
        const float* dv  = Dv         + (size_t)i * DI;
        const float* opw = out_proj_w + (size_t)i * DM * DI;
        const float* nw  = norm_w     + (size_t)i * DM;

        rmsnorm_kernel<<<LSEQ, 256>>>(gx, nw, gxn);

        // in_proj: (2048x768) x (3072x768)^T
        gemm_tf32<<<dim3(2 * DI / BN, LSEQ / BM), 256>>>(gxn, DM, ipw, DM, gxz, 2 * DI,
                                                         LSEQ, 2 * DI, DM, nullptr, 0);
        conv_silu_kernel<<<(LSEQ * DI + 255) / 256, 256>>>(gxz, cw, cb, gxc);

        // x_proj: (2048x1536) x (80x1536)^T
        gemm_tf32<<<dim3((PROJW + BN - 1) / BN, LSEQ / BM), 256>>>(gxc, DI, xpw, DI, gproj, PROJW,
                                                                   LSEQ, PROJW, DI, nullptr, 0);
        // dt_proj + bias + softplus: (2048x48) x (1536x48)^T
        gemm_tf32<<<dim3(DI / BN, LSEQ / BM), 256>>>(gproj, PROJW, dtw, DTR, gdelta, DI,
                                                     LSEQ, DI, DTR, dtb, 1);
        scan_kernel<<<(DI * DS) / 256, 256>>>(gdelta, gxc, gproj, gxz, al, dv, gy);

        // out_proj + residual add
        gemm_tf32<<<dim3(DM / BN, LSEQ / BM), 256>>>(gy, DI, opw, DI, gx, DM,
                                                     LSEQ, DM, DI, nullptr, 2);
    }

    rmsnorm_kernel<<<LSEQ, 256>>>(gx, norm_f_w, gxn);
    gemm_tf32<<<dim3(OUTD / BN, LSEQ / BM), 256>>>(gxn, DM, head_w, DM, out, OUTD,
                                                   LSEQ, OUTD, DM, nullptr, 0);
}

// round 4
// speedup vs baseline: 1.3540x; 1.1897x over previous
#include <cuda_runtime.h>
#include <math.h>
#include <stdint.h>

#define LSEQ 2048
#define DM 768
#define DI 1536
#define DS 16
#define DTR 48
#define DCONV 4
#define OUTD 128
#define PROJW (DTR + 2*DS)   // 80
#define NLAYER 2

// ---------------- scratch ----------------
__device__ float g_x[LSEQ*DM];
__device__ float g_xn[LSEQ*DM];
__device__ float g_xz[LSEQ*2*DI];
__device__ float g_xc[LSEQ*DI];
__device__ float g_proj[LSEQ*PROJW];
__device__ float g_delta[LSEQ*DI];
__device__ float g_y[LSEQ*DI];

// ---------------- packed f32x2 helpers ----------------
__device__ __forceinline__ void ffma2(unsigned long long& d, unsigned long long a, unsigned long long b) {
    asm("fma.rn.f32x2 %0, %1, %2, %0;" : "+l"(d) : "l"(a), "l"(b));
}
__device__ __forceinline__ unsigned long long pack2(float lo, float hi) {
    unsigned long long p;
    asm("mov.b64 %0, {%1, %2};" : "=l"(p) : "f"(lo), "f"(hi));
    return p;
}
__device__ __forceinline__ void unpack2(unsigned long long p, float& lo, float& hi) {
    asm("mov.b64 {%0, %1}, %2;" : "=f"(lo), "=f"(hi) : "l"(p));
}

// ---------------- FFMA2 SIMT GEMM ----------------
// C[M,N] = A[M,K] * B[N,K]^T (+ epilogue)
// mode 0: plain; 1: softplus(acc + bias[n]); 2: C += acc (residual)
// M % 128 == 0, K % 8 == 0. N arbitrary (guarded).
#define GBM 128
#define GBN 128
#define GBK 8

__global__ void __launch_bounds__(256, 2)
gemm_ffma2(const float* __restrict__ A, int lda,
           const float* __restrict__ B, int ldb,
           float* __restrict__ C, int ldc,
           int N, int K, const float* __restrict__ bias, int mode) {
    __shared__ float As[2][GBK][GBM + 4];
    __shared__ float Bs[2][GBK][GBN + 4];

    int t = threadIdx.x;
    int m0 = blockIdx.y * GBM, n0 = blockIdx.x * GBN;
    int ty = t >> 4, tx = t & 15;          // 16x16 thread grid, 8x8 per thread
    int row = t >> 1;                       // 0..127 (loader row)
    int kq = (t & 1) * 4;                   // 0 or 4

    // 32 packed accumulators: acc[j][n] holds C[m0+ty*8+2j (+1)][n0+tx*8+n]
    unsigned long long acc[4][8];
    #pragma unroll
    for (int j = 0; j < 4; j++)
        #pragma unroll
        for (int n = 0; n < 8; n++) acc[j][n] = 0ull;

    int nk = K / GBK;

    const float* Aptr = A + (size_t)(m0 + row) * lda + kq;
    const float* Bptr = B + (size_t)(n0 + row) * ldb + kq;
    bool bvalid = (n0 + row) < N;

    float4 av = *(const float4*)(Aptr);
    float4 bv = bvalid ? *(const float4*)(Bptr) : make_float4(0.f, 0.f, 0.f, 0.f);
    {
        As[0][kq + 0][row] = av.x; As[0][kq + 1][row] = av.y;
        As[0][kq + 2][row] = av.z; As[0][kq + 3][row] = av.w;
        Bs[0][kq + 0][row] = bv.x; Bs[0][kq + 1][row] = bv.y;
        Bs[0][kq + 2][row] = bv.z; Bs[0][kq + 3][row] = bv.w;
    }
    __syncthreads();

    for (int kt = 0; kt < nk; kt++) {
        int buf = kt & 1;
        if (kt + 1 < nk) {
            int k0 = (kt + 1) * GBK;
            av = *(const float4*)(Aptr + k0);
            bv = bvalid ? *(const float4*)(Bptr + k0) : make_float4(0.f, 0.f, 0.f, 0.f);
        }
        #pragma unroll
        for (int k = 0; k < GBK; k++) {
            float4 a0 = *(const float4*)(&As[buf][k][ty * 8]);
            float4 a1 = *(const float4*)(&As[buf][k][ty * 8 + 4]);
            float4 b0 = *(const float4*)(&Bs[buf][k][tx * 8]);
            float4 b1 = *(const float4*)(&Bs[buf][k][tx * 8 + 4]);
            unsigned long long ap[4];
            ap[0] = pack2(a0.x, a0.y); ap[1] = pack2(a0.z, a0.w);
            ap[2] = pack2(a1.x, a1.y); ap[3] = pack2(a1.z, a1.w);
            float bb[8] = {b0.x, b0.y, b0.z, b0.w, b1.x, b1.y, b1.z, b1.w};
            #pragma unroll
            for (int n = 0; n < 8; n++) {
                unsigned long long bd = pack2(bb[n], bb[n]);
                #pragma unroll
                for (int j = 0; j < 4; j++) ffma2(acc[j][n], ap[j], bd);
            }
        }
        if (kt + 1 < nk) {
            int nb = buf ^ 1;
            As[nb][kq + 0][row] = av.x; As[nb][kq + 1][row] = av.y;
            As[nb][kq + 2][row] = av.z; As[nb][kq + 3][row] = av.w;
            Bs[nb][kq + 0][row] = bv.x; Bs[nb][kq + 1][row] = bv.y;
            Bs[nb][kq + 2][row] = bv.z; Bs[nb][kq + 3][row] = bv.w;
            __syncthreads();
        }
    }

    // epilogue: each thread writes 8 rows x 8 cols
    int nbase = n0 + tx * 8;
    bool fullN = (n0 + GBN) <= N;
    #pragma unroll
    for (int j = 0; j < 4; j++) {
        #pragma unroll
        for (int half = 0; half < 2; half++) {
            int m = m0 + ty * 8 + 2 * j + half;
            float v[8];
            #pragma unroll
            for (int n = 0; n < 8; n++) {
                float lo, hi;
                unpack2(acc[j][n], lo, hi);
                v[n] = half ? hi : lo;
            }
            float* crow = C + (size_t)m * ldc + nbase;
            if (mode == 0) {
                if (fullN) {
                    *(float4*)(crow) = make_float4(v[0], v[1], v[2], v[3]);
                    *(float4*)(crow + 4) = make_float4(v[4], v[5], v[6], v[7]);
                } else {
                    #pragma unroll
                    for (int n = 0; n < 8; n++) if (nbase + n < N) crow[n] = v[n];
                }
            } else if (mode == 1) {
                #pragma unroll
                for (int n = 0; n < 8; n++) {
                    float w = v[n] + bias[nbase + n];
                    v[n] = (w > 20.f) ? w : log1pf(__expf(w));
                }
                *(float4*)(crow) = make_float4(v[0], v[1], v[2], v[3]);
                *(float4*)(crow + 4) = make_float4(v[4], v[5], v[6], v[7]);
            } else { // residual add
                float4 c0 = *(const float4*)(crow);
                float4 c1 = *(const float4*)(crow + 4);
                *(float4*)(crow) = make_float4(v[0] + c0.x, v[1] + c0.y, v[2] + c0.z, v[3] + c0.w);
                *(float4*)(crow + 4) = make_float4(v[4] + c1.x, v[5] + c1.y, v[6] + c1.z, v[7] + c1.w);
            }
        }
    }
}

// ---------------- small kernels ----------------
__global__ void copy_kernel(const float* __restrict__ in, float* __restrict__ out, int n) {
    int i = blockIdx.x * blockDim.x + threadIdx.x;
    if (i < n) out[i] = in[i];
}

__global__ void rmsnorm_kernel(const float* __restrict__ x, const float* __restrict__ w,
                               float* __restrict__ out) {
    int l = blockIdx.x;
    const float* xr = x + (size_t)l * DM;
    __shared__ float red[8];
    __shared__ float s_r;
    float ss = 0.f;
    for (int i = threadIdx.x; i < DM; i += 256) { float v = xr[i]; ss += v * v; }
    #pragma unroll
    for (int o = 16; o; o >>= 1) ss += __shfl_xor_sync(0xffffffffu, ss, o);
    if ((threadIdx.x & 31) == 0) red[threadIdx.x >> 5] = ss;
    __syncthreads();
    if (threadIdx.x == 0) {
        float t = 0.f;
        #pragma unroll
        for (int i = 0; i < 8; i++) t += red[i];
        s_r = rsqrtf(t / DM + 1e-5f);
    }
    __syncthreads();
    float r = s_r;
    for (int i = threadIdx.x; i < DM; i += 256) out[(size_t)l * DM + i] = xr[i] * r * w[i];
}

__global__ void conv_silu_kernel(const float* __restrict__ xz, const float* __restrict__ w,
                                 const float* __restrict__ b, float* __restrict__ out) {
    int idx = blockIdx.x * blockDim.x + threadIdx.x;
    if (idx >= LSEQ * DI) return;
    int l = idx / DI, c = idx % DI;
    float acc = b[c];
    #pragma unroll
    for (int j = 0; j < DCONV; j++) {
        int ls = l - (DCONV - 1) + j;
        if (ls >= 0) acc += w[c * DCONV + j] * xz[(size_t)ls * (2 * DI) + c];
    }
    out[idx] = acc / (1.f + __expf(-acc));
}

// selective scan: 16 lanes per channel, explicit prefetch for MLP
__global__ void scan_kernel(const float* __restrict__ delta, const float* __restrict__ u,
                            const float* __restrict__ proj, const float* __restrict__ xz,
                            const float* __restrict__ A_log, const float* __restrict__ Dv,
                            float* __restrict__ y) {
    int gid = blockIdx.x * blockDim.x + threadIdx.x;
    int d = gid >> 4;
    int n = gid & 15;
    if (d >= DI) return;
    float A = -__expf(A_log[d * DS + n]);
    float Dd = Dv[d];
    float s = 0.f;
    float p_dl = delta[d];
    float p_ul = u[d];
    float p_B  = proj[DTR + n];
    float p_C  = proj[DTR + DS + n];
    float p_res = xz[DI + d];
    for (int l = 0; l < LSEQ; l++) {
        float dl = p_dl, ul = p_ul, Bn = p_B, Cn = p_C, res = p_res;
        if (l + 1 < LSEQ) {
            size_t o = (size_t)(l + 1) * DI + d;
            p_dl = delta[o];
            p_ul = u[o];
            p_B  = proj[(l + 1) * PROJW + DTR + n];
            p_C  = proj[(l + 1) * PROJW + DTR + DS + n];
            p_res = xz[(size_t)(l + 1) * (2 * DI) + DI + d];
        }
        float dA = __expf(dl * A);
        s = fmaf(dA, s, (dl * ul) * Bn);
        float v = s * Cn;
        v += __shfl_xor_sync(0xffffffffu, v, 8, 16);
        v += __shfl_xor_sync(0xffffffffu, v, 4, 16);
        v += __shfl_xor_sync(0xffffffffu, v, 2, 16);
        v += __shfl_xor_sync(0xffffffffu, v, 1, 16);
        if (n == 0) {
            float g = res / (1.f + __expf(-res));
            y[(size_t)l * DI + d] = (v + ul * Dd) * g;
        }
    }
}

// ---------------- host orchestration ----------------
extern "C" void kernel_launch(void* const* d_in, const int* in_sizes, int n_in,
                              void* d_out, int out_size) {
    const float* x_in      = (const float*)d_in[0];
    const float* in_proj_w = (const float*)d_in[1];
    const float* conv_w    = (const float*)d_in[2];
    const float* conv_b    = (const float*)d_in[3];
    const float* x_proj_w  = (const float*)d_in[4];
    const float* dt_proj_w = (const float*)d_in[5];
    const float* dt_proj_b = (const float*)d_in[6];
    const float* A_log     = (const float*)d_in[7];
    const float* Dv        = (const float*)d_in[8];
    const float* out_proj_w= (const float*)d_in[9];
    const float* norm_w    = (const float*)d_in[10];
    const float* norm_f_w  = (const float*)d_in[11];
    const float* head_w    = (const float*)d_in[12];
    float* out = (float*)d_out;

    float *gx, *gxn, *gxz, *gxc, *gproj, *gdelta, *gy;
    cudaGetSymbolAddress((void**)&gx,     g_x);
    cudaGetSymbolAddress((void**)&gxn,    g_xn);
    cudaGetSymbolAddress((void**)&gxz,    g_xz);
    cudaGetSymbolAddress((void**)&gxc,    g_xc);
    cudaGetSymbolAddress((void**)&gproj,  g_proj);
    cudaGetSymbolAddress((void**)&gdelta, g_delta);
    cudaGetSymbolAddress((void**)&gy,     g_y);

    copy_kernel<<<(LSEQ * DM + 255) / 256, 256>>>(x_in, gx, LSEQ * DM);

    for (int i = 0; i < NLAYER; i++) {
        const float* ipw = in_proj_w  + (size_t)i * 2 * DI * DM;
        const float* cw  = conv_w     + (size_t)i * DI * DCONV;
        const float* cb  = conv_b     + (size_t)i * DI;
        const float* xpw = x_proj_w   + (size_t)i * PROJW * DI;
        const float* dtw = dt_proj_w  + (size_t)i * DI * DTR;
        const float* dtb = dt_proj_b  + (size_t)i * DI;
        const float* al  = A_log      + (size_t)i * DI * DS;
        const float* dv  = Dv         + (size_t)i * DI;
        const float* opw = out_proj_w + (size_t)i * DM * DI;
        const float* nw  = norm_w     + (size_t)i * DM;

        rmsnorm_kernel<<<LSEQ, 256>>>(gx, nw, gxn);

        // in_proj: (2048x768) x (3072x768)^T
        gemm_ffma2<<<dim3(2 * DI / GBN, LSEQ / GBM), 256>>>(
            gxn, DM, ipw, DM, gxz, 2 * DI, 2 * DI, DM, nullptr, 0);
        conv_silu_kernel<<<(LSEQ * DI + 255) / 256, 256>>>(gxz, cw, cb, gxc);

        // x_proj: (2048x1536) x (80x1536)^T -> N=80 (guarded)
        gemm_ffma2<<<dim3(1, LSEQ / GBM), 256>>>(
            gxc, DI, xpw, DI, gproj, PROJW, PROJW, DI, nullptr, 0);
        // dt_proj + bias + softplus: (2048x80[48 used]) x (1536x48)^T
        gemm_ffma2<<<dim3(DI / GBN, LSEQ / GBM), 256>>>(
            gproj, PROJW, dtw, DTR, gdelta, DI, DI, DTR, dtb, 1);
        scan_kernel<<<(DI * DS) / 256, 256>>>(gdelta, gxc, gproj, gxz, al, dv, gy);

        // out_proj + residual add
        gemm_ffma2<<<dim3(DM / GBN, LSEQ / GBM), 256>>>(
            gy, DI, opw, DI, gx, DM, DM, DI, nullptr, 2);
    }

    rmsnorm_kernel<<<LSEQ, 256>>>(gx, norm_f_w, gxn);
    gemm_ffma2<<<dim3(OUTD / GBN, LSEQ / GBM), 256>>>(
        gxn, DM, head_w, DM, out, OUTD, OUTD, DM, nullptr, 0);
}

// round 5
// speedup vs baseline: 1.5815x; 1.1680x over previous
#include <cuda_runtime.h>
#include <math.h>
#include <stdint.h>

#define LSEQ 2048
#define DM 768
#define DI 1536
#define DS 16
#define DTR 48
#define DCONV 4
#define OUTD 128
#define PROJW (DTR + 2*DS)   // 80
#define NLAYER 2
#define XSPLIT 8             // split-K factor for x_proj

// ---------------- scratch ----------------
__device__ float g_x[LSEQ*DM];
__device__ float g_xn[LSEQ*DM];
__device__ float g_xz[LSEQ*2*DI];
__device__ float g_xc[LSEQ*DI];
__device__ float g_proj[LSEQ*PROJW];
__device__ float g_projp[XSPLIT*LSEQ*PROJW];   // split-K partials
__device__ float g_delta[LSEQ*DI];
__device__ float g_y[LSEQ*DI];

// ---------------- packed f32x2 helpers ----------------
__device__ __forceinline__ void ffma2(unsigned long long& d, unsigned long long a, unsigned long long b) {
    asm("fma.rn.f32x2 %0, %1, %2, %0;" : "+l"(d) : "l"(a), "l"(b));
}
__device__ __forceinline__ unsigned long long pack2(float lo, float hi) {
    unsigned long long p;
    asm("mov.b64 %0, {%1, %2};" : "=l"(p) : "f"(lo), "f"(hi));
    return p;
}
__device__ __forceinline__ void unpack2(unsigned long long p, float& lo, float& hi) {
    asm("mov.b64 {%0, %1}, %2;" : "=f"(lo), "=f"(hi) : "l"(p));
}

// ---------------- FFMA2 SIMT GEMM ----------------
// C[M,N] = A[M,K] * B[N,K]^T (+ epilogue)
// mode 0: plain; 1: softplus(acc + bias[n]); 2: C += acc (residual)
// If kchunk > 0: this block handles K-range [blockIdx.z*kchunk, +kchunk) and
// writes to C + blockIdx.z*czstride (mode must be 0).
#define GBM 128
#define GBN 128
#define GBK 8

__global__ void __launch_bounds__(256, 1)
gemm_ffma2(const float* __restrict__ A, int lda,
           const float* __restrict__ B, int ldb,
           float* __restrict__ C, int ldc,
           int N, int K, const float* __restrict__ bias, int mode,
           int kchunk, size_t czstride) {
    __shared__ float As[2][GBK][GBM + 4];
    __shared__ float Bs[2][GBK][GBN + 4];

    int t = threadIdx.x;
    int m0 = blockIdx.y * GBM, n0 = blockIdx.x * GBN;
    int ty = t >> 4, tx = t & 15;
    int row = t >> 1;                       // 0..127 loader row
    int kq = (t & 1) * 4;                   // 0 or 4

    int kbeg = 0, kend = K;
    if (kchunk > 0) {
        kbeg = blockIdx.z * kchunk;
        kend = kbeg + kchunk;
        if (kend > K) kend = K;
        C += (size_t)blockIdx.z * czstride;
    }

    // acc[i][n]: i = m-pair index (pairs: ty*4+0/1, ty*4+2/3, 64+ty*4+0/1, 64+ty*4+2/3)
    //            n = col index (n<4: n0+tx*4+n ; n>=4: n0+64+tx*4+(n-4))
    unsigned long long acc[4][8];
    #pragma unroll
    for (int i = 0; i < 4; i++)
        #pragma unroll
        for (int n = 0; n < 8; n++) acc[i][n] = 0ull;

    int nk = (kend - kbeg) / GBK;

    const float* Aptr = A + (size_t)(m0 + row) * lda + kbeg + kq;
    const float* Bptr = B + (size_t)(n0 + row) * ldb + kbeg + kq;
    bool bvalid = (n0 + row) < N;

    float4 av = *(const float4*)(Aptr);
    float4 bv = bvalid ? *(const float4*)(Bptr) : make_float4(0.f, 0.f, 0.f, 0.f);
    As[0][kq + 0][row] = av.x; As[0][kq + 1][row] = av.y;
    As[0][kq + 2][row] = av.z; As[0][kq + 3][row] = av.w;
    Bs[0][kq + 0][row] = bv.x; Bs[0][kq + 1][row] = bv.y;
    Bs[0][kq + 2][row] = bv.z; Bs[0][kq + 3][row] = bv.w;
    __syncthreads();

    for (int kt = 0; kt < nk; kt++) {
        int buf = kt & 1;
        if (kt + 1 < nk) {
            int k0 = (kt + 1) * GBK;
            av = *(const float4*)(Aptr + k0);
            bv = bvalid ? *(const float4*)(Bptr + k0) : make_float4(0.f, 0.f, 0.f, 0.f);
        }
        #pragma unroll
        for (int k = 0; k < GBK; k++) {
            float4 a0 = *(const float4*)(&As[buf][k][ty * 4]);
            float4 a1 = *(const float4*)(&As[buf][k][64 + ty * 4]);
            float4 b0 = *(const float4*)(&Bs[buf][k][tx * 4]);
            float4 b1 = *(const float4*)(&Bs[buf][k][64 + tx * 4]);
            unsigned long long ap[4];
            ap[0] = pack2(a0.x, a0.y); ap[1] = pack2(a0.z, a0.w);
            ap[2] = pack2(a1.x, a1.y); ap[3] = pack2(a1.z, a1.w);
            float bb[8] = {b0.x, b0.y, b0.z, b0.w, b1.x, b1.y, b1.z, b1.w};
            #pragma unroll
            for (int n = 0; n < 8; n++) {
                unsigned long long bd = pack2(bb[n], bb[n]);
                #pragma unroll
                for (int i = 0; i < 4; i++) ffma2(acc[i][n], ap[i], bd);
            }
        }
        if (kt + 1 < nk) {
            int nb = buf ^ 1;
            As[nb][kq + 0][row] = av.x; As[nb][kq + 1][row] = av.y;
            As[nb][kq + 2][row] = av.z; As[nb][kq + 3][row] = av.w;
            Bs[nb][kq + 0][row] = bv.x; Bs[nb][kq + 1][row] = bv.y;
            Bs[nb][kq + 2][row] = bv.z; Bs[nb][kq + 3][row] = bv.w;
            __syncthreads();
        }
    }

    // epilogue: 8 rows x (4 + 4) cols per thread
    bool fullN = (n0 + GBN) <= N;
    #pragma unroll
    for (int i = 0; i < 4; i++) {
        #pragma unroll
        for (int half = 0; half < 2; half++) {
            int m = m0 + ((i < 2) ? (ty * 4 + i * 2 + half) : (64 + ty * 4 + (i - 2) * 2 + half));
            float v[8];
            #pragma unroll
            for (int n = 0; n < 8; n++) {
                float lo, hi;
                unpack2(acc[i][n], lo, hi);
                v[n] = half ? hi : lo;
            }
            int nb0 = n0 + tx * 4;
            int nb1 = n0 + 64 + tx * 4;
            float* c0 = C + (size_t)m * ldc + nb0;
            float* c1 = C + (size_t)m * ldc + nb1;
            if (mode == 1) {
                #pragma unroll
                for (int n = 0; n < 4; n++) {
                    float w0 = v[n] + bias[nb0 + n];
                    v[n] = (w0 > 20.f) ? w0 : log1pf(__expf(w0));
                    float w1 = v[n + 4] + bias[nb1 + n];
                    v[n + 4] = (w1 > 20.f) ? w1 : log1pf(__expf(w1));
                }
                *(float4*)c0 = make_float4(v[0], v[1], v[2], v[3]);
                *(float4*)c1 = make_float4(v[4], v[5], v[6], v[7]);
            } else if (mode == 2) {
                float4 o0 = *(const float4*)c0;
                float4 o1 = *(const float4*)c1;
                *(float4*)c0 = make_float4(v[0] + o0.x, v[1] + o0.y, v[2] + o0.z, v[3] + o0.w);
                *(float4*)c1 = make_float4(v[4] + o1.x, v[5] + o1.y, v[6] + o1.z, v[7] + o1.w);
            } else {
                if (fullN) {
                    *(float4*)c0 = make_float4(v[0], v[1], v[2], v[3]);
                    *(float4*)c1 = make_float4(v[4], v[5], v[6], v[7]);
                } else {
                    #pragma unroll
                    for (int n = 0; n < 4; n++) {
                        if (nb0 + n < N) c0[n] = v[n];
                        if (nb1 + n < N) c1[n] = v[n + 4];
                    }
                }
            }
        }
    }
}

// reduce split-K partials: out[i] = sum_z partial[z*stride + i]
__global__ void reduce_splitk(const float* __restrict__ part, float* __restrict__ out,
                              int n, int nz, size_t stride) {
    int i = blockIdx.x * blockDim.x + threadIdx.x;
    if (i >= n) return;
    float s = 0.f;
    #pragma unroll
    for (int z = 0; z < XSPLIT; z++) s += part[(size_t)z * stride + i];
    out[i] = s;
}

// ---------------- small kernels ----------------
__global__ void copy_kernel(const float* __restrict__ in, float* __restrict__ out, int n) {
    int i = blockIdx.x * blockDim.x + threadIdx.x;
    if (i < n) out[i] = in[i];
}

__global__ void rmsnorm_kernel(const float* __restrict__ x, const float* __restrict__ w,
                               float* __restrict__ out) {
    int l = blockIdx.x;
    const float* xr = x + (size_t)l * DM;
    __shared__ float red[8];
    __shared__ float s_r;
    float ss = 0.f;
    for (int i = threadIdx.x; i < DM; i += 256) { float v = xr[i]; ss += v * v; }
    #pragma unroll
    for (int o = 16; o; o >>= 1) ss += __shfl_xor_sync(0xffffffffu, ss, o);
    if ((threadIdx.x & 31) == 0) red[threadIdx.x >> 5] = ss;
    __syncthreads();
    if (threadIdx.x == 0) {
        float t = 0.f;
        #pragma unroll
        for (int i = 0; i < 8; i++) t += red[i];
        s_r = rsqrtf(t / DM + 1e-5f);
    }
    __syncthreads();
    float r = s_r;
    for (int i = threadIdx.x; i < DM; i += 256) out[(size_t)l * DM + i] = xr[i] * r * w[i];
}

__global__ void conv_silu_kernel(const float* __restrict__ xz, const float* __restrict__ w,
                                 const float* __restrict__ b, float* __restrict__ out) {
    int idx = blockIdx.x * blockDim.x + threadIdx.x;
    if (idx >= LSEQ * DI) return;
    int l = idx / DI, c = idx % DI;
    float acc = b[c];
    #pragma unroll
    for (int j = 0; j < DCONV; j++) {
        int ls = l - (DCONV - 1) + j;
        if (ls >= 0) acc += w[c * DCONV + j] * xz[(size_t)ls * (2 * DI) + c];
    }
    out[idx] = acc / (1.f + __expf(-acc));
}

// selective scan: 16 lanes per channel (one per state)
__global__ void scan_kernel(const float* __restrict__ delta, const float* __restrict__ u,
                            const float* __restrict__ proj, const float* __restrict__ xz,
                            const float* __restrict__ A_log, const float* __restrict__ Dv,
                            float* __restrict__ y) {
    int gid = blockIdx.x * blockDim.x + threadIdx.x;
    int d = gid >> 4;
    int n = gid & 15;
    if (d >= DI) return;
    float A = -__expf(A_log[d * DS + n]);
    float Dd = Dv[d];
    float s = 0.f;
    float p_dl = delta[d];
    float p_ul = u[d];
    float p_B  = proj[DTR + n];
    float p_C  = proj[DTR + DS + n];
    float p_res = xz[DI + d];
    for (int l = 0; l < LSEQ; l++) {
        float dl = p_dl, ul = p_ul, Bn = p_B, Cn = p_C, res = p_res;
        if (l + 1 < LSEQ) {
            size_t o = (size_t)(l + 1) * DI + d;
            p_dl = delta[o];
            p_ul = u[o];
            p_B  = proj[(l + 1) * PROJW + DTR + n];
            p_C  = proj[(l + 1) * PROJW + DTR + DS + n];
            p_res = xz[(size_t)(l + 1) * (2 * DI) + DI + d];
        }
        float dA = __expf(dl * A);
        s = fmaf(dA, s, (dl * ul) * Bn);
        float v = s * Cn;
        v += __shfl_xor_sync(0xffffffffu, v, 8, 16);
        v += __shfl_xor_sync(0xffffffffu, v, 4, 16);
        v += __shfl_xor_sync(0xffffffffu, v, 2, 16);
        v += __shfl_xor_sync(0xffffffffu, v, 1, 16);
        if (n == 0) {
            float g = res / (1.f + __expf(-res));
            y[(size_t)l * DI + d] = (v + ul * Dd) * g;
        }
    }
}

// ---------------- host orchestration ----------------
extern "C" void kernel_launch(void* const* d_in, const int* in_sizes, int n_in,
                              void* d_out, int out_size) {
    const float* x_in      = (const float*)d_in[0];
    const float* in_proj_w = (const float*)d_in[1];
    const float* conv_w    = (const float*)d_in[2];
    const float* conv_b    = (const float*)d_in[3];
    const float* x_proj_w  = (const float*)d_in[4];
    const float* dt_proj_w = (const float*)d_in[5];
    const float* dt_proj_b = (const float*)d_in[6];
    const float* A_log     = (const float*)d_in[7];
    const float* Dv        = (const float*)d_in[8];
    const float* out_proj_w= (const float*)d_in[9];
    const float* norm_w    = (const float*)d_in[10];
    const float* norm_f_w  = (const float*)d_in[11];
    const float* head_w    = (const float*)d_in[12];
    float* out = (float*)d_out;

    float *gx, *gxn, *gxz, *gxc, *gproj, *gprojp, *gdelta, *gy;
    cudaGetSymbolAddress((void**)&gx,     g_x);
    cudaGetSymbolAddress((void**)&gxn,    g_xn);
    cudaGetSymbolAddress((void**)&gxz,    g_xz);
    cudaGetSymbolAddress((void**)&gxc,    g_xc);
    cudaGetSymbolAddress((void**)&gproj,  g_proj);
    cudaGetSymbolAddress((void**)&gprojp, g_projp);
    cudaGetSymbolAddress((void**)&gdelta, g_delta);
    cudaGetSymbolAddress((void**)&gy,     g_y);

    copy_kernel<<<(LSEQ * DM + 255) / 256, 256>>>(x_in, gx, LSEQ * DM);

    for (int i = 0; i < NLAYER; i++) {
        const float* ipw = in_proj_w  + (size_t)i * 2 * DI * DM;
        const float* cw  = conv_w     + (size_t)i * DI * DCONV;
        const float* cb  = conv_b     + (size_t)i * DI;
        const float* xpw = x_proj_w   + (size_t)i * PROJW * DI;
        const float* dtw = dt_proj_w  + (size_t)i * DI * DTR;
        const float* dtb = dt_proj_b  + (size_t)i * DI;
        const float* al  = A_log      + (size_t)i * DI * DS;
        const float* dv  = Dv         + (size_t)i * DI;
        const float* opw = out_proj_w + (size_t)i * DM * DI;
        const float* nw  = norm_w     + (size_t)i * DM;

        rmsnorm_kernel<<<LSEQ, 256>>>(gx, nw, gxn);

        // in_proj: (2048x768) x (3072x768)^T
        gemm_ffma2<<<dim3(2 * DI / GBN, LSEQ / GBM), 256>>>(
            gxn, DM, ipw, DM, gxz, 2 * DI, 2 * DI, DM, nullptr, 0, 0, 0);
        conv_silu_kernel<<<(LSEQ * DI + 255) / 256, 256>>>(gxz, cw, cb, gxc);

        // x_proj split-K x8: (2048x1536) x (80x1536)^T
        gemm_ffma2<<<dim3(1, LSEQ / GBM, XSPLIT), 256>>>(
            gxc, DI, xpw, DI, gprojp, PROJW, PROJW, DI, nullptr, 0,
            DI / XSPLIT, (size_t)LSEQ * PROJW);
        reduce_splitk<<<(LSEQ * PROJW + 255) / 256, 256>>>(
            gprojp, gproj, LSEQ * PROJW, XSPLIT, (size_t)LSEQ * PROJW);

        // dt_proj + bias + softplus: (2048x48) x (1536x48)^T
        gemm_ffma2<<<dim3(DI / GBN, LSEQ / GBM), 256>>>(
            gproj, PROJW, dtw, DTR, gdelta, DI, DI, DTR, dtb, 1, 0, 0);
        scan_kernel<<<(DI * DS) / 128, 128>>>(gdelta, gxc, gproj, gxz, al, dv, gy);

        // out_proj + residual add
        gemm_ffma2<<<dim3(DM / GBN, LSEQ / GBM), 256>>>(
            gy, DI, opw, DI, gx, DM, DM, DI, nullptr, 2, 0, 0);
    }

    rmsnorm_kernel<<<LSEQ, 256>>>(gx, norm_f_w, gxn);
    gemm_ffma2<<<dim3(OUTD / GBN, LSEQ / GBM), 256>>>(
        gxn, DM, head_w, DM, out, OUTD, OUTD, DM, nullptr, 0, 0, 0);
}

// round 7
// speedup vs baseline: 1.6556x; 1.0468x over previous
#include <cuda_runtime.h>
#include <cuda_fp16.h>
#include <math.h>
#include <stdint.h>

#define LSEQ 2048
#define DM 768
#define DI 1536
#define DS 16
#define DTR 48
#define DCONV 4
#define OUTD 128
#define PROJW (DTR + 2*DS)   // 80
#define NLAYER 2
#define XSPLIT 8
#define OSPLIT 2
#define HSPLIT 8

// ---------------- scratch ----------------
__device__ float g_x[LSEQ*DM];
__device__ float g_xn[LSEQ*DM];
__device__ float g_xz[LSEQ*2*DI];
__device__ float g_xc[LSEQ*DI];
__device__ float g_proj[LSEQ*PROJW];
__device__ float g_projp[XSPLIT*LSEQ*PROJW];
__device__ float g_delta[LSEQ*DI];
__device__ float g_y[LSEQ*DI];
__device__ float g_yp[OSPLIT*LSEQ*DM];
__device__ float g_headp[HSPLIT*LSEQ*OUTD];

__device__ __forceinline__ uint32_t smem_u32(const void* p) {
    uint32_t a;
    asm("{ .reg .u64 t; cvta.to.shared.u64 t, %1; cvt.u32.u64 %0, t; }" : "=r"(a) : "l"(p));
    return a;
}
__device__ __forceinline__ void ldsm_x4(uint32_t& r0, uint32_t& r1, uint32_t& r2, uint32_t& r3, uint32_t addr) {
    asm volatile("ldmatrix.sync.aligned.m8n8.x4.shared.b16 {%0,%1,%2,%3}, [%4];"
                 : "=r"(r0), "=r"(r1), "=r"(r2), "=r"(r3) : "r"(addr));
}
__device__ __forceinline__ void mma16816(float* c, const uint32_t* a, uint32_t b0, uint32_t b1) {
    asm volatile("mma.sync.aligned.m16n8k16.row.col.f32.f16.f16.f32 "
                 "{%0,%1,%2,%3}, {%4,%5,%6,%7}, {%8,%9}, {%0,%1,%2,%3};"
                 : "+f"(c[0]), "+f"(c[1]), "+f"(c[2]), "+f"(c[3])
                 : "r"(a[0]), "r"(a[1]), "r"(a[2]), "r"(a[3]), "r"(b0), "r"(b1));
}

// ---------------- fp16 tensor-core GEMM ----------------
// C[M,N] = A[M,K] * B[N,K]^T, A/B fp32 in gmem (converted on load)
// mode 0: plain store; 1: softplus(acc + bias[n])
// kchunk>0: K-range [bz*kchunk, +kchunk), C += bz*czstride (mode 0)
#define TBM 128
#define TBN 128
#define TBK 32
#define APAD 40   // row stride in halves

__global__ void __launch_bounds__(256, 1)
gemm_hmma(const float* __restrict__ A, int lda,
          const float* __restrict__ B, int ldb,
          float* __restrict__ C, int ldc,
          int N, int K, const float* __restrict__ bias, int mode,
          int kchunk, size_t czstride) {
    __shared__ __align__(16) __half As[2][TBM * APAD];
    __shared__ __align__(16) __half Bs[2][TBN * APAD];

    int t = threadIdx.x;
    int m0 = blockIdx.y * TBM, n0 = blockIdx.x * TBN;
    int wid = t >> 5, lane = t & 31;
    int wm = (wid & 1) * 64;       // warp m-offset
    int wn = (wid >> 1) * 32;      // warp n-offset

    int kbeg = 0, kend = K;
    if (kchunk > 0) {
        kbeg = blockIdx.z * kchunk;
        kend = min(kbeg + kchunk, K);
        C += (size_t)blockIdx.z * czstride;
    }
    int nk = (kend - kbeg + TBK - 1) / TBK;

    int row = t >> 1;              // 0..127
    int kh = (t & 1) * 16;         // 0 or 16
    // NOTE: pointers pre-offset by kh; stage() must NOT add kh again.
    const float* Aptr = A + (size_t)(m0 + row) * lda + kbeg + kh;
    const float* Bptr = B + (size_t)(n0 + row) * ldb + kbeg + kh;
    bool bvalid = (n0 + row) < N;
    int krem0 = kend - kbeg - kh;  // #valid k-elements from (kbeg+kh)

    // lane addressing for ldmatrix
    uint32_t sA = smem_u32(As), sB = smem_u32(Bs);
    int a_row = wm + (lane & 15);
    int a_koff = (lane >> 4) << 3;
    int b_row = wn + ((lane >> 4) << 3) + (lane & 7);
    int b_koff = lane & 8;

    float acc[4][4][4];            // [mt][nt][reg]
    #pragma unroll
    for (int i = 0; i < 4; i++)
        #pragma unroll
        for (int j = 0; j < 4; j++)
            #pragma unroll
            for (int q = 0; q < 4; q++) acc[i][j][q] = 0.f;

    // stage tile kt into regs (offsets relative to Aptr/Bptr, kh already applied)
    float4 sa[4], sb[4];
    auto stage = [&](int kt) {
        int kc0 = kt * TBK;
        #pragma unroll
        for (int j = 0; j < 4; j++) {
            int kc = kc0 + j * 4;   // offset from (kbeg+kh)
            sa[j] = (kc < krem0) ? *(const float4*)(Aptr + kc) : make_float4(0.f,0.f,0.f,0.f);
            sb[j] = (bvalid && kc < krem0) ? *(const float4*)(Bptr + kc) : make_float4(0.f,0.f,0.f,0.f);
        }
    };
    auto commit = [&](int buf) {
        __half* ap = &As[buf][row * APAD + kh];
        __half* bp = &Bs[buf][row * APAD + kh];
        #pragma unroll
        for (int j = 0; j < 4; j++) {
            __half2 a01 = __floats2half2_rn(sa[j].x, sa[j].y);
            __half2 a23 = __floats2half2_rn(sa[j].z, sa[j].w);
            *(__half2*)(ap + j * 4)     = a01;
            *(__half2*)(ap + j * 4 + 2) = a23;
            __half2 b01 = __floats2half2_rn(sb[j].x, sb[j].y);
            __half2 b23 = __floats2half2_rn(sb[j].z, sb[j].w);
            *(__half2*)(bp + j * 4)     = b01;
            *(__half2*)(bp + j * 4 + 2) = b23;
        }
    };

    stage(0); commit(0);
    __syncthreads();

    for (int kt = 0; kt < nk; kt++) {
        int buf = kt & 1;
        if (kt + 1 < nk) stage(kt + 1);
        uint32_t aBase = sA + buf * (TBM * APAD * 2);
        uint32_t bBase = sB + buf * (TBN * APAD * 2);
        #pragma unroll
        for (int k16 = 0; k16 < 2; k16++) {
            uint32_t af[4][4];
            #pragma unroll
            for (int mt = 0; mt < 4; mt++) {
                uint32_t addr = aBase + ((a_row + mt * 16) * APAD + k16 * 16 + a_koff) * 2;
                ldsm_x4(af[mt][0], af[mt][1], af[mt][2], af[mt][3], addr);
            }
            uint32_t bf[4][2];
            #pragma unroll
            for (int np = 0; np < 2; np++) {
                uint32_t addr = bBase + ((b_row + np * 16) * APAD + k16 * 16 + b_koff) * 2;
                uint32_t r0, r1, r2, r3;
                ldsm_x4(r0, r1, r2, r3, addr);
                bf[np * 2 + 0][0] = r0; bf[np * 2 + 0][1] = r1;
                bf[np * 2 + 1][0] = r2; bf[np * 2 + 1][1] = r3;
            }
            #pragma unroll
            for (int mt = 0; mt < 4; mt++)
                #pragma unroll
                for (int nt = 0; nt < 4; nt++)
                    mma16816(acc[mt][nt], af[mt], bf[nt][0], bf[nt][1]);
        }
        if (kt + 1 < nk) {
            __syncthreads();
            commit(buf ^ 1);
            __syncthreads();
        }
    }

    // epilogue
    int qr = lane >> 2;           // 0..7
    int qc = (lane & 3) * 2;      // 0,2,4,6
    #pragma unroll
    for (int mt = 0; mt < 4; mt++) {
        #pragma unroll
        for (int nt = 0; nt < 4; nt++) {
            int cb = n0 + wn + nt * 8;
            if (cb >= N) continue;
            int c = cb + qc;
            int r0 = m0 + wm + mt * 16 + qr;
            float* p0 = C + (size_t)r0 * ldc + c;
            float* p1 = C + (size_t)(r0 + 8) * ldc + c;
            float v0 = acc[mt][nt][0], v1 = acc[mt][nt][1];
            float v2 = acc[mt][nt][2], v3 = acc[mt][nt][3];
            if (mode == 1) {
                float b0 = bias[c], b1 = bias[c + 1];
                v0 += b0; v1 += b1; v2 += b0; v3 += b1;
                v0 = (v0 > 20.f) ? v0 : log1pf(__expf(v0));
                v1 = (v1 > 20.f) ? v1 : log1pf(__expf(v1));
                v2 = (v2 > 20.f) ? v2 : log1pf(__expf(v2));
                v3 = (v3 > 20.f) ? v3 : log1pf(__expf(v3));
            }
            p0[0] = v0; p0[1] = v1;
            p1[0] = v2; p1[1] = v3;
        }
    }
}

// ---------------- reduce kernels ----------------
__global__ void reduce_k(const float* __restrict__ part, float* __restrict__ out,
                         int n, int nz, size_t stride) {
    int i = blockIdx.x * blockDim.x + threadIdx.x;
    if (i >= n) return;
    float s = 0.f;
    for (int z = 0; z < nz; z++) s += part[(size_t)z * stride + i];
    out[i] = s;
}
__global__ void reduce_k_res(const float* __restrict__ part, float* __restrict__ out,
                             int n, int nz, size_t stride) {
    int i = blockIdx.x * blockDim.x + threadIdx.x;
    if (i >= n) return;
    float s = out[i];
    for (int z = 0; z < nz; z++) s += part[(size_t)z * stride + i];
    out[i] = s;
}

// ---------------- small kernels ----------------
__global__ void copy_kernel(const float* __restrict__ in, float* __restrict__ out, int n) {
    int i = blockIdx.x * blockDim.x + threadIdx.x;
    if (i < n) out[i] = in[i];
}

__global__ void rmsnorm_kernel(const float* __restrict__ x, const float* __restrict__ w,
                               float* __restrict__ out) {
    int l = blockIdx.x;
    const float* xr = x + (size_t)l * DM;
    __shared__ float red[8];
    __shared__ float s_r;
    float ss = 0.f;
    for (int i = threadIdx.x; i < DM; i += 256) { float v = xr[i]; ss += v * v; }
    #pragma unroll
    for (int o = 16; o; o >>= 1) ss += __shfl_xor_sync(0xffffffffu, ss, o);
    if ((threadIdx.x & 31) == 0) red[threadIdx.x >> 5] = ss;
    __syncthreads();
    if (threadIdx.x == 0) {
        float tt = 0.f;
        #pragma unroll
        for (int i = 0; i < 8; i++) tt += red[i];
        s_r = rsqrtf(tt / DM + 1e-5f);
    }
    __syncthreads();
    float r = s_r;
    for (int i = threadIdx.x; i < DM; i += 256) out[(size_t)l * DM + i] = xr[i] * r * w[i];
}

__global__ void conv_silu_kernel(const float* __restrict__ xz, const float* __restrict__ w,
                                 const float* __restrict__ b, float* __restrict__ out) {
    int idx = blockIdx.x * blockDim.x + threadIdx.x;
    if (idx >= LSEQ * DI) return;
    int l = idx / DI, c = idx % DI;
    float acc = b[c];
    #pragma unroll
    for (int j = 0; j < DCONV; j++) {
        int ls = l - (DCONV - 1) + j;
        if (ls >= 0) acc += w[c * DCONV + j] * xz[(size_t)ls * (2 * DI) + c];
    }
    out[idx] = acc / (1.f + __expf(-acc));
}

__global__ void scan_kernel(const float* __restrict__ delta, const float* __restrict__ u,
                            const float* __restrict__ proj, const float* __restrict__ xz,
                            const float* __restrict__ A_log, const float* __restrict__ Dv,
                            float* __restrict__ y) {
    int gid = blockIdx.x * blockDim.x + threadIdx.x;
    int d = gid >> 4;
    int n = gid & 15;
    if (d >= DI) return;
    float A = -__expf(A_log[d * DS + n]);
    float Dd = Dv[d];
    float s = 0.f;
    float p_dl = delta[d];
    float p_ul = u[d];
    float p_B  = proj[DTR + n];
    float p_C  = proj[DTR + DS + n];
    float p_res = xz[DI + d];
    for (int l = 0; l < LSEQ; l++) {
        float dl = p_dl, ul = p_ul, Bn = p_B, Cn = p_C, res = p_res;
        if (l + 1 < LSEQ) {
            size_t o = (size_t)(l + 1) * DI + d;
            p_dl = delta[o];
            p_ul = u[o];
            p_B  = proj[(l + 1) * PROJW + DTR + n];
            p_C  = proj[(l + 1) * PROJW + DTR + DS + n];
            p_res = xz[(size_t)(l + 1) * (2 * DI) + DI + d];
        }
        float dA = __expf(dl * A);
        s = fmaf(dA, s, (dl * ul) * Bn);
        float v = s * Cn;
        v += __shfl_xor_sync(0xffffffffu, v, 8, 16);
        v += __shfl_xor_sync(0xffffffffu, v, 4, 16);
        v += __shfl_xor_sync(0xffffffffu, v, 2, 16);
        v += __shfl_xor_sync(0xffffffffu, v, 1, 16);
        if (n == 0) {
            float g = res / (1.f + __expf(-res));
            y[(size_t)l * DI + d] = (v + ul * Dd) * g;
        }
    }
}

// ---------------- host orchestration ----------------
extern "C" void kernel_launch(void* const* d_in, const int* in_sizes, int n_in,
                              void* d_out, int out_size) {
    const float* x_in      = (const float*)d_in[0];
    const float* in_proj_w = (const float*)d_in[1];
    const float* conv_w    = (const float*)d_in[2];
    const float* conv_b    = (const float*)d_in[3];
    const float* x_proj_w  = (const float*)d_in[4];
    const float* dt_proj_w = (const float*)d_in[5];
    const float* dt_proj_b = (const float*)d_in[6];
    const float* A_log     = (const float*)d_in[7];
    const float* Dv        = (const float*)d_in[8];
    const float* out_proj_w= (const float*)d_in[9];
    const float* norm_w    = (const float*)d_in[10];
    const float* norm_f_w  = (const float*)d_in[11];
    const float* head_w    = (const float*)d_in[12];
    float* out = (float*)d_out;

    float *gx, *gxn, *gxz, *gxc, *gproj, *gprojp, *gdelta, *gy, *gyp, *gheadp;
    cudaGetSymbolAddress((void**)&gx,     g_x);
    cudaGetSymbolAddress((void**)&gxn,    g_xn);
    cudaGetSymbolAddress((void**)&gxz,    g_xz);
    cudaGetSymbolAddress((void**)&gxc,    g_xc);
    cudaGetSymbolAddress((void**)&gproj,  g_proj);
    cudaGetSymbolAddress((void**)&gprojp, g_projp);
    cudaGetSymbolAddress((void**)&gdelta, g_delta);
    cudaGetSymbolAddress((void**)&gy,     g_y);
    cudaGetSymbolAddress((void**)&gyp,    g_yp);
    cudaGetSymbolAddress((void**)&gheadp, g_headp);

    copy_kernel<<<(LSEQ * DM + 255) / 256, 256>>>(x_in, gx, LSEQ * DM);

    for (int i = 0; i < NLAYER; i++) {
        const float* ipw = in_proj_w  + (size_t)i * 2 * DI * DM;
        const float* cw  = conv_w     + (size_t)i * DI * DCONV;
        const float* cb  = conv_b     + (size_t)i * DI;
        const float* xpw = x_proj_w   + (size_t)i * PROJW * DI;
        const float* dtw = dt_proj_w  + (size_t)i * DI * DTR;
        const float* dtb = dt_proj_b  + (size_t)i * DI;
        const float* al  = A_log      + (size_t)i * DI * DS;
        const float* dv  = Dv         + (size_t)i * DI;
        const float* opw = out_proj_w + (size_t)i * DM * DI;
        const float* nw  = norm_w     + (size_t)i * DM;

        rmsnorm_kernel<<<LSEQ, 256>>>(gx, nw, gxn);

        // in_proj: (2048x768)x(3072x768)^T
        gemm_hmma<<<dim3(2 * DI / TBN, LSEQ / TBM), 256>>>(
            gxn, DM, ipw, DM, gxz, 2 * DI, 2 * DI, DM, nullptr, 0, 0, 0);
        conv_silu_kernel<<<(LSEQ * DI + 255) / 256, 256>>>(gxz, cw, cb, gxc);

        // x_proj split-K x8
        gemm_hmma<<<dim3(1, LSEQ / TBM, XSPLIT), 256>>>(
            gxc, DI, xpw, DI, gprojp, PROJW, PROJW, DI, nullptr, 0,
            DI / XSPLIT, (size_t)LSEQ * PROJW);
        reduce_k<<<(LSEQ * PROJW + 255) / 256, 256>>>(
            gprojp, gproj, LSEQ * PROJW, XSPLIT, (size_t)LSEQ * PROJW);

        // dt_proj + bias + softplus (K=48)
        gemm_hmma<<<dim3(DI / TBN, LSEQ / TBM), 256>>>(
            gproj, PROJW, dtw, DTR, gdelta, DI, DI, DTR, dtb, 1, 0, 0);
        scan_kernel<<<(DI * DS) / 128, 128>>>(gdelta, gxc, gproj, gxz, al, dv, gy);

        // out_proj split-K x2, residual folded into reduce
        gemm_hmma<<<dim3(DM / TBN, LSEQ / TBM, OSPLIT), 256>>>(
            gy, DI, opw, DI, gyp, DM, DM, DI, nullptr, 0,
            DI / OSPLIT, (size_t)LSEQ * DM);
        reduce_k_res<<<(LSEQ * DM + 255) / 256, 256>>>(
            gyp, gx, LSEQ * DM, OSPLIT, (size_t)LSEQ * DM);
    }

    rmsnorm_kernel<<<LSEQ, 256>>>(gx, norm_f_w, gxn);
    // head split-K x8
    gemm_hmma<<<dim3(OUTD / TBN, LSEQ / TBM, HSPLIT), 256>>>(
        gxn, DM, head_w, DM, gheadp, OUTD, OUTD, DM, nullptr, 0,
        DM / HSPLIT, (size_t)LSEQ * OUTD);
    reduce_k<<<(LSEQ * OUTD + 255) / 256, 256>>>(
        gheadp, out, LSEQ * OUTD, HSPLIT, (size_t)LSEQ * OUTD);
}

// round 8
// speedup vs baseline: 4.5581x; 2.7532x over previous
#include <cuda_runtime.h>
#include <cuda_fp16.h>
#include <math.h>
#include <stdint.h>

#define LSEQ 2048
#define DM 768
#define DI 1536
#define DS 16
#define DTR 48
#define DCONV 4
#define OUTD 128
#define PROJW (DTR + 2*DS)   // 80
#define NLAYER 2
#define XSPLIT 8
#define OSPLIT 2
#define HSPLIT 8
#define NCHUNK 32
#define CLEN (LSEQ / NCHUNK)   // 64
#define DN (DI * DS)           // 24576

// ---------------- scratch ----------------
__device__ float g_x[LSEQ*DM];
__device__ float g_xn[LSEQ*DM];
__device__ float g_xz[LSEQ*2*DI];
__device__ float g_xc[LSEQ*DI];
__device__ float g_proj[LSEQ*PROJW];
__device__ float g_projp[XSPLIT*LSEQ*PROJW];
__device__ float g_delta[LSEQ*DI];
__device__ float g_y[LSEQ*DI];
__device__ float g_yp[OSPLIT*LSEQ*DM];
__device__ float g_headp[HSPLIT*LSEQ*OUTD];
__device__ float g_carryA[NCHUNK*DN];
__device__ float g_carryB[NCHUNK*DN];
__device__ float g_sin[NCHUNK*DN];

__device__ __forceinline__ uint32_t smem_u32(const void* p) {
    uint32_t a;
    asm("{ .reg .u64 t; cvta.to.shared.u64 t, %1; cvt.u32.u64 %0, t; }" : "=r"(a) : "l"(p));
    return a;
}
__device__ __forceinline__ void ldsm_x4(uint32_t& r0, uint32_t& r1, uint32_t& r2, uint32_t& r3, uint32_t addr) {
    asm volatile("ldmatrix.sync.aligned.m8n8.x4.shared.b16 {%0,%1,%2,%3}, [%4];"
                 : "=r"(r0), "=r"(r1), "=r"(r2), "=r"(r3) : "r"(addr));
}
__device__ __forceinline__ void mma16816(float* c, const uint32_t* a, uint32_t b0, uint32_t b1) {
    asm volatile("mma.sync.aligned.m16n8k16.row.col.f32.f16.f16.f32 "
                 "{%0,%1,%2,%3}, {%4,%5,%6,%7}, {%8,%9}, {%0,%1,%2,%3};"
                 : "+f"(c[0]), "+f"(c[1]), "+f"(c[2]), "+f"(c[3])
                 : "r"(a[0]), "r"(a[1]), "r"(a[2]), "r"(a[3]), "r"(b0), "r"(b1));
}

// ---------------- fp16 tensor-core GEMM (unchanged from R7) ----------------
#define TBM 128
#define TBN 128
#define TBK 32
#define APAD 40

__global__ void __launch_bounds__(256, 1)
gemm_hmma(const float* __restrict__ A, int lda,
          const float* __restrict__ B, int ldb,
          float* __restrict__ C, int ldc,
          int N, int K, const float* __restrict__ bias, int mode,
          int kchunk, size_t czstride) {
    __shared__ __align__(16) __half As[2][TBM * APAD];
    __shared__ __align__(16) __half Bs[2][TBN * APAD];

    int t = threadIdx.x;
    int m0 = blockIdx.y * TBM, n0 = blockIdx.x * TBN;
    int wid = t >> 5, lane = t & 31;
    int wm = (wid & 1) * 64;
    int wn = (wid >> 1) * 32;

    int kbeg = 0, kend = K;
    if (kchunk > 0) {
        kbeg = blockIdx.z * kchunk;
        kend = min(kbeg + kchunk, K);
        C += (size_t)blockIdx.z * czstride;
    }
    int nk = (kend - kbeg + TBK - 1) / TBK;

    int row = t >> 1;
    int kh = (t & 1) * 16;
    const float* Aptr = A + (size_t)(m0 + row) * lda + kbeg + kh;
    const float* Bptr = B + (size_t)(n0 + row) * ldb + kbeg + kh;
    bool bvalid = (n0 + row) < N;
    int krem0 = kend - kbeg - kh;

    uint32_t sA = smem_u32(As), sB = smem_u32(Bs);
    int a_row = wm + (lane & 15);
    int a_koff = (lane >> 4) << 3;
    int b_row = wn + ((lane >> 4) << 3) + (lane & 7);
    int b_koff = lane & 8;

    float acc[4][4][4];
    #pragma unroll
    for (int i = 0; i < 4; i++)
        #pragma unroll
        for (int j = 0; j < 4; j++)
            #pragma unroll
            for (int q = 0; q < 4; q++) acc[i][j][q] = 0.f;

    float4 sa[4], sb[4];
    auto stage = [&](int kt) {
        int kc0 = kt * TBK;
        #pragma unroll
        for (int j = 0; j < 4; j++) {
            int kc = kc0 + j * 4;
            sa[j] = (kc < krem0) ? *(const float4*)(Aptr + kc) : make_float4(0.f,0.f,0.f,0.f);
            sb[j] = (bvalid && kc < krem0) ? *(const float4*)(Bptr + kc) : make_float4(0.f,0.f,0.f,0.f);
        }
    };
    auto commit = [&](int buf) {
        __half* ap = &As[buf][row * APAD + kh];
        __half* bp = &Bs[buf][row * APAD + kh];
        #pragma unroll
        for (int j = 0; j < 4; j++) {
            *(__half2*)(ap + j * 4)     = __floats2half2_rn(sa[j].x, sa[j].y);
            *(__half2*)(ap + j * 4 + 2) = __floats2half2_rn(sa[j].z, sa[j].w);
            *(__half2*)(bp + j * 4)     = __floats2half2_rn(sb[j].x, sb[j].y);
            *(__half2*)(bp + j * 4 + 2) = __floats2half2_rn(sb[j].z, sb[j].w);
        }
    };

    stage(0); commit(0);
    __syncthreads();

    for (int kt = 0; kt < nk; kt++) {
        int buf = kt & 1;
        if (kt + 1 < nk) stage(kt + 1);
        uint32_t aBase = sA + buf * (TBM * APAD * 2);
        uint32_t bBase = sB + buf * (TBN * APAD * 2);
        #pragma unroll
        for (int k16 = 0; k16 < 2; k16++) {
            uint32_t af[4][4];
            #pragma unroll
            for (int mt = 0; mt < 4; mt++) {
                uint32_t addr = aBase + ((a_row + mt * 16) * APAD + k16 * 16 + a_koff) * 2;
                ldsm_x4(af[mt][0], af[mt][1], af[mt][2], af[mt][3], addr);
            }
            uint32_t bf[4][2];
            #pragma unroll
            for (int np = 0; np < 2; np++) {
                uint32_t addr = bBase + ((b_row + np * 16) * APAD + k16 * 16 + b_koff) * 2;
                uint32_t r0, r1, r2, r3;
                ldsm_x4(r0, r1, r2, r3, addr);
                bf[np * 2 + 0][0] = r0; bf[np * 2 + 0][1] = r1;
                bf[np * 2 + 1][0] = r2; bf[np * 2 + 1][1] = r3;
            }
            #pragma unroll
            for (int mt = 0; mt < 4; mt++)
                #pragma unroll
                for (int nt = 0; nt < 4; nt++)
                    mma16816(acc[mt][nt], af[mt], bf[nt][0], bf[nt][1]);
        }
        if (kt + 1 < nk) {
            __syncthreads();
            commit(buf ^ 1);
            __syncthreads();
        }
    }

    int qr = lane >> 2;
    int qc = (lane & 3) * 2;
    #pragma unroll
    for (int mt = 0; mt < 4; mt++) {
        #pragma unroll
        for (int nt = 0; nt < 4; nt++) {
            int cb = n0 + wn + nt * 8;
            if (cb >= N) continue;
            int c = cb + qc;
            int r0 = m0 + wm + mt * 16 + qr;
            float* p0 = C + (size_t)r0 * ldc + c;
            float* p1 = C + (size_t)(r0 + 8) * ldc + c;
            float v0 = acc[mt][nt][0], v1 = acc[mt][nt][1];
            float v2 = acc[mt][nt][2], v3 = acc[mt][nt][3];
            if (mode == 1) {
                float b0 = bias[c], b1 = bias[c + 1];
                v0 += b0; v1 += b1; v2 += b0; v3 += b1;
                v0 = (v0 > 20.f) ? v0 : log1pf(__expf(v0));
                v1 = (v1 > 20.f) ? v1 : log1pf(__expf(v1));
                v2 = (v2 > 20.f) ? v2 : log1pf(__expf(v2));
                v3 = (v3 > 20.f) ? v3 : log1pf(__expf(v3));
            }
            p0[0] = v0; p0[1] = v1;
            p1[0] = v2; p1[1] = v3;
        }
    }
}

// ---------------- reduce kernels ----------------
__global__ void reduce_k(const float* __restrict__ part, float* __restrict__ out,
                         int n, int nz, size_t stride) {
    int i = blockIdx.x * blockDim.x + threadIdx.x;
    if (i >= n) return;
    float s = 0.f;
    for (int z = 0; z < nz; z++) s += part[(size_t)z * stride + i];
    out[i] = s;
}
__global__ void reduce_k_res(const float* __restrict__ part, float* __restrict__ out,
                             int n, int nz, size_t stride) {
    int i = blockIdx.x * blockDim.x + threadIdx.x;
    if (i >= n) return;
    float s = out[i];
    for (int z = 0; z < nz; z++) s += part[(size_t)z * stride + i];
    out[i] = s;
}

// ---------------- small kernels ----------------
__global__ void copy_kernel(const float* __restrict__ in, float* __restrict__ out, int n) {
    int i = blockIdx.x * blockDim.x + threadIdx.x;
    if (i < n) out[i] = in[i];
}

__global__ void rmsnorm_kernel(const float* __restrict__ x, const float* __restrict__ w,
                               float* __restrict__ out) {
    int l = blockIdx.x;
    const float* xr = x + (size_t)l * DM;
    __shared__ float red[8];
    __shared__ float s_r;
    float ss = 0.f;
    for (int i = threadIdx.x; i < DM; i += 256) { float v = xr[i]; ss += v * v; }
    #pragma unroll
    for (int o = 16; o; o >>= 1) ss += __shfl_xor_sync(0xffffffffu, ss, o);
    if ((threadIdx.x & 31) == 0) red[threadIdx.x >> 5] = ss;
    __syncthreads();
    if (threadIdx.x == 0) {
        float tt = 0.f;
        #pragma unroll
        for (int i = 0; i < 8; i++) tt += red[i];
        s_r = rsqrtf(tt / DM + 1e-5f);
    }
    __syncthreads();
    float r = s_r;
    for (int i = threadIdx.x; i < DM; i += 256) out[(size_t)l * DM + i] = xr[i] * r * w[i];
}

__global__ void conv_silu_kernel(const float* __restrict__ xz, const float* __restrict__ w,
                                 const float* __restrict__ b, float* __restrict__ out) {
    int idx = blockIdx.x * blockDim.x + threadIdx.x;
    if (idx >= LSEQ * DI) return;
    int l = idx / DI, c = idx % DI;
    float acc = b[c];
    #pragma unroll
    for (int j = 0; j < DCONV; j++) {
        int ls = l - (DCONV - 1) + j;
        if (ls >= 0) acc += w[c * DCONV + j] * xz[(size_t)ls * (2 * DI) + c];
    }
    out[idx] = acc / (1.f + __expf(-acc));
}

// ---------------- 3-phase parallel selective scan ----------------
// Thread layout (p1/p3): gid = c*DN + d*DS + n  (n in low lane bits -> shfl16 ok)
__global__ void scan_p1(const float* __restrict__ delta, const float* __restrict__ u,
                        const float* __restrict__ proj, const float* __restrict__ A_log,
                        float* __restrict__ carryA, float* __restrict__ carryB) {
    int gid = blockIdx.x * blockDim.x + threadIdx.x;
    int c = gid / DN;
    int r = gid - c * DN;
    int d = r >> 4, n = r & 15;
    float A = -__expf(A_log[d * DS + n]);
    float ap = 1.f, s = 0.f;
    int l0 = c * CLEN;
    for (int l = l0; l < l0 + CLEN; l++) {
        float dl = delta[(size_t)l * DI + d];
        float ul = u[(size_t)l * DI + d];
        float Bn = proj[l * PROJW + DTR + n];
        float a = __expf(dl * A);
        ap *= a;
        s = fmaf(a, s, (dl * ul) * Bn);
    }
    carryA[gid] = ap;
    carryB[gid] = s;
}

__global__ void scan_p2(const float* __restrict__ carryA, const float* __restrict__ carryB,
                        float* __restrict__ sin_) {
    int gid = blockIdx.x * blockDim.x + threadIdx.x;   // 0..DN-1
    float s = 0.f;
    #pragma unroll
    for (int c = 0; c < NCHUNK; c++) {
        sin_[c * DN + gid] = s;
        s = fmaf(carryA[c * DN + gid], s, carryB[c * DN + gid]);
    }
}

__global__ void scan_p3(const float* __restrict__ delta, const float* __restrict__ u,
                        const float* __restrict__ proj, const float* __restrict__ xz,
                        const float* __restrict__ A_log, const float* __restrict__ Dv,
                        const float* __restrict__ sin_, float* __restrict__ y) {
    int gid = blockIdx.x * blockDim.x + threadIdx.x;
    int c = gid / DN;
    int r = gid - c * DN;
    int d = r >> 4, n = r & 15;
    float A = -__expf(A_log[d * DS + n]);
    float Dd = Dv[d];
    float s = sin_[gid];
    int l0 = c * CLEN;
    for (int l = l0; l < l0 + CLEN; l++) {
        float dl = delta[(size_t)l * DI + d];
        float ul = u[(size_t)l * DI + d];
        float Bn = proj[l * PROJW + DTR + n];
        float Cn = proj[l * PROJW + DTR + DS + n];
        float a = __expf(dl * A);
        s = fmaf(a, s, (dl * ul) * Bn);
        float v = s * Cn;
        v += __shfl_xor_sync(0xffffffffu, v, 8, 16);
        v += __shfl_xor_sync(0xffffffffu, v, 4, 16);
        v += __shfl_xor_sync(0xffffffffu, v, 2, 16);
        v += __shfl_xor_sync(0xffffffffu, v, 1, 16);
        if (n == 0) {
            float res = xz[(size_t)l * (2 * DI) + DI + d];
            float g = res / (1.f + __expf(-res));
            y[(size_t)l * DI + d] = (v + ul * Dd) * g;
        }
    }
}

// ---------------- host orchestration ----------------
extern "C" void kernel_launch(void* const* d_in, const int* in_sizes, int n_in,
                              void* d_out, int out_size) {
    const float* x_in      = (const float*)d_in[0];
    const float* in_proj_w = (const float*)d_in[1];
    const float* conv_w    = (const float*)d_in[2];
    const float* conv_b    = (const float*)d_in[3];
    const float* x_proj_w  = (const float*)d_in[4];
    const float* dt_proj_w = (const float*)d_in[5];
    const float* dt_proj_b = (const float*)d_in[6];
    const float* A_log     = (const float*)d_in[7];
    const float* Dv        = (const float*)d_in[8];
    const float* out_proj_w= (const float*)d_in[9];
    const float* norm_w    = (const float*)d_in[10];
    const float* norm_f_w  = (const float*)d_in[11];
    const float* head_w    = (const float*)d_in[12];
    float* out = (float*)d_out;

    float *gx, *gxn, *gxz, *gxc, *gproj, *gprojp, *gdelta, *gy, *gyp, *gheadp;
    float *gcA, *gcB, *gsin;
    cudaGetSymbolAddress((void**)&gx,     g_x);
    cudaGetSymbolAddress((void**)&gxn,    g_xn);
    cudaGetSymbolAddress((void**)&gxz,    g_xz);
    cudaGetSymbolAddress((void**)&gxc,    g_xc);
    cudaGetSymbolAddress((void**)&gproj,  g_proj);
    cudaGetSymbolAddress((void**)&gprojp, g_projp);
    cudaGetSymbolAddress((void**)&gdelta, g_delta);
    cudaGetSymbolAddress((void**)&gy,     g_y);
    cudaGetSymbolAddress((void**)&gyp,    g_yp);
    cudaGetSymbolAddress((void**)&gheadp, g_headp);
    cudaGetSymbolAddress((void**)&gcA,    g_carryA);
    cudaGetSymbolAddress((void**)&gcB,    g_carryB);
    cudaGetSymbolAddress((void**)&gsin,   g_sin);

    copy_kernel<<<(LSEQ * DM + 255) / 256, 256>>>(x_in, gx, LSEQ * DM);

    for (int i = 0; i < NLAYER; i++) {
        const float* ipw = in_proj_w  + (size_t)i * 2 * DI * DM;
        const float* cw  = conv_w     + (size_t)i * DI * DCONV;
        const float* cb  = conv_b     + (size_t)i * DI;
        const float* xpw = x_proj_w   + (size_t)i * PROJW * DI;
        const float* dtw = dt_proj_w  + (size_t)i * DI * DTR;
        const float* dtb = dt_proj_b  + (size_t)i * DI;
        const float* al  = A_log      + (size_t)i * DI * DS;
        const float* dv  = Dv         + (size_t)i * DI;
        const float* opw = out_proj_w + (size_t)i * DM * DI;
        const float* nw  = norm_w     + (size_t)i * DM;

        rmsnorm_kernel<<<LSEQ, 256>>>(gx, nw, gxn);

        gemm_hmma<<<dim3(2 * DI / TBN, LSEQ / TBM), 256>>>(
            gxn, DM, ipw, DM, gxz, 2 * DI, 2 * DI, DM, nullptr, 0, 0, 0);
        conv_silu_kernel<<<(LSEQ * DI + 255) / 256, 256>>>(gxz, cw, cb, gxc);

        gemm_hmma<<<dim3(1, LSEQ / TBM, XSPLIT), 256>>>(
            gxc, DI, xpw, DI, gprojp, PROJW, PROJW, DI, nullptr, 0,
            DI / XSPLIT, (size_t)LSEQ * PROJW);
        reduce_k<<<(LSEQ * PROJW + 255) / 256, 256>>>(
            gprojp, gproj, LSEQ * PROJW, XSPLIT, (size_t)LSEQ * PROJW);

        gemm_hmma<<<dim3(DI / TBN, LSEQ / TBM), 256>>>(
            gproj, PROJW, dtw, DTR, gdelta, DI, DI, DTR, dtb, 1, 0, 0);

        // 3-phase parallel scan
        scan_p1<<<NCHUNK * DN / 256, 256>>>(gdelta, gxc, gproj, al, gcA, gcB);
        scan_p2<<<DN / 256, 256>>>(gcA, gcB, gsin);
        scan_p3<<<NCHUNK * DN / 256, 256>>>(gdelta, gxc, gproj, gxz, al, dv, gsin, gy);

        gemm_hmma<<<dim3(DM / TBN, LSEQ / TBM, OSPLIT), 256>>>(
            gy, DI, opw, DI, gyp, DM, DM, DI, nullptr, 0,
            DI / OSPLIT, (size_t)LSEQ * DM);
        reduce_k_res<<<(LSEQ * DM + 255) / 256, 256>>>(
            gyp, gx, LSEQ * DM, OSPLIT, (size_t)LSEQ * DM);
    }

    rmsnorm_kernel<<<LSEQ, 256>>>(gx, norm_f_w, gxn);
    gemm_hmma<<<dim3(OUTD / TBN, LSEQ / TBM, HSPLIT), 256>>>(
        gxn, DM, head_w, DM, gheadp, OUTD, OUTD, DM, nullptr, 0,
        DM / HSPLIT, (size_t)LSEQ * OUTD);
    reduce_k<<<(LSEQ * OUTD + 255) / 256, 256>>>(
        gheadp, out, LSEQ * OUTD, HSPLIT, (size_t)LSEQ * OUTD);
}

// round 9
// speedup vs baseline: 5.5357x; 1.2145x over previous
#include <cuda_runtime.h>
#include <cuda_fp16.h>
#include <math.h>
#include <stdint.h>

#define LSEQ 2048
#define DM 768
#define DI 1536
#define DS 16
#define DTR 48
#define DCONV 4
#define OUTD 128
#define PROJW (DTR + 2*DS)   // 80
#define NLAYER 2
#define XSPLIT 8
#define OSPLIT 2
#define HSPLIT 6
#define NCHUNK 32
#define CLEN (LSEQ / NCHUNK)   // 64
#define DN (DI * DS)           // 24576

// ---------------- scratch ----------------
__device__ float g_x[LSEQ*DM];
__device__ float g_xz[LSEQ*2*DI];
__device__ float g_xc[LSEQ*DI];
__device__ float g_proj[LSEQ*PROJW];
__device__ float g_projp[XSPLIT*LSEQ*PROJW];
__device__ float g_delta[LSEQ*DI];
__device__ float g_yp[OSPLIT*LSEQ*DM];
__device__ float g_headp[HSPLIT*LSEQ*OUTD];
__device__ float g_carryA[NCHUNK*DN];
__device__ float g_carryB[NCHUNK*DN];
__device__ float g_sin[NCHUNK*DN];
// fp16 weights + activations
__device__ __half g_ipw16[NLAYER*2*DI*DM];
__device__ __half g_xpw16[NLAYER*PROJW*DI];
__device__ __half g_dtw16[NLAYER*DI*DTR];
__device__ __half g_opw16[NLAYER*DM*DI];
__device__ __half g_hw16[OUTD*DM];
__device__ __half g_xn16[LSEQ*DM];
__device__ __half g_xch[LSEQ*DI];
__device__ __half g_projh[LSEQ*PROJW];
__device__ __half g_yh[LSEQ*DI];

__device__ __forceinline__ uint32_t smem_u32(const void* p) {
    uint32_t a;
    asm("{ .reg .u64 t; cvta.to.shared.u64 t, %1; cvt.u32.u64 %0, t; }" : "=r"(a) : "l"(p));
    return a;
}
__device__ __forceinline__ void ldsm_x4(uint32_t& r0, uint32_t& r1, uint32_t& r2, uint32_t& r3, uint32_t addr) {
    asm volatile("ldmatrix.sync.aligned.m8n8.x4.shared.b16 {%0,%1,%2,%3}, [%4];"
                 : "=r"(r0), "=r"(r1), "=r"(r2), "=r"(r3) : "r"(addr));
}
__device__ __forceinline__ void mma16816(float* c, const uint32_t* a, uint32_t b0, uint32_t b1) {
    asm volatile("mma.sync.aligned.m16n8k16.row.col.f32.f16.f16.f32 "
                 "{%0,%1,%2,%3}, {%4,%5,%6,%7}, {%8,%9}, {%0,%1,%2,%3};"
                 : "+f"(c[0]), "+f"(c[1]), "+f"(c[2]), "+f"(c[3])
                 : "r"(a[0]), "r"(a[1]), "r"(a[2]), "r"(a[3]), "r"(b0), "r"(b1));
}
__device__ __forceinline__ void cpasync16(uint32_t dst, const void* src, int sz) {
    asm volatile("cp.async.cg.shared.global [%0], [%1], 16, %2;"
                 :: "r"(dst), "l"(src), "r"(sz) : "memory");
}

// ---------------- fp16 cp.async tensor-core GEMM ----------------
// C[M,N] = A[M,K] * B[N,K]^T, A/B fp16, C fp32
// mode 0: plain; 1: softplus(acc + bias[n])
// kchunk>0: K-range [bz*kchunk,+kchunk), C += bz*czstride
#define TBM 128
#define TBN 128
#define TBK 64
#define APAD 72                       // halves; 144B row stride (16B-aligned, ldsm conflict-free)
#define ASTAGE (TBM * APAD * 2)       // 18432 B
#define NSTAGE 3
#define GSMEM (NSTAGE * 2 * ASTAGE)   // 110592 B

__global__ void __launch_bounds__(256, 1)
gemm_f16(const __half* __restrict__ A, int lda,
         const __half* __restrict__ B, int ldb,
         float* __restrict__ C, int ldc,
         int N, int K, const float* __restrict__ bias, int mode,
         int kchunk, size_t czstride) {
    extern __shared__ __align__(16) char smem[];
    uint32_t sA = smem_u32(smem);
    uint32_t sB = sA + NSTAGE * ASTAGE;

    int t = threadIdx.x;
    int m0 = blockIdx.y * TBM, n0 = blockIdx.x * TBN;
    int wid = t >> 5, lane = t & 31;
    int wm = (wid & 1) * 64;
    int wn = (wid >> 1) * 32;

    int kbeg = 0, kend = K;
    if (kchunk > 0) {
        kbeg = blockIdx.z * kchunk;
        kend = min(kbeg + kchunk, K);
        C += (size_t)blockIdx.z * czstride;
    }
    int Klocal = kend - kbeg;
    int nk = (Klocal + TBK - 1) / TBK;

    int a_row = wm + (lane & 15);
    int a_koff = (lane >> 4) << 3;
    int b_row = wn + ((lane >> 4) << 3) + (lane & 7);
    int b_koff = lane & 8;

    float acc[4][4][4];
    #pragma unroll
    for (int i = 0; i < 4; i++)
        #pragma unroll
        for (int j = 0; j < 4; j++)
            #pragma unroll
            for (int q = 0; q < 4; q++) acc[i][j][q] = 0.f;

    auto issue = [&](int kt) {
        if (kt < nk) {
            int buf = kt - (kt / NSTAGE) * NSTAGE;
            #pragma unroll
            for (int i = 0; i < 4; i++) {
                int idx = t + i * 256;          // 0..1023
                int row = idx >> 3, ch = idx & 7;
                int kOff = kt * TBK + ch * 8;   // halves from kbeg
                int szA = (Klocal - kOff) * 2;
                szA = szA < 0 ? 0 : (szA > 16 ? 16 : szA);
                uint32_t doff = (uint32_t)buf * ASTAGE + (uint32_t)(row * APAD + ch * 8) * 2;
                const __half* srcA = (szA > 0) ? (A + (size_t)(m0 + row) * lda + kbeg + kOff) : A;
                cpasync16(sA + doff, srcA, szA);
                int brow = n0 + row;
                int szB = (brow < N) ? szA : 0;
                const __half* srcB = (szB > 0) ? (B + (size_t)brow * ldb + kbeg + kOff) : B;
                cpasync16(sB + doff, srcB, szB);
            }
        }
        asm volatile("cp.async.commit_group;" ::: "memory");
    };

    issue(0);
    issue(1);

    for (int kt = 0; kt < nk; kt++) {
        int buf = kt - (kt / NSTAGE) * NSTAGE;
        asm volatile("cp.async.wait_group 1;" ::: "memory");
        __syncthreads();
        uint32_t aBase = sA + buf * ASTAGE;
        uint32_t bBase = sB + buf * ASTAGE;
        #pragma unroll
        for (int k16 = 0; k16 < 4; k16++) {
            uint32_t af[4][4];
            #pragma unroll
            for (int mt = 0; mt < 4; mt++) {
                uint32_t addr = aBase + ((a_row + mt * 16) * APAD + k16 * 16 + a_koff) * 2;
                ldsm_x4(af[mt][0], af[mt][1], af[mt][2], af[mt][3], addr);
            }
            uint32_t bf[4][2];
            #pragma unroll
            for (int np = 0; np < 2; np++) {
                uint32_t addr = bBase + ((b_row + np * 16) * APAD + k16 * 16 + b_koff) * 2;
                uint32_t r0, r1, r2, r3;
                ldsm_x4(r0, r1, r2, r3, addr);
                bf[np * 2 + 0][0] = r0; bf[np * 2 + 0][1] = r1;
                bf[np * 2 + 1][0] = r2; bf[np * 2 + 1][1] = r3;
            }
            #pragma unroll
            for (int mt = 0; mt < 4; mt++)
                #pragma unroll
                for (int nt = 0; nt < 4; nt++)
                    mma16816(acc[mt][nt], af[mt], bf[nt][0], bf[nt][1]);
        }
        issue(kt + 2);
    }

    int qr = lane >> 2;
    int qc = (lane & 3) * 2;
    #pragma unroll
    for (int mt = 0; mt < 4; mt++) {
        #pragma unroll
        for (int nt = 0; nt < 4; nt++) {
            int cb = n0 + wn + nt * 8;
            if (cb >= N) continue;
            int c = cb + qc;
            int r0 = m0 + wm + mt * 16 + qr;
            float* p0 = C + (size_t)r0 * ldc + c;
            float* p1 = C + (size_t)(r0 + 8) * ldc + c;
            float v0 = acc[mt][nt][0], v1 = acc[mt][nt][1];
            float v2 = acc[mt][nt][2], v3 = acc[mt][nt][3];
            if (mode == 1) {
                float b0 = bias[c], b1 = bias[c + 1];
                v0 += b0; v1 += b1; v2 += b0; v3 += b1;
                v0 = (v0 > 20.f) ? v0 : log1pf(__expf(v0));
                v1 = (v1 > 20.f) ? v1 : log1pf(__expf(v1));
                v2 = (v2 > 20.f) ? v2 : log1pf(__expf(v2));
                v3 = (v3 > 20.f) ? v3 : log1pf(__expf(v3));
            }
            p0[0] = v0; p0[1] = v1;
            p1[0] = v2; p1[1] = v3;
        }
    }
}

// ---------------- converts / reduces / small kernels ----------------
__global__ void f32tof16(const float* __restrict__ in, __half* __restrict__ out, int n) {
    int i = (blockIdx.x * blockDim.x + threadIdx.x) * 2;
    if (i < n) {
        float2 v = *(const float2*)(in + i);
        *(__half2*)(out + i) = __floats2half2_rn(v.x, v.y);
    }
}

__global__ void reduce_k(const float* __restrict__ part, float* __restrict__ out,
                         int n, int nz, size_t stride) {
    int i = blockIdx.x * blockDim.x + threadIdx.x;
    if (i >= n) return;
    float s = 0.f;
    for (int z = 0; z < nz; z++) s += part[(size_t)z * stride + i];
    out[i] = s;
}
// reduce + also emit fp16 shadow
__global__ void reduce_k_h(const float* __restrict__ part, float* __restrict__ out,
                           __half* __restrict__ outh, int n, int nz, size_t stride) {
    int i = blockIdx.x * blockDim.x + threadIdx.x;
    if (i >= n) return;
    float s = 0.f;
    for (int z = 0; z < nz; z++) s += part[(size_t)z * stride + i];
    out[i] = s;
    outh[i] = __float2half(s);
}
__global__ void reduce_k_res(const float* __restrict__ part, float* __restrict__ out,
                             int n, int nz, size_t stride) {
    int i = blockIdx.x * blockDim.x + threadIdx.x;
    if (i >= n) return;
    float s = out[i];
    for (int z = 0; z < nz; z++) s += part[(size_t)z * stride + i];
    out[i] = s;
}

__global__ void copy_kernel(const float* __restrict__ in, float* __restrict__ out, int n) {
    int i = blockIdx.x * blockDim.x + threadIdx.x;
    if (i < n) out[i] = in[i];
}

// rmsnorm with fp16 output (feeds GEMMs only)
__global__ void rmsnorm16_kernel(const float* __restrict__ x, const float* __restrict__ w,
                                 __half* __restrict__ out) {
    int l = blockIdx.x;
    const float* xr = x + (size_t)l * DM;
    __shared__ float red[8];
    __shared__ float s_r;
    float ss = 0.f;
    for (int i = threadIdx.x; i < DM; i += 256) { float v = xr[i]; ss += v * v; }
    #pragma unroll
    for (int o = 16; o; o >>= 1) ss += __shfl_xor_sync(0xffffffffu, ss, o);
    if ((threadIdx.x & 31) == 0) red[threadIdx.x >> 5] = ss;
    __syncthreads();
    if (threadIdx.x == 0) {
        float tt = 0.f;
        #pragma unroll
        for (int i = 0; i < 8; i++) tt += red[i];
        s_r = rsqrtf(tt / DM + 1e-5f);
    }
    __syncthreads();
    float r = s_r;
    for (int i = threadIdx.x; i < DM; i += 256)
        out[(size_t)l * DM + i] = __float2half(xr[i] * r * w[i]);
}

__global__ void conv_silu_kernel(const float* __restrict__ xz, const float* __restrict__ w,
                                 const float* __restrict__ b, float* __restrict__ out,
                                 __half* __restrict__ outh) {
    int idx = blockIdx.x * blockDim.x + threadIdx.x;
    if (idx >= LSEQ * DI) return;
    int l = idx / DI, c = idx % DI;
    float acc = b[c];
    #pragma unroll
    for (int j = 0; j < DCONV; j++) {
        int ls = l - (DCONV - 1) + j;
        if (ls >= 0) acc += w[c * DCONV + j] * xz[(size_t)ls * (2 * DI) + c];
    }
    float v = acc / (1.f + __expf(-acc));
    out[idx] = v;
    outh[idx] = __float2half(v);
}

// ---------------- 3-phase parallel scan ----------------
__global__ void scan_p1(const float* __restrict__ delta, const float* __restrict__ u,
                        const float* __restrict__ proj, const float* __restrict__ A_log,
                        float* __restrict__ carryA, float* __restrict__ carryB) {
    int gid = blockIdx.x * blockDim.x + threadIdx.x;
    int c = gid / DN;
    int r = gid - c * DN;
    int d = r >> 4, n = r & 15;
    float A = -__expf(A_log[d * DS + n]);
    float ap = 1.f, s = 0.f;
    int l0 = c * CLEN;
    for (int l = l0; l < l0 + CLEN; l++) {
        float dl = delta[(size_t)l * DI + d];
        float ul = u[(size_t)l * DI + d];
        float Bn = proj[l * PROJW + DTR + n];
        float a = __expf(dl * A);
        ap *= a;
        s = fmaf(a, s, (dl * ul) * Bn);
    }
    carryA[gid] = ap;
    carryB[gid] = s;
}

__global__ void scan_p2(const float* __restrict__ carryA, const float* __restrict__ carryB,
                        float* __restrict__ sin_) {
    int gid = blockIdx.x * blockDim.x + threadIdx.x;
    float s = 0.f;
    #pragma unroll
    for (int c = 0; c < NCHUNK; c++) {
        sin_[c * DN + gid] = s;
        s = fmaf(carryA[c * DN + gid], s, carryB[c * DN + gid]);
    }
}

__global__ void scan_p3(const float* __restrict__ delta, const float* __restrict__ u,
                        const float* __restrict__ proj, const float* __restrict__ xz,
                        const float* __restrict__ A_log, const float* __restrict__ Dv,
                        const float* __restrict__ sin_, __half* __restrict__ yh) {
    int gid = blockIdx.x * blockDim.x + threadIdx.x;
    int c = gid / DN;
    int r = gid - c * DN;
    int d = r >> 4, n = r & 15;
    float A = -__expf(A_log[d * DS + n]);
    float Dd = Dv[d];
    float s = sin_[gid];
    int l0 = c * CLEN;
    for (int l = l0; l < l0 + CLEN; l++) {
        float dl = delta[(size_t)l * DI + d];
        float ul = u[(size_t)l * DI + d];
        float Bn = proj[l * PROJW + DTR + n];
        float Cn = proj[l * PROJW + DTR + DS + n];
        float a = __expf(dl * A);
        s = fmaf(a, s, (dl * ul) * Bn);
        float v = s * Cn;
        v += __shfl_xor_sync(0xffffffffu, v, 8, 16);
        v += __shfl_xor_sync(0xffffffffu, v, 4, 16);
        v += __shfl_xor_sync(0xffffffffu, v, 2, 16);
        v += __shfl_xor_sync(0xffffffffu, v, 1, 16);
        if (n == 0) {
            float res = xz[(size_t)l * (2 * DI) + DI + d];
            float g = res / (1.f + __expf(-res));
            yh[(size_t)l * DI + d] = __float2half((v + ul * Dd) * g);
        }
    }
}

// ---------------- host orchestration ----------------
extern "C" void kernel_launch(void* const* d_in, const int* in_sizes, int n_in,
                              void* d_out, int out_size) {
    const float* x_in      = (const float*)d_in[0];
    const float* in_proj_w = (const float*)d_in[1];
    const float* conv_w    = (const float*)d_in[2];
    const float* conv_b    = (const float*)d_in[3];
    const float* x_proj_w  = (const float*)d_in[4];
    const float* dt_proj_w = (const float*)d_in[5];
    const float* dt_proj_b = (const float*)d_in[6];
    const float* A_log     = (const float*)d_in[7];
    const float* Dv        = (const float*)d_in[8];
    const float* out_proj_w= (const float*)d_in[9];
    const float* norm_w    = (const float*)d_in[10];
    const float* norm_f_w  = (const float*)d_in[11];
    const float* head_w    = (const float*)d_in[12];
    float* out = (float*)d_out;

    float *gx, *gxz, *gxc, *gproj, *gprojp, *gdelta, *gyp, *gheadp, *gcA, *gcB, *gsin;
    __half *ipw16, *xpw16, *dtw16, *opw16, *hw16, *xn16, *xch, *projh, *yh;
    cudaGetSymbolAddress((void**)&gx,     g_x);
    cudaGetSymbolAddress((void**)&gxz,    g_xz);
    cudaGetSymbolAddress((void**)&gxc,    g_xc);
    cudaGetSymbolAddress((void**)&gproj,  g_proj);
    cudaGetSymbolAddress((void**)&gprojp, g_projp);
    cudaGetSymbolAddress((void**)&gdelta, g_delta);
    cudaGetSymbolAddress((void**)&gyp,    g_yp);
    cudaGetSymbolAddress((void**)&gheadp, g_headp);
    cudaGetSymbolAddress((void**)&gcA,    g_carryA);
    cudaGetSymbolAddress((void**)&gcB,    g_carryB);
    cudaGetSymbolAddress((void**)&gsin,   g_sin);
    cudaGetSymbolAddress((void**)&ipw16,  g_ipw16);
    cudaGetSymbolAddress((void**)&xpw16,  g_xpw16);
    cudaGetSymbolAddress((void**)&dtw16,  g_dtw16);
    cudaGetSymbolAddress((void**)&opw16,  g_opw16);
    cudaGetSymbolAddress((void**)&hw16,   g_hw16);
    cudaGetSymbolAddress((void**)&xn16,   g_xn16);
    cudaGetSymbolAddress((void**)&xch,    g_xch);
    cudaGetSymbolAddress((void**)&projh,  g_projh);
    cudaGetSymbolAddress((void**)&yh,     g_yh);

    cudaFuncSetAttribute(gemm_f16, cudaFuncAttributeMaxDynamicSharedMemorySize, GSMEM);

    // weight conversions (fp32 -> fp16), whole stacked tensors
    {
        int n;
        n = NLAYER * 2 * DI * DM; f32tof16<<<(n/2 + 255)/256, 256>>>(in_proj_w, ipw16, n);
        n = NLAYER * PROJW * DI;  f32tof16<<<(n/2 + 255)/256, 256>>>(x_proj_w, xpw16, n);
        n = NLAYER * DI * DTR;    f32tof16<<<(n/2 + 255)/256, 256>>>(dt_proj_w, dtw16, n);
        n = NLAYER * DM * DI;     f32tof16<<<(n/2 + 255)/256, 256>>>(out_proj_w, opw16, n);
        n = OUTD * DM;            f32tof16<<<(n/2 + 255)/256, 256>>>(head_w, hw16, n);
    }

    copy_kernel<<<(LSEQ * DM + 255) / 256, 256>>>(x_in, gx, LSEQ * DM);

    for (int i = 0; i < NLAYER; i++) {
        const __half* ipw = ipw16 + (size_t)i * 2 * DI * DM;
        const float*  cw  = conv_w     + (size_t)i * DI * DCONV;
        const float*  cb  = conv_b     + (size_t)i * DI;
        const __half* xpw = xpw16 + (size_t)i * PROJW * DI;
        const __half* dtw = dtw16 + (size_t)i * DI * DTR;
        const float*  dtb = dt_proj_b  + (size_t)i * DI;
        const float*  al  = A_log      + (size_t)i * DI * DS;
        const float*  dv  = Dv         + (size_t)i * DI;
        const __half* opw = opw16 + (size_t)i * DM * DI;
        const float*  nw  = norm_w     + (size_t)i * DM;

        rmsnorm16_kernel<<<LSEQ, 256>>>(gx, nw, xn16);

        // in_proj: (2048x768)x(3072x768)^T
        gemm_f16<<<dim3(2 * DI / TBN, LSEQ / TBM), 256, GSMEM>>>(
            xn16, DM, ipw, DM, gxz, 2 * DI, 2 * DI, DM, nullptr, 0, 0, 0);
        conv_silu_kernel<<<(LSEQ * DI + 255) / 256, 256>>>(gxz, cw, cb, gxc, xch);

        // x_proj split-K x8 (chunks of 192)
        gemm_f16<<<dim3(1, LSEQ / TBM, XSPLIT), 256, GSMEM>>>(
            xch, DI, xpw, DI, gprojp, PROJW, PROJW, DI, nullptr, 0,
            DI / XSPLIT, (size_t)LSEQ * PROJW);
        reduce_k_h<<<(LSEQ * PROJW + 255) / 256, 256>>>(
            gprojp, gproj, projh, LSEQ * PROJW, XSPLIT, (size_t)LSEQ * PROJW);

        // dt_proj + bias + softplus (K=48, zfilled to 64)
        gemm_f16<<<dim3(DI / TBN, LSEQ / TBM), 256, GSMEM>>>(
            projh, PROJW, dtw, DTR, gdelta, DI, DI, DTR, dtb, 1, 0, 0);

        // 3-phase parallel scan (emits fp16 y)
        scan_p1<<<NCHUNK * DN / 256, 256>>>(gdelta, gxc, gproj, al, gcA, gcB);
        scan_p2<<<DN / 256, 256>>>(gcA, gcB, gsin);
        scan_p3<<<NCHUNK * DN / 256, 256>>>(gdelta, gxc, gproj, gxz, al, dv, gsin, yh);

        // out_proj split-K x2 + residual in reduce
        gemm_f16<<<dim3(DM / TBN, LSEQ / TBM, OSPLIT), 256, GSMEM>>>(
            yh, DI, opw, DI, gyp, DM, DM, DI, nullptr, 0,
            DI / OSPLIT, (size_t)LSEQ * DM);
        reduce_k_res<<<(LSEQ * DM + 255) / 256, 256>>>(
            gyp, gx, LSEQ * DM, OSPLIT, (size_t)LSEQ * DM);
    }

    rmsnorm16_kernel<<<LSEQ, 256>>>(gx, norm_f_w, xn16);
    // head split-K x6 (chunks of 128)
    gemm_f16<<<dim3(OUTD / TBN, LSEQ / TBM, HSPLIT), 256, GSMEM>>>(
        xn16, DM, hw16, DM, gheadp, OUTD, OUTD, DM, nullptr, 0,
        DM / HSPLIT, (size_t)LSEQ * OUTD);
    reduce_k<<<(LSEQ * OUTD + 255) / 256, 256>>>(
        gheadp, out, LSEQ * OUTD, HSPLIT, (size_t)LSEQ * OUTD);
}

// round 10
// speedup vs baseline: 5.7483x; 1.0384x over previous
#include <cuda_runtime.h>
#include <cuda_fp16.h>
#include <math.h>
#include <stdint.h>

#define LSEQ 2048
#define DM 768
#define DI 1536
#define DS 16
#define DTR 48
#define DCONV 4
#define OUTD 128
#define PROJW (DTR + 2*DS)   // 80
#define NLAYER 2
#define XSPLIT 8
#define OSPLIT 2
#define HSPLIT 6
#define NCHUNK 32
#define CLEN (LSEQ / NCHUNK)   // 64
#define DN (DI * DS)           // 24576

// ---------------- scratch ----------------
__device__ float g_x[LSEQ*DM];
__device__ float g_xz[LSEQ*2*DI];
__device__ float g_xc[LSEQ*DI];
__device__ float g_proj[LSEQ*PROJW];
__device__ float g_projp[XSPLIT*LSEQ*PROJW];
__device__ float g_delta[LSEQ*DI];
__device__ float g_yp[OSPLIT*LSEQ*DM];
__device__ float g_headp[HSPLIT*LSEQ*OUTD];
__device__ float g_carryA[NCHUNK*DN];
__device__ float g_carryB[NCHUNK*DN];
__device__ float g_sin[NCHUNK*DN];
// fp16 weights + activations
__device__ __half g_ipw16[NLAYER*2*DI*DM];
__device__ __half g_xpw16[NLAYER*PROJW*DI];
__device__ __half g_dtw16[NLAYER*DI*DTR];
__device__ __half g_opw16[NLAYER*DM*DI];
__device__ __half g_hw16[OUTD*DM];
__device__ __half g_xn16[LSEQ*DM];
__device__ __half g_xch[LSEQ*DI];
__device__ __half g_projh[LSEQ*PROJW];
__device__ __half g_yh[LSEQ*DI];

__device__ __forceinline__ uint32_t smem_u32(const void* p) {
    uint32_t a;
    asm("{ .reg .u64 t; cvta.to.shared.u64 t, %1; cvt.u32.u64 %0, t; }" : "=r"(a) : "l"(p));
    return a;
}
__device__ __forceinline__ void ldsm_x4(uint32_t& r0, uint32_t& r1, uint32_t& r2, uint32_t& r3, uint32_t addr) {
    asm volatile("ldmatrix.sync.aligned.m8n8.x4.shared.b16 {%0,%1,%2,%3}, [%4];"
                 : "=r"(r0), "=r"(r1), "=r"(r2), "=r"(r3) : "r"(addr));
}
__device__ __forceinline__ void mma16816(float* c, const uint32_t* a, uint32_t b0, uint32_t b1) {
    asm volatile("mma.sync.aligned.m16n8k16.row.col.f32.f16.f16.f32 "
                 "{%0,%1,%2,%3}, {%4,%5,%6,%7}, {%8,%9}, {%0,%1,%2,%3};"
                 : "+f"(c[0]), "+f"(c[1]), "+f"(c[2]), "+f"(c[3])
                 : "r"(a[0]), "r"(a[1]), "r"(a[2]), "r"(a[3]), "r"(b0), "r"(b1));
}
__device__ __forceinline__ void cpasync16(uint32_t dst, const void* src, int sz) {
    asm volatile("cp.async.cg.shared.global [%0], [%1], 16, %2;"
                 :: "r"(dst), "l"(src), "r"(sz) : "memory");
}

// ---------------- fp16 cp.async tensor-core GEMM ----------------
// C[M,N] = A[M,K] * B[N,K]^T, A/B fp16, C fp32
// mode 0: plain; 1: softplus(acc + bias[n])
// kchunk>0: K-range [bz*kchunk,+kchunk), C += bz*czstride
#define TBM 128
#define TBN 128
#define TBK 32
#define APAD 40                       // halves; 80B row stride -> ldsm conflict-free
#define ASTAGE (TBM * APAD * 2)       // 10240 B
#define NSTAGE 4
#define GSMEM (NSTAGE * 2 * ASTAGE)   // 81920 B -> 2 CTAs/SM

__global__ void __launch_bounds__(256, 2)
gemm_f16(const __half* __restrict__ A, int lda,
         const __half* __restrict__ B, int ldb,
         float* __restrict__ C, int ldc,
         int N, int K, const float* __restrict__ bias, int mode,
         int kchunk, size_t czstride) {
    extern __shared__ __align__(16) char smem[];
    uint32_t sA = smem_u32(smem);
    uint32_t sB = sA + NSTAGE * ASTAGE;

    int t = threadIdx.x;
    int m0 = blockIdx.y * TBM, n0 = blockIdx.x * TBN;
    int wid = t >> 5, lane = t & 31;
    int wm = (wid & 1) * 64;
    int wn = (wid >> 1) * 32;

    int kbeg = 0, kend = K;
    if (kchunk > 0) {
        kbeg = blockIdx.z * kchunk;
        kend = min(kbeg + kchunk, K);
        C += (size_t)blockIdx.z * czstride;
    }
    int Klocal = kend - kbeg;
    int nk = (Klocal + TBK - 1) / TBK;

    int a_row = wm + (lane & 15);
    int a_koff = (lane >> 4) << 3;
    int b_row = wn + ((lane >> 4) << 3) + (lane & 7);
    int b_koff = lane & 8;

    float acc[4][4][4];
    #pragma unroll
    for (int i = 0; i < 4; i++)
        #pragma unroll
        for (int j = 0; j < 4; j++)
            #pragma unroll
            for (int q = 0; q < 4; q++) acc[i][j][q] = 0.f;

    // one stage = 128 rows x 32 halves per matrix = 512 x 16B chunks -> 2/thread/matrix
    auto issue = [&](int kt) {
        if (kt < nk) {
            int buf = kt & (NSTAGE - 1);
            #pragma unroll
            for (int i = 0; i < 2; i++) {
                int idx = t + i * 256;          // 0..511
                int row = idx >> 2, ch = idx & 3;
                int kOff = kt * TBK + ch * 8;   // halves from kbeg
                int szA = (Klocal - kOff) * 2;
                szA = szA < 0 ? 0 : (szA > 16 ? 16 : szA);
                uint32_t doff = (uint32_t)buf * ASTAGE + (uint32_t)(row * APAD + ch * 8) * 2;
                const __half* srcA = (szA > 0) ? (A + (size_t)(m0 + row) * lda + kbeg + kOff) : A;
                cpasync16(sA + doff, srcA, szA);
                int brow = n0 + row;
                int szB = (brow < N) ? szA : 0;
                const __half* srcB = (szB > 0) ? (B + (size_t)brow * ldb + kbeg + kOff) : B;
                cpasync16(sB + doff, srcB, szB);
            }
        }
        asm volatile("cp.async.commit_group;" ::: "memory");
    };

    issue(0);
    issue(1);
    issue(2);

    for (int kt = 0; kt < nk; kt++) {
        int buf = kt & (NSTAGE - 1);
        asm volatile("cp.async.wait_group 2;" ::: "memory");
        __syncthreads();
        uint32_t aBase = sA + buf * ASTAGE;
        uint32_t bBase = sB + buf * ASTAGE;
        #pragma unroll
        for (int k16 = 0; k16 < 2; k16++) {
            uint32_t af[4][4];
            #pragma unroll
            for (int mt = 0; mt < 4; mt++) {
                uint32_t addr = aBase + ((a_row + mt * 16) * APAD + k16 * 16 + a_koff) * 2;
                ldsm_x4(af[mt][0], af[mt][1], af[mt][2], af[mt][3], addr);
            }
            uint32_t bf[4][2];
            #pragma unroll
            for (int np = 0; np < 2; np++) {
                uint32_t addr = bBase + ((b_row + np * 16) * APAD + k16 * 16 + b_koff) * 2;
                uint32_t r0, r1, r2, r3;
                ldsm_x4(r0, r1, r2, r3, addr);
                bf[np * 2 + 0][0] = r0; bf[np * 2 + 0][1] = r1;
                bf[np * 2 + 1][0] = r2; bf[np * 2 + 1][1] = r3;
            }
            #pragma unroll
            for (int mt = 0; mt < 4; mt++)
                #pragma unroll
                for (int nt = 0; nt < 4; nt++)
                    mma16816(acc[mt][nt], af[mt], bf[nt][0], bf[nt][1]);
        }
        issue(kt + 3);
    }

    int qr = lane >> 2;
    int qc = (lane & 3) * 2;
    #pragma unroll
    for (int mt = 0; mt < 4; mt++) {
        #pragma unroll
        for (int nt = 0; nt < 4; nt++) {
            int cb = n0 + wn + nt * 8;
            if (cb >= N) continue;
            int c = cb + qc;
            int r0 = m0 + wm + mt * 16 + qr;
            float* p0 = C + (size_t)r0 * ldc + c;
            float* p1 = C + (size_t)(r0 + 8) * ldc + c;
            float v0 = acc[mt][nt][0], v1 = acc[mt][nt][1];
            float v2 = acc[mt][nt][2], v3 = acc[mt][nt][3];
            if (mode == 1) {
                float b0 = bias[c], b1 = bias[c + 1];
                v0 += b0; v1 += b1; v2 += b0; v3 += b1;
                v0 = (v0 > 20.f) ? v0 : log1pf(__expf(v0));
                v1 = (v1 > 20.f) ? v1 : log1pf(__expf(v1));
                v2 = (v2 > 20.f) ? v2 : log1pf(__expf(v2));
                v3 = (v3 > 20.f) ? v3 : log1pf(__expf(v3));
            }
            p0[0] = v0; p0[1] = v1;
            p1[0] = v2; p1[1] = v3;
        }
    }
}

// ---------------- converts / reduces / small kernels ----------------
__global__ void f32tof16(const float* __restrict__ in, __half* __restrict__ out, int n) {
    int i = (blockIdx.x * blockDim.x + threadIdx.x) * 2;
    if (i < n) {
        float2 v = *(const float2*)(in + i);
        *(__half2*)(out + i) = __floats2half2_rn(v.x, v.y);
    }
}

__global__ void reduce_k(const float* __restrict__ part, float* __restrict__ out,
                         int n, int nz, size_t stride) {
    int i = blockIdx.x * blockDim.x + threadIdx.x;
    if (i >= n) return;
    float s = 0.f;
    for (int z = 0; z < nz; z++) s += part[(size_t)z * stride + i];
    out[i] = s;
}
__global__ void reduce_k_h(const float* __restrict__ part, float* __restrict__ out,
                           __half* __restrict__ outh, int n, int nz, size_t stride) {
    int i = blockIdx.x * blockDim.x + threadIdx.x;
    if (i >= n) return;
    float s = 0.f;
    for (int z = 0; z < nz; z++) s += part[(size_t)z * stride + i];
    out[i] = s;
    outh[i] = __float2half(s);
}
__global__ void reduce_k_res(const float* __restrict__ part, float* __restrict__ out,
                             int n, int nz, size_t stride) {
    int i = blockIdx.x * blockDim.x + threadIdx.x;
    if (i >= n) return;
    float s = out[i];
    for (int z = 0; z < nz; z++) s += part[(size_t)z * stride + i];
    out[i] = s;
}

__global__ void copy_kernel(const float* __restrict__ in, float* __restrict__ out, int n) {
    int i = blockIdx.x * blockDim.x + threadIdx.x;
    if (i < n) out[i] = in[i];
}

__global__ void rmsnorm16_kernel(const float* __restrict__ x, const float* __restrict__ w,
                                 __half* __restrict__ out) {
    int l = blockIdx.x;
    const float* xr = x + (size_t)l * DM;
    __shared__ float red[8];
    __shared__ float s_r;
    float ss = 0.f;
    for (int i = threadIdx.x; i < DM; i += 256) { float v = xr[i]; ss += v * v; }
    #pragma unroll
    for (int o = 16; o; o >>= 1) ss += __shfl_xor_sync(0xffffffffu, ss, o);
    if ((threadIdx.x & 31) == 0) red[threadIdx.x >> 5] = ss;
    __syncthreads();
    if (threadIdx.x == 0) {
        float tt = 0.f;
        #pragma unroll
        for (int i = 0; i < 8; i++) tt += red[i];
        s_r = rsqrtf(tt / DM + 1e-5f);
    }
    __syncthreads();
    float r = s_r;
    for (int i = threadIdx.x; i < DM; i += 256)
        out[(size_t)l * DM + i] = __float2half(xr[i] * r * w[i]);
}

__global__ void conv_silu_kernel(const float* __restrict__ xz, const float* __restrict__ w,
                                 const float* __restrict__ b, float* __restrict__ out,
                                 __half* __restrict__ outh) {
    int idx = blockIdx.x * blockDim.x + threadIdx.x;
    if (idx >= LSEQ * DI) return;
    int l = idx / DI, c = idx % DI;
    float acc = b[c];
    #pragma unroll
    for (int j = 0; j < DCONV; j++) {
        int ls = l - (DCONV - 1) + j;
        if (ls >= 0) acc += w[c * DCONV + j] * xz[(size_t)ls * (2 * DI) + c];
    }
    float v = acc / (1.f + __expf(-acc));
    out[idx] = v;
    outh[idx] = __float2half(v);
}

// ---------------- 3-phase parallel scan ----------------
__global__ void scan_p1(const float* __restrict__ delta, const float* __restrict__ u,
                        const float* __restrict__ proj, const float* __restrict__ A_log,
                        float* __restrict__ carryA, float* __restrict__ carryB) {
    int gid = blockIdx.x * blockDim.x + threadIdx.x;
    int c = gid / DN;
    int r = gid - c * DN;
    int d = r >> 4, n = r & 15;
    float A = -__expf(A_log[d * DS + n]);
    float ap = 1.f, s = 0.f;
    int l0 = c * CLEN;
    for (int l = l0; l < l0 + CLEN; l++) {
        float dl = delta[(size_t)l * DI + d];
        float ul = u[(size_t)l * DI + d];
        float Bn = proj[l * PROJW + DTR + n];
        float a = __expf(dl * A);
        ap *= a;
        s = fmaf(a, s, (dl * ul) * Bn);
    }
    carryA[gid] = ap;
    carryB[gid] = s;
}

__global__ void scan_p2(const float* __restrict__ carryA, const float* __restrict__ carryB,
                        float* __restrict__ sin_) {
    int gid = blockIdx.x * blockDim.x + threadIdx.x;
    float s = 0.f;
    #pragma unroll
    for (int c = 0; c < NCHUNK; c++) {
        sin_[c * DN + gid] = s;
        s = fmaf(carryA[c * DN + gid], s, carryB[c * DN + gid]);
    }
}

__global__ void scan_p3(const float* __restrict__ delta, const float* __restrict__ u,
                        const float* __restrict__ proj, const float* __restrict__ xz,
                        const float* __restrict__ A_log, const float* __restrict__ Dv,
                        const float* __restrict__ sin_, __half* __restrict__ yh) {
    int gid = blockIdx.x * blockDim.x + threadIdx.x;
    int c = gid / DN;
    int r = gid - c * DN;
    int d = r >> 4, n = r & 15;
    float A = -__expf(A_log[d * DS + n]);
    float Dd = Dv[d];
    float s = sin_[gid];
    int l0 = c * CLEN;
    for (int l = l0; l < l0 + CLEN; l++) {
        float dl = delta[(size_t)l * DI + d];
        float ul = u[(size_t)l * DI + d];
        float Bn = proj[l * PROJW + DTR + n];
        float Cn = proj[l * PROJW + DTR + DS + n];
        float a = __expf(dl * A);
        s = fmaf(a, s, (dl * ul) * Bn);
        float v = s * Cn;
        v += __shfl_xor_sync(0xffffffffu, v, 8, 16);
        v += __shfl_xor_sync(0xffffffffu, v, 4, 16);
        v += __shfl_xor_sync(0xffffffffu, v, 2, 16);
        v += __shfl_xor_sync(0xffffffffu, v, 1, 16);
        if (n == 0) {
            float res = xz[(size_t)l * (2 * DI) + DI + d];
            float g = res / (1.f + __expf(-res));
            yh[(size_t)l * DI + d] = __float2half((v + ul * Dd) * g);
        }
    }
}

// ---------------- host orchestration ----------------
extern "C" void kernel_launch(void* const* d_in, const int* in_sizes, int n_in,
                              void* d_out, int out_size) {
    const float* x_in      = (const float*)d_in[0];
    const float* in_proj_w = (const float*)d_in[1];
    const float* conv_w    = (const float*)d_in[2];
    const float* conv_b    = (const float*)d_in[3];
    const float* x_proj_w  = (const float*)d_in[4];
    const float* dt_proj_w = (const float*)d_in[5];
    const float* dt_proj_b = (const float*)d_in[6];
    const float* A_log     = (const float*)d_in[7];
    const float* Dv        = (const float*)d_in[8];
    const float* out_proj_w= (const float*)d_in[9];
    const float* norm_w    = (const float*)d_in[10];
    const float* norm_f_w  = (const float*)d_in[11];
    const float* head_w    = (const float*)d_in[12];
    float* out = (float*)d_out;

    float *gx, *gxz, *gxc, *gproj, *gprojp, *gdelta, *gyp, *gheadp, *gcA, *gcB, *gsin;
    __half *ipw16, *xpw16, *dtw16, *opw16, *hw16, *xn16, *xch, *projh, *yh;
    cudaGetSymbolAddress((void**)&gx,     g_x);
    cudaGetSymbolAddress((void**)&gxz,    g_xz);
    cudaGetSymbolAddress((void**)&gxc,    g_xc);
    cudaGetSymbolAddress((void**)&gproj,  g_proj);
    cudaGetSymbolAddress((void**)&gprojp, g_projp);
    cudaGetSymbolAddress((void**)&gdelta, g_delta);
    cudaGetSymbolAddress((void**)&gyp,    g_yp);
    cudaGetSymbolAddress((void**)&gheadp, g_headp);
    cudaGetSymbolAddress((void**)&gcA,    g_carryA);
    cudaGetSymbolAddress((void**)&gcB,    g_carryB);
    cudaGetSymbolAddress((void**)&gsin,   g_sin);
    cudaGetSymbolAddress((void**)&ipw16,  g_ipw16);
    cudaGetSymbolAddress((void**)&xpw16,  g_xpw16);
    cudaGetSymbolAddress((void**)&dtw16,  g_dtw16);
    cudaGetSymbolAddress((void**)&opw16,  g_opw16);
    cudaGetSymbolAddress((void**)&hw16,   g_hw16);
    cudaGetSymbolAddress((void**)&xn16,   g_xn16);
    cudaGetSymbolAddress((void**)&xch,    g_xch);
    cudaGetSymbolAddress((void**)&projh,  g_projh);
    cudaGetSymbolAddress((void**)&yh,     g_yh);

    cudaFuncSetAttribute(gemm_f16, cudaFuncAttributeMaxDynamicSharedMemorySize, GSMEM);

    {
        int n;
        n = NLAYER * 2 * DI * DM; f32tof16<<<(n/2 + 255)/256, 256>>>(in_proj_w, ipw16, n);
        n = NLAYER * PROJW * DI;  f32tof16<<<(n/2 + 255)/256, 256>>>(x_proj_w, xpw16, n);
        n = NLAYER * DI * DTR;    f32tof16<<<(n/2 + 255)/256, 256>>>(dt_proj_w, dtw16, n);
        n = NLAYER * DM * DI;     f32tof16<<<(n/2 + 255)/256, 256>>>(out_proj_w, opw16, n);
        n = OUTD * DM;            f32tof16<<<(n/2 + 255)/256, 256>>>(head_w, hw16, n);
    }

    copy_kernel<<<(LSEQ * DM + 255) / 256, 256>>>(x_in, gx, LSEQ * DM);

    for (int i = 0; i < NLAYER; i++) {
        const __half* ipw = ipw16 + (size_t)i * 2 * DI * DM;
        const float*  cw  = conv_w     + (size_t)i * DI * DCONV;
        const float*  cb  = conv_b     + (size_t)i * DI;
        const __half* xpw = xpw16 + (size_t)i * PROJW * DI;
        const __half* dtw = dtw16 + (size_t)i * DI * DTR;
        const float*  dtb = dt_proj_b  + (size_t)i * DI;
        const float*  al  = A_log      + (size_t)i * DI * DS;
        const float*  dv  = Dv         + (size_t)i * DI;
        const __half* opw = opw16 + (size_t)i * DM * DI;
        const float*  nw  = norm_w     + (size_t)i * DM;

        rmsnorm16_kernel<<<LSEQ, 256>>>(gx, nw, xn16);

        gemm_f16<<<dim3(2 * DI / TBN, LSEQ / TBM), 256, GSMEM>>>(
            xn16, DM, ipw, DM, gxz, 2 * DI, 2 * DI, DM, nullptr, 0, 0, 0);
        conv_silu_kernel<<<(LSEQ * DI + 255) / 256, 256>>>(gxz, cw, cb, gxc, xch);

        gemm_f16<<<dim3(1, LSEQ / TBM, XSPLIT), 256, GSMEM>>>(
            xch, DI, xpw, DI, gprojp, PROJW, PROJW, DI, nullptr, 0,
            DI / XSPLIT, (size_t)LSEQ * PROJW);
        reduce_k_h<<<(LSEQ * PROJW + 255) / 256, 256>>>(
            gprojp, gproj, projh, LSEQ * PROJW, XSPLIT, (size_t)LSEQ * PROJW);

        gemm_f16<<<dim3(DI / TBN, LSEQ / TBM), 256, GSMEM>>>(
            projh, PROJW, dtw, DTR, gdelta, DI, DI, DTR, dtb, 1, 0, 0);

        scan_p1<<<NCHUNK * DN / 256, 256>>>(gdelta, gxc, gproj, al, gcA, gcB);
        scan_p2<<<DN / 256, 256>>>(gcA, gcB, gsin);
        scan_p3<<<NCHUNK * DN / 256, 256>>>(gdelta, gxc, gproj, gxz, al, dv, gsin, yh);

        gemm_f16<<<dim3(DM / TBN, LSEQ / TBM, OSPLIT), 256, GSMEM>>>(
            yh, DI, opw, DI, gyp, DM, DM, DI, nullptr, 0,
            DI / OSPLIT, (size_t)LSEQ * DM);
        reduce_k_res<<<(LSEQ * DM + 255) / 256, 256>>>(
            gyp, gx, LSEQ * DM, OSPLIT, (size_t)LSEQ * DM);
    }

    rmsnorm16_kernel<<<LSEQ, 256>>>(gx, norm_f_w, xn16);
    gemm_f16<<<dim3(OUTD / TBN, LSEQ / TBM, HSPLIT), 256, GSMEM>>>(
        xn16, DM, hw16, DM, gheadp, OUTD, OUTD, DM, nullptr, 0,
        DM / HSPLIT, (size_t)LSEQ * OUTD);
    reduce_k<<<(LSEQ * OUTD + 255) / 256, 256>>>(
        gheadp, out, LSEQ * OUTD, HSPLIT, (size_t)LSEQ * OUTD);
}

// round 11
// speedup vs baseline: 6.7838x; 1.1802x over previous
#include <cuda_runtime.h>
#include <cuda_fp16.h>
#include <math.h>
#include <stdint.h>

#define LSEQ 2048
#define DM 768
#define DI 1536
#define DS 16
#define DTR 48
#define DCONV 4
#define OUTD 128
#define PROJW (DTR + 2*DS)   // 80
#define NLAYER 2
#define ISPLIT 2
#define XSPLIT 16
#define OSPLIT 3
#define HSPLIT 12
#define NCHUNK 32
#define CLEN (LSEQ / NCHUNK)   // 64
#define DN (DI * DS)           // 24576

// ---------------- scratch ----------------
__device__ float g_x[LSEQ*DM];
__device__ float g_xz[LSEQ*2*DI];
__device__ float g_ipp[ISPLIT*LSEQ*2*DI];
__device__ float g_xc[LSEQ*DI];
__device__ float g_proj[LSEQ*PROJW];
__device__ float g_projp[XSPLIT*LSEQ*PROJW];
__device__ float g_delta[LSEQ*DI];
__device__ float g_yp[OSPLIT*LSEQ*DM];
__device__ float g_headp[HSPLIT*LSEQ*OUTD];
__device__ float g_carryA[NCHUNK*DN];
__device__ float g_carryB[NCHUNK*DN];
__device__ float g_sin[NCHUNK*DN];
// fp16 weights + activations
__device__ __half g_ipw16[NLAYER*2*DI*DM];
__device__ __half g_xpw16[NLAYER*PROJW*DI];
__device__ __half g_dtw16[NLAYER*DI*DTR];
__device__ __half g_opw16[NLAYER*DM*DI];
__device__ __half g_hw16[OUTD*DM];
__device__ __half g_xn16[LSEQ*DM];
__device__ __half g_xch[LSEQ*DI];
__device__ __half g_projh[LSEQ*PROJW];
__device__ __half g_yh[LSEQ*DI];

__device__ __forceinline__ uint32_t smem_u32(const void* p) {
    uint32_t a;
    asm("{ .reg .u64 t; cvta.to.shared.u64 t, %1; cvt.u32.u64 %0, t; }" : "=r"(a) : "l"(p));
    return a;
}
__device__ __forceinline__ void ldsm_x4(uint32_t& r0, uint32_t& r1, uint32_t& r2, uint32_t& r3, uint32_t addr) {
    asm volatile("ldmatrix.sync.aligned.m8n8.x4.shared.b16 {%0,%1,%2,%3}, [%4];"
                 : "=r"(r0), "=r"(r1), "=r"(r2), "=r"(r3) : "r"(addr));
}
__device__ __forceinline__ void mma16816(float* c, const uint32_t* a, uint32_t b0, uint32_t b1) {
    asm volatile("mma.sync.aligned.m16n8k16.row.col.f32.f16.f16.f32 "
                 "{%0,%1,%2,%3}, {%4,%5,%6,%7}, {%8,%9}, {%0,%1,%2,%3};"
                 : "+f"(c[0]), "+f"(c[1]), "+f"(c[2]), "+f"(c[3])
                 : "r"(a[0]), "r"(a[1]), "r"(a[2]), "r"(a[3]), "r"(b0), "r"(b1));
}
__device__ __forceinline__ void cpasync16(uint32_t dst, const void* src, int sz) {
    asm volatile("cp.async.cg.shared.global [%0], [%1], 16, %2;"
                 :: "r"(dst), "l"(src), "r"(sz) : "memory");
}

// ---------------- fp16 cp.async tensor-core GEMM (R10 core) ----------------
#define TBM 128
#define TBN 128
#define TBK 32
#define APAD 40
#define ASTAGE (TBM * APAD * 2)       // 10240 B
#define NSTAGE 4
#define GSMEM (NSTAGE * 2 * ASTAGE)   // 81920 B -> 2 CTAs/SM

__global__ void __launch_bounds__(256, 2)
gemm_f16(const __half* __restrict__ A, int lda,
         const __half* __restrict__ B, int ldb,
         float* __restrict__ C, int ldc,
         int N, int K, const float* __restrict__ bias, int mode,
         int kchunk, size_t czstride) {
    extern __shared__ __align__(16) char smem[];
    uint32_t sA = smem_u32(smem);
    uint32_t sB = sA + NSTAGE * ASTAGE;

    int t = threadIdx.x;
    int m0 = blockIdx.y * TBM, n0 = blockIdx.x * TBN;
    int wid = t >> 5, lane = t & 31;
    int wm = (wid & 1) * 64;
    int wn = (wid >> 1) * 32;

    int kbeg = 0, kend = K;
    if (kchunk > 0) {
        kbeg = blockIdx.z * kchunk;
        kend = min(kbeg + kchunk, K);
        C += (size_t)blockIdx.z * czstride;
    }
    int Klocal = kend - kbeg;
    int nk = (Klocal + TBK - 1) / TBK;

    int a_row = wm + (lane & 15);
    int a_koff = (lane >> 4) << 3;
    int b_row = wn + ((lane >> 4) << 3) + (lane & 7);
    int b_koff = lane & 8;

    float acc[4][4][4];
    #pragma unroll
    for (int i = 0; i < 4; i++)
        #pragma unroll
        for (int j = 0; j < 4; j++)
            #pragma unroll
            for (int q = 0; q < 4; q++) acc[i][j][q] = 0.f;

    auto issue = [&](int kt) {
        if (kt < nk) {
            int buf = kt & (NSTAGE - 1);
            #pragma unroll
            for (int i = 0; i < 2; i++) {
                int idx = t + i * 256;
                int row = idx >> 2, ch = idx & 3;
                int kOff = kt * TBK + ch * 8;
                int szA = (Klocal - kOff) * 2;
                szA = szA < 0 ? 0 : (szA > 16 ? 16 : szA);
                uint32_t doff = (uint32_t)buf * ASTAGE + (uint32_t)(row * APAD + ch * 8) * 2;
                const __half* srcA = (szA > 0) ? (A + (size_t)(m0 + row) * lda + kbeg + kOff) : A;
                cpasync16(sA + doff, srcA, szA);
                int brow = n0 + row;
                int szB = (brow < N) ? szA : 0;
                const __half* srcB = (szB > 0) ? (B + (size_t)brow * ldb + kbeg + kOff) : B;
                cpasync16(sB + doff, srcB, szB);
            }
        }
        asm volatile("cp.async.commit_group;" ::: "memory");
    };

    issue(0);
    issue(1);
    issue(2);

    for (int kt = 0; kt < nk; kt++) {
        int buf = kt & (NSTAGE - 1);
        asm volatile("cp.async.wait_group 2;" ::: "memory");
        __syncthreads();
        uint32_t aBase = sA + buf * ASTAGE;
        uint32_t bBase = sB + buf * ASTAGE;
        #pragma unroll
        for (int k16 = 0; k16 < 2; k16++) {
            uint32_t af[4][4];
            #pragma unroll
            for (int mt = 0; mt < 4; mt++) {
                uint32_t addr = aBase + ((a_row + mt * 16) * APAD + k16 * 16 + a_koff) * 2;
                ldsm_x4(af[mt][0], af[mt][1], af[mt][2], af[mt][3], addr);
            }
            uint32_t bf[4][2];
            #pragma unroll
            for (int np = 0; np < 2; np++) {
                uint32_t addr = bBase + ((b_row + np * 16) * APAD + k16 * 16 + b_koff) * 2;
                uint32_t r0, r1, r2, r3;
                ldsm_x4(r0, r1, r2, r3, addr);
                bf[np * 2 + 0][0] = r0; bf[np * 2 + 0][1] = r1;
                bf[np * 2 + 1][0] = r2; bf[np * 2 + 1][1] = r3;
            }
            #pragma unroll
            for (int mt = 0; mt < 4; mt++)
                #pragma unroll
                for (int nt = 0; nt < 4; nt++)
                    mma16816(acc[mt][nt], af[mt], bf[nt][0], bf[nt][1]);
        }
        issue(kt + 3);
    }

    int qr = lane >> 2;
    int qc = (lane & 3) * 2;
    #pragma unroll
    for (int mt = 0; mt < 4; mt++) {
        #pragma unroll
        for (int nt = 0; nt < 4; nt++) {
            int cb = n0 + wn + nt * 8;
            if (cb >= N) continue;
            int c = cb + qc;
            int r0 = m0 + wm + mt * 16 + qr;
            float* p0 = C + (size_t)r0 * ldc + c;
            float* p1 = C + (size_t)(r0 + 8) * ldc + c;
            float v0 = acc[mt][nt][0], v1 = acc[mt][nt][1];
            float v2 = acc[mt][nt][2], v3 = acc[mt][nt][3];
            if (mode == 1) {
                float b0 = bias[c], b1 = bias[c + 1];
                v0 += b0; v1 += b1; v2 += b0; v3 += b1;
                v0 = (v0 > 20.f) ? v0 : log1pf(__expf(v0));
                v1 = (v1 > 20.f) ? v1 : log1pf(__expf(v1));
                v2 = (v2 > 20.f) ? v2 : log1pf(__expf(v2));
                v3 = (v3 > 20.f) ? v3 : log1pf(__expf(v3));
            }
            p0[0] = v0; p0[1] = v1;
            p1[0] = v2; p1[1] = v3;
        }
    }
}

// ---------------- converts / reduces / small kernels ----------------
__global__ void f32tof16(const float* __restrict__ in, __half* __restrict__ out, int n) {
    int i = (blockIdx.x * blockDim.x + threadIdx.x) * 2;
    if (i < n) {
        float2 v = *(const float2*)(in + i);
        *(__half2*)(out + i) = __floats2half2_rn(v.x, v.y);
    }
}
__global__ void reduce_k(const float* __restrict__ part, float* __restrict__ out,
                         int n, int nz, size_t stride) {
    int i = blockIdx.x * blockDim.x + threadIdx.x;
    if (i >= n) return;
    float s = 0.f;
    for (int z = 0; z < nz; z++) s += part[(size_t)z * stride + i];
    out[i] = s;
}
__global__ void reduce_k_h(const float* __restrict__ part, float* __restrict__ out,
                           __half* __restrict__ outh, int n, int nz, size_t stride) {
    int i = blockIdx.x * blockDim.x + threadIdx.x;
    if (i >= n) return;
    float s = 0.f;
    for (int z = 0; z < nz; z++) s += part[(size_t)z * stride + i];
    out[i] = s;
    outh[i] = __float2half(s);
}
__global__ void reduce_k_res(const float* __restrict__ part, float* __restrict__ out,
                             int n, int nz, size_t stride) {
    int i = blockIdx.x * blockDim.x + threadIdx.x;
    if (i >= n) return;
    float s = out[i];
    for (int z = 0; z < nz; z++) s += part[(size_t)z * stride + i];
    out[i] = s;
}
__global__ void copy_kernel(const float* __restrict__ in, float* __restrict__ out, int n) {
    int i = blockIdx.x * blockDim.x + threadIdx.x;
    if (i < n) out[i] = in[i];
}

__global__ void rmsnorm16_kernel(const float* __restrict__ x, const float* __restrict__ w,
                                 __half* __restrict__ out) {
    int l = blockIdx.x;
    const float* xr = x + (size_t)l * DM;
    __shared__ float red[8];
    __shared__ float s_r;
    float ss = 0.f;
    for (int i = threadIdx.x; i < DM; i += 256) { float v = xr[i]; ss += v * v; }
    #pragma unroll
    for (int o = 16; o; o >>= 1) ss += __shfl_xor_sync(0xffffffffu, ss, o);
    if ((threadIdx.x & 31) == 0) red[threadIdx.x >> 5] = ss;
    __syncthreads();
    if (threadIdx.x == 0) {
        float tt = 0.f;
        #pragma unroll
        for (int i = 0; i < 8; i++) tt += red[i];
        s_r = rsqrtf(tt / DM + 1e-5f);
    }
    __syncthreads();
    float r = s_r;
    for (int i = threadIdx.x; i < DM; i += 256)
        out[(size_t)l * DM + i] = __float2half(xr[i] * r * w[i]);
}

__global__ void conv_silu_kernel(const float* __restrict__ xz, const float* __restrict__ w,
                                 const float* __restrict__ b, float* __restrict__ out,
                                 __half* __restrict__ outh) {
    int idx = blockIdx.x * blockDim.x + threadIdx.x;
    if (idx >= LSEQ * DI) return;
    int l = idx / DI, c = idx % DI;
    float acc = b[c];
    #pragma unroll
    for (int j = 0; j < DCONV; j++) {
        int ls = l - (DCONV - 1) + j;
        if (ls >= 0) acc += w[c * DCONV + j] * xz[(size_t)ls * (2 * DI) + c];
    }
    float v = acc / (1.f + __expf(-acc));
    out[idx] = v;
    outh[idx] = __float2half(v);
}

// ---------------- 3-phase parallel scan, smem-staged ----------------
// block = 256 threads = 16 d-groups x 16 n-lanes, all same chunk c
__global__ void __launch_bounds__(256)
scan_p1(const float* __restrict__ delta, const float* __restrict__ u,
        const float* __restrict__ proj, const float* __restrict__ A_log,
        float* __restrict__ carryA, float* __restrict__ carryB) {
    __shared__ float sdel[CLEN][20];
    __shared__ float su[CLEN][20];
    __shared__ float sBC[CLEN][36];
    int tid = threadIdx.x;
    int gid0 = blockIdx.x * 256;
    int c = gid0 / DN;
    int r0 = gid0 - c * DN;
    int d0 = r0 >> 4;
    int l0 = c * CLEN;
    // stage delta & u: 64 rows x 16 floats each
    {
        int l = tid >> 2, seg = (tid & 3) * 4;
        *(float4*)&sdel[l][seg] = *(const float4*)(delta + (size_t)(l0 + l) * DI + d0 + seg);
        *(float4*)&su[l][seg]   = *(const float4*)(u     + (size_t)(l0 + l) * DI + d0 + seg);
    }
    // stage B|C: 64 rows x 32 floats
    #pragma unroll
    for (int i = 0; i < 2; i++) {
        int q = tid + i * 256;
        int l = q >> 3, seg = (q & 7) * 4;
        *(float4*)&sBC[l][seg] = *(const float4*)(proj + (size_t)(l0 + l) * PROJW + DTR + seg);
    }
    __syncthreads();
    int j = tid >> 4, n = tid & 15;
    float A = -__expf(A_log[(d0 + j) * DS + n]);
    float ap = 1.f, s = 0.f;
    #pragma unroll 4
    for (int l = 0; l < CLEN; l++) {
        float dl = sdel[l][j];
        float ul = su[l][j];
        float Bn = sBC[l][n];
        float a = __expf(dl * A);
        ap *= a;
        s = fmaf(a, s, (dl * ul) * Bn);
    }
    carryA[gid0 + tid] = ap;
    carryB[gid0 + tid] = s;
}

__global__ void scan_p2(const float* __restrict__ carryA, const float* __restrict__ carryB,
                        float* __restrict__ sin_) {
    int gid = blockIdx.x * blockDim.x + threadIdx.x;
    float s = 0.f;
    #pragma unroll
    for (int c = 0; c < NCHUNK; c++) {
        sin_[c * DN + gid] = s;
        s = fmaf(carryA[c * DN + gid], s, carryB[c * DN + gid]);
    }
}

__global__ void __launch_bounds__(256)
scan_p3(const float* __restrict__ delta, const float* __restrict__ u,
        const float* __restrict__ proj, const float* __restrict__ xz,
        const float* __restrict__ A_log, const float* __restrict__ Dv,
        const float* __restrict__ sin_, __half* __restrict__ yh) {
    __shared__ float sdel[CLEN][20];
    __shared__ float su[CLEN][20];
    __shared__ float sBC[CLEN][36];
    __shared__ float sres[CLEN][20];
    int tid = threadIdx.x;
    int gid0 = blockIdx.x * 256;
    int c = gid0 / DN;
    int r0 = gid0 - c * DN;
    int d0 = r0 >> 4;
    int l0 = c * CLEN;
    {
        int l = tid >> 2, seg = (tid & 3) * 4;
        *(float4*)&sdel[l][seg] = *(const float4*)(delta + (size_t)(l0 + l) * DI + d0 + seg);
        *(float4*)&su[l][seg]   = *(const float4*)(u     + (size_t)(l0 + l) * DI + d0 + seg);
        *(float4*)&sres[l][seg] = *(const float4*)(xz    + (size_t)(l0 + l) * (2 * DI) + DI + d0 + seg);
    }
    #pragma unroll
    for (int i = 0; i < 2; i++) {
        int q = tid + i * 256;
        int l = q >> 3, seg = (q & 7) * 4;
        *(float4*)&sBC[l][seg] = *(const float4*)(proj + (size_t)(l0 + l) * PROJW + DTR + seg);
    }
    __syncthreads();
    int j = tid >> 4, n = tid & 15;
    float A = -__expf(A_log[(d0 + j) * DS + n]);
    float Dd = Dv[d0 + j];
    float s = sin_[gid0 + tid];
    for (int l = 0; l < CLEN; l++) {
        float dl = sdel[l][j];
        float ul = su[l][j];
        float Bn = sBC[l][n];
        float Cn = sBC[l][16 + n];
        float a = __expf(dl * A);
        s = fmaf(a, s, (dl * ul) * Bn);
        float v = s * Cn;
        v += __shfl_xor_sync(0xffffffffu, v, 8, 16);
        v += __shfl_xor_sync(0xffffffffu, v, 4, 16);
        v += __shfl_xor_sync(0xffffffffu, v, 2, 16);
        v += __shfl_xor_sync(0xffffffffu, v, 1, 16);
        if (n == 0) {
            float res = sres[l][j];
            float g = res / (1.f + __expf(-res));
            yh[(size_t)(l0 + l) * DI + d0 + j] = __float2half((v + ul * Dd) * g);
        }
    }
}

// ---------------- host orchestration ----------------
extern "C" void kernel_launch(void* const* d_in, const int* in_sizes, int n_in,
                              void* d_out, int out_size) {
    const float* x_in      = (const float*)d_in[0];
    const float* in_proj_w = (const float*)d_in[1];
    const float* conv_w    = (const float*)d_in[2];
    const float* conv_b    = (const float*)d_in[3];
    const float* x_proj_w  = (const float*)d_in[4];
    const float* dt_proj_w = (const float*)d_in[5];
    const float* dt_proj_b = (const float*)d_in[6];
    const float* A_log     = (const float*)d_in[7];
    const float* Dv        = (const float*)d_in[8];
    const float* out_proj_w= (const float*)d_in[9];
    const float* norm_w    = (const float*)d_in[10];
    const float* norm_f_w  = (const float*)d_in[11];
    const float* head_w    = (const float*)d_in[12];
    float* out = (float*)d_out;

    float *gx, *gxz, *gipp, *gxc, *gproj, *gprojp, *gdelta, *gyp, *gheadp, *gcA, *gcB, *gsin;
    __half *ipw16, *xpw16, *dtw16, *opw16, *hw16, *xn16, *xch, *projh, *yh;
    cudaGetSymbolAddress((void**)&gx,     g_x);
    cudaGetSymbolAddress((void**)&gxz,    g_xz);
    cudaGetSymbolAddress((void**)&gipp,   g_ipp);
    cudaGetSymbolAddress((void**)&gxc,    g_xc);
    cudaGetSymbolAddress((void**)&gproj,  g_proj);
    cudaGetSymbolAddress((void**)&gprojp, g_projp);
    cudaGetSymbolAddress((void**)&gdelta, g_delta);
    cudaGetSymbolAddress((void**)&gyp,    g_yp);
    cudaGetSymbolAddress((void**)&gheadp, g_headp);
    cudaGetSymbolAddress((void**)&gcA,    g_carryA);
    cudaGetSymbolAddress((void**)&gcB,    g_carryB);
    cudaGetSymbolAddress((void**)&gsin,   g_sin);
    cudaGetSymbolAddress((void**)&ipw16,  g_ipw16);
    cudaGetSymbolAddress((void**)&xpw16,  g_xpw16);
    cudaGetSymbolAddress((void**)&dtw16,  g_dtw16);
    cudaGetSymbolAddress((void**)&opw16,  g_opw16);
    cudaGetSymbolAddress((void**)&hw16,   g_hw16);
    cudaGetSymbolAddress((void**)&xn16,   g_xn16);
    cudaGetSymbolAddress((void**)&xch,    g_xch);
    cudaGetSymbolAddress((void**)&projh,  g_projh);
    cudaGetSymbolAddress((void**)&yh,     g_yh);

    cudaFuncSetAttribute(gemm_f16, cudaFuncAttributeMaxDynamicSharedMemorySize, GSMEM);

    {
        int n;
        n = NLAYER * 2 * DI * DM; f32tof16<<<(n/2 + 255)/256, 256>>>(in_proj_w, ipw16, n);
        n = NLAYER * PROJW * DI;  f32tof16<<<(n/2 + 255)/256, 256>>>(x_proj_w, xpw16, n);
        n = NLAYER * DI * DTR;    f32tof16<<<(n/2 + 255)/256, 256>>>(dt_proj_w, dtw16, n);
        n = NLAYER * DM * DI;     f32tof16<<<(n/2 + 255)/256, 256>>>(out_proj_w, opw16, n);
        n = OUTD * DM;            f32tof16<<<(n/2 + 255)/256, 256>>>(head_w, hw16, n);
    }

    copy_kernel<<<(LSEQ * DM + 255) / 256, 256>>>(x_in, gx, LSEQ * DM);

    for (int i = 0; i < NLAYER; i++) {
        const __half* ipw = ipw16 + (size_t)i * 2 * DI * DM;
        const float*  cw  = conv_w     + (size_t)i * DI * DCONV;
        const float*  cb  = conv_b     + (size_t)i * DI;
        const __half* xpw = xpw16 + (size_t)i * PROJW * DI;
        const __half* dtw = dtw16 + (size_t)i * DI * DTR;
        const float*  dtb = dt_proj_b  + (size_t)i * DI;
        const float*  al  = A_log      + (size_t)i * DI * DS;
        const float*  dv  = Dv         + (size_t)i * DI;
        const __half* opw = opw16 + (size_t)i * DM * DI;
        const float*  nw  = norm_w     + (size_t)i * DM;

        rmsnorm16_kernel<<<LSEQ, 256>>>(gx, nw, xn16);

        // in_proj split-K x2: 768 blocks
        gemm_f16<<<dim3(2 * DI / TBN, LSEQ / TBM, ISPLIT), 256, GSMEM>>>(
            xn16, DM, ipw, DM, gipp, 2 * DI, 2 * DI, DM, nullptr, 0,
            DM / ISPLIT, (size_t)LSEQ * 2 * DI);
        reduce_k<<<(LSEQ * 2 * DI + 255) / 256, 256>>>(
            gipp, gxz, LSEQ * 2 * DI, ISPLIT, (size_t)LSEQ * 2 * DI);

        conv_silu_kernel<<<(LSEQ * DI + 255) / 256, 256>>>(gxz, cw, cb, gxc, xch);

        // x_proj split-K x16: 256 blocks
        gemm_f16<<<dim3(1, LSEQ / TBM, XSPLIT), 256, GSMEM>>>(
            xch, DI, xpw, DI, gprojp, PROJW, PROJW, DI, nullptr, 0,
            DI / XSPLIT, (size_t)LSEQ * PROJW);
        reduce_k_h<<<(LSEQ * PROJW + 255) / 256, 256>>>(
            gprojp, gproj, projh, LSEQ * PROJW, XSPLIT, (size_t)LSEQ * PROJW);

        // dt_proj + bias + softplus (K=48)
        gemm_f16<<<dim3(DI / TBN, LSEQ / TBM), 256, GSMEM>>>(
            projh, PROJW, dtw, DTR, gdelta, DI, DI, DTR, dtb, 1, 0, 0);

        // 3-phase parallel scan (smem-staged)
        scan_p1<<<NCHUNK * DN / 256, 256>>>(gdelta, gxc, gproj, al, gcA, gcB);
        scan_p2<<<DN / 256, 256>>>(gcA, gcB, gsin);
        scan_p3<<<NCHUNK * DN / 256, 256>>>(gdelta, gxc, gproj, gxz, al, dv, gsin, yh);

        // out_proj split-K x3 (288 blocks, one full wave), residual in reduce
        gemm_f16<<<dim3(DM / TBN, LSEQ / TBM, OSPLIT), 256, GSMEM>>>(
            yh, DI, opw, DI, gyp, DM, DM, DI, nullptr, 0,
            DI / OSPLIT, (size_t)LSEQ * DM);
        reduce_k_res<<<(LSEQ * DM + 255) / 256, 256>>>(
            gyp, gx, LSEQ * DM, OSPLIT, (size_t)LSEQ * DM);
    }

    rmsnorm16_kernel<<<LSEQ, 256>>>(gx, norm_f_w, xn16);
    // head split-K x12
    gemm_f16<<<dim3(OUTD / TBN, LSEQ / TBM, HSPLIT), 256, GSMEM>>>(
        xn16, DM, hw16, DM, gheadp, OUTD, OUTD, DM, nullptr, 0,
        DM / HSPLIT, (size_t)LSEQ * OUTD);
    reduce_k<<<(LSEQ * OUTD + 255) / 256, 256>>>(
        gheadp, out, LSEQ * OUTD, HSPLIT, (size_t)LSEQ * OUTD);
}

// round 12
// speedup vs baseline: 7.2942x; 1.0752x over previous
#include <cuda_runtime.h>
#include <cuda_fp16.h>
#include <math.h>
#include <stdint.h>

#define LSEQ 2048
#define DM 768
#define DI 1536
#define DS 16
#define DTR 48
#define DCONV 4
#define OUTD 128
#define PROJW (DTR + 2*DS)   // 80
#define NLAYER 2
#define ISPLIT 2
#define XSPLIT 16
#define OSPLIT 3
#define HSPLIT 12
#define NCHUNK 32
#define CLEN (LSEQ / NCHUNK)   // 64
#define DN (DI * DS)           // 24576

// ---------------- scratch ----------------
__device__ float g_x[LSEQ*DM];
__device__ float g_ipp[ISPLIT*LSEQ*2*DI];
__device__ float g_xc[LSEQ*DI];
__device__ float g_res[LSEQ*DI];
__device__ float g_proj[LSEQ*PROJW];
__device__ float g_projp[XSPLIT*LSEQ*PROJW];
__device__ float g_delta[LSEQ*DI];
__device__ float g_yp[OSPLIT*LSEQ*DM];
__device__ float g_headp[HSPLIT*LSEQ*OUTD];
__device__ float g_carryA[NCHUNK*DN];
__device__ float g_carryB[NCHUNK*DN];
__device__ float g_sin[NCHUNK*DN];
// fp16 weights + activations
__device__ __half g_ipw16[NLAYER*2*DI*DM];
__device__ __half g_xpw16[NLAYER*PROJW*DI];
__device__ __half g_dtw16[NLAYER*DI*DTR];
__device__ __half g_opw16[NLAYER*DM*DI];
__device__ __half g_hw16[OUTD*DM];
__device__ __half g_xn16[LSEQ*DM];
__device__ __half g_xch[LSEQ*DI];
__device__ __half g_projh[LSEQ*PROJW];
__device__ __half g_yh[LSEQ*DI];

__device__ __forceinline__ uint32_t smem_u32(const void* p) {
    uint32_t a;
    asm("{ .reg .u64 t; cvta.to.shared.u64 t, %1; cvt.u32.u64 %0, t; }" : "=r"(a) : "l"(p));
    return a;
}
__device__ __forceinline__ void ldsm_x4(uint32_t& r0, uint32_t& r1, uint32_t& r2, uint32_t& r3, uint32_t addr) {
    asm volatile("ldmatrix.sync.aligned.m8n8.x4.shared.b16 {%0,%1,%2,%3}, [%4];"
                 : "=r"(r0), "=r"(r1), "=r"(r2), "=r"(r3) : "r"(addr));
}
__device__ __forceinline__ void mma16816(float* c, const uint32_t* a, uint32_t b0, uint32_t b1) {
    asm volatile("mma.sync.aligned.m16n8k16.row.col.f32.f16.f16.f32 "
                 "{%0,%1,%2,%3}, {%4,%5,%6,%7}, {%8,%9}, {%0,%1,%2,%3};"
                 : "+f"(c[0]), "+f"(c[1]), "+f"(c[2]), "+f"(c[3])
                 : "r"(a[0]), "r"(a[1]), "r"(a[2]), "r"(a[3]), "r"(b0), "r"(b1));
}
__device__ __forceinline__ void cpasync16(uint32_t dst, const void* src, int sz) {
    asm volatile("cp.async.cg.shared.global [%0], [%1], 16, %2;"
                 :: "r"(dst), "l"(src), "r"(sz) : "memory");
}

// ---------------- fp16 cp.async tensor-core GEMM ----------------
#define TBM 128
#define TBN 128
#define TBK 32
#define APAD 40
#define ASTAGE (TBM * APAD * 2)
#define NSTAGE 4
#define GSMEM (NSTAGE * 2 * ASTAGE)   // 81920 B -> 2 CTAs/SM

__global__ void __launch_bounds__(256, 2)
gemm_f16(const __half* __restrict__ A, int lda,
         const __half* __restrict__ B, int ldb,
         float* __restrict__ C, int ldc,
         int N, int K, const float* __restrict__ bias, int mode,
         int kchunk, size_t czstride) {
    extern __shared__ __align__(16) char smem[];
    uint32_t sA = smem_u32(smem);
    uint32_t sB = sA + NSTAGE * ASTAGE;

    int t = threadIdx.x;
    int m0 = blockIdx.y * TBM, n0 = blockIdx.x * TBN;
    int wid = t >> 5, lane = t & 31;
    int wm = (wid & 1) * 64;
    int wn = (wid >> 1) * 32;

    int kbeg = 0, kend = K;
    if (kchunk > 0) {
        kbeg = blockIdx.z * kchunk;
        kend = min(kbeg + kchunk, K);
        C += (size_t)blockIdx.z * czstride;
    }
    int Klocal = kend - kbeg;
    int nk = (Klocal + TBK - 1) / TBK;

    int a_row = wm + (lane & 15);
    int a_koff = (lane >> 4) << 3;
    int b_row = wn + ((lane >> 4) << 3) + (lane & 7);
    int b_koff = lane & 8;

    float acc[4][4][4];
    #pragma unroll
    for (int i = 0; i < 4; i++)
        #pragma unroll
        for (int j = 0; j < 4; j++)
            #pragma unroll
            for (int q = 0; q < 4; q++) acc[i][j][q] = 0.f;

    auto issue = [&](int kt) {
        if (kt < nk) {
            int buf = kt & (NSTAGE - 1);
            #pragma unroll
            for (int i = 0; i < 2; i++) {
                int idx = t + i * 256;
                int row = idx >> 2, ch = idx & 3;
                int kOff = kt * TBK + ch * 8;
                int szA = (Klocal - kOff) * 2;
                szA = szA < 0 ? 0 : (szA > 16 ? 16 : szA);
                uint32_t doff = (uint32_t)buf * ASTAGE + (uint32_t)(row * APAD + ch * 8) * 2;
                const __half* srcA = (szA > 0) ? (A + (size_t)(m0 + row) * lda + kbeg + kOff) : A;
                cpasync16(sA + doff, srcA, szA);
                int brow = n0 + row;
                int szB = (brow < N) ? szA : 0;
                const __half* srcB = (szB > 0) ? (B + (size_t)brow * ldb + kbeg + kOff) : B;
                cpasync16(sB + doff, srcB, szB);
            }
        }
        asm volatile("cp.async.commit_group;" ::: "memory");
    };

    issue(0);
    issue(1);
    issue(2);

    for (int kt = 0; kt < nk; kt++) {
        int buf = kt & (NSTAGE - 1);
        asm volatile("cp.async.wait_group 2;" ::: "memory");
        __syncthreads();
        uint32_t aBase = sA + buf * ASTAGE;
        uint32_t bBase = sB + buf * ASTAGE;
        #pragma unroll
        for (int k16 = 0; k16 < 2; k16++) {
            uint32_t af[4][4];
            #pragma unroll
            for (int mt = 0; mt < 4; mt++) {
                uint32_t addr = aBase + ((a_row + mt * 16) * APAD + k16 * 16 + a_koff) * 2;
                ldsm_x4(af[mt][0], af[mt][1], af[mt][2], af[mt][3], addr);
            }
            uint32_t bf[4][2];
            #pragma unroll
            for (int np = 0; np < 2; np++) {
                uint32_t addr = bBase + ((b_row + np * 16) * APAD + k16 * 16 + b_koff) * 2;
                uint32_t r0, r1, r2, r3;
                ldsm_x4(r0, r1, r2, r3, addr);
                bf[np * 2 + 0][0] = r0; bf[np * 2 + 0][1] = r1;
                bf[np * 2 + 1][0] = r2; bf[np * 2 + 1][1] = r3;
            }
            #pragma unroll
            for (int mt = 0; mt < 4; mt++)
                #pragma unroll
                for (int nt = 0; nt < 4; nt++)
                    mma16816(acc[mt][nt], af[mt], bf[nt][0], bf[nt][1]);
        }
        issue(kt + 3);
    }

    int qr = lane >> 2;
    int qc = (lane & 3) * 2;
    #pragma unroll
    for (int mt = 0; mt < 4; mt++) {
        #pragma unroll
        for (int nt = 0; nt < 4; nt++) {
            int cb = n0 + wn + nt * 8;
            if (cb >= N) continue;
            int c = cb + qc;
            int r0 = m0 + wm + mt * 16 + qr;
            float* p0 = C + (size_t)r0 * ldc + c;
            float* p1 = C + (size_t)(r0 + 8) * ldc + c;
            float v0 = acc[mt][nt][0], v1 = acc[mt][nt][1];
            float v2 = acc[mt][nt][2], v3 = acc[mt][nt][3];
            if (mode == 1) {
                float b0 = bias[c], b1 = bias[c + 1];
                v0 += b0; v1 += b1; v2 += b0; v3 += b1;
                v0 = (v0 > 20.f) ? v0 : log1pf(__expf(v0));
                v1 = (v1 > 20.f) ? v1 : log1pf(__expf(v1));
                v2 = (v2 > 20.f) ? v2 : log1pf(__expf(v2));
                v3 = (v3 > 20.f) ? v3 : log1pf(__expf(v3));
            }
            p0[0] = v0; p0[1] = v1;
            p1[0] = v2; p1[1] = v3;
        }
    }
}

// ---------------- fused kernels ----------------
__global__ void f32tof16(const float* __restrict__ in, __half* __restrict__ out, int n) {
    int i = (blockIdx.x * blockDim.x + threadIdx.x) * 2;
    if (i < n) {
        float2 v = *(const float2*)(in + i);
        *(__half2*)(out + i) = __floats2half2_rn(v.x, v.y);
    }
}
__global__ void reduce_k(const float* __restrict__ part, float* __restrict__ out,
                         int n, int nz, size_t stride) {
    int i = blockIdx.x * blockDim.x + threadIdx.x;
    if (i >= n) return;
    float s = 0.f;
    for (int z = 0; z < nz; z++) s += part[(size_t)z * stride + i];
    out[i] = s;
}
__global__ void reduce_k_h(const float* __restrict__ part, float* __restrict__ out,
                           __half* __restrict__ outh, int n, int nz, size_t stride) {
    int i = blockIdx.x * blockDim.x + threadIdx.x;
    if (i >= n) return;
    float s = 0.f;
    for (int z = 0; z < nz; z++) s += part[(size_t)z * stride + i];
    out[i] = s;
    outh[i] = __float2half(s);
}
__global__ void copy_kernel(const float* __restrict__ in, float* __restrict__ out, int n) {
    int i = blockIdx.x * blockDim.x + threadIdx.x;
    if (i < n) out[i] = in[i];
}

// fused: residual += split-K partials, then rmsnorm -> fp16 normed row
// nz == 0: skip residual update (gx already holds x)
__global__ void __launch_bounds__(256)
resnorm16(const float* __restrict__ part, int nz, size_t stride,
          float* __restrict__ gx, const float* __restrict__ w,
          __half* __restrict__ out) {
    int l = blockIdx.x;
    int tid = threadIdx.x;
    __shared__ float red[8];
    __shared__ float s_r;
    float vals[3];
    float ss = 0.f;
    #pragma unroll
    for (int i = 0; i < 3; i++) {
        int c = tid + i * 256;
        size_t o = (size_t)l * DM + c;
        float s = gx[o];
        for (int z = 0; z < nz; z++) s += part[(size_t)z * stride + o];
        vals[i] = s;
        ss += s * s;
    }
    #pragma unroll
    for (int o = 16; o; o >>= 1) ss += __shfl_xor_sync(0xffffffffu, ss, o);
    if ((tid & 31) == 0) red[tid >> 5] = ss;
    __syncthreads();
    if (tid == 0) {
        float tt = 0.f;
        #pragma unroll
        for (int i = 0; i < 8; i++) tt += red[i];
        s_r = rsqrtf(tt / DM + 1e-5f);
    }
    __syncthreads();
    float r = s_r;
    #pragma unroll
    for (int i = 0; i < 3; i++) {
        int c = tid + i * 256;
        size_t o = (size_t)l * DM + c;
        if (nz > 0) gx[o] = vals[i];
        out[o] = __float2half(vals[i] * r * w[c]);
    }
}

// fused: in_proj partial-sum + causal conv + silu + res extraction
__global__ void fuse_conv(const float* __restrict__ p, const float* __restrict__ w,
                          const float* __restrict__ b, float* __restrict__ gxc,
                          __half* __restrict__ xch, float* __restrict__ gres) {
    int idx = blockIdx.x * blockDim.x + threadIdx.x;
    if (idx >= LSEQ * DI) return;
    int l = idx / DI, c = idx % DI;
    const size_t S = (size_t)LSEQ * 2 * DI;
    size_t ro = (size_t)l * 2 * DI + DI + c;
    gres[idx] = p[ro] + p[S + ro];
    float acc = b[c];
    #pragma unroll
    for (int j = 0; j < DCONV; j++) {
        int ls = l - (DCONV - 1) + j;
        if (ls >= 0) {
            size_t o = (size_t)ls * 2 * DI + c;
            acc += w[c * DCONV + j] * (p[o] + p[S + o]);
        }
    }
    float v = acc / (1.f + __expf(-acc));
    gxc[idx] = v;
    xch[idx] = __float2half(v);
}

// ---------------- 3-phase parallel scan, smem-staged ----------------
__global__ void __launch_bounds__(256)
scan_p1(const float* __restrict__ delta, const float* __restrict__ u,
        const float* __restrict__ proj, const float* __restrict__ A_log,
        float* __restrict__ carryA, float* __restrict__ carryB) {
    __shared__ float sdel[CLEN][20];
    __shared__ float su[CLEN][20];
    __shared__ float sBC[CLEN][36];
    int tid = threadIdx.x;
    int gid0 = blockIdx.x * 256;
    int c = gid0 / DN;
    int r0 = gid0 - c * DN;
    int d0 = r0 >> 4;
    int l0 = c * CLEN;
    {
        int l = tid >> 2, seg = (tid & 3) * 4;
        *(float4*)&sdel[l][seg] = *(const float4*)(delta + (size_t)(l0 + l) * DI + d0 + seg);
        *(float4*)&su[l][seg]   = *(const float4*)(u     + (size_t)(l0 + l) * DI + d0 + seg);
    }
    #pragma unroll
    for (int i = 0; i < 2; i++) {
        int q = tid + i * 256;
        int l = q >> 3, seg = (q & 7) * 4;
        *(float4*)&sBC[l][seg] = *(const float4*)(proj + (size_t)(l0 + l) * PROJW + DTR + seg);
    }
    __syncthreads();
    int j = tid >> 4, n = tid & 15;
    float A = -__expf(A_log[(d0 + j) * DS + n]);
    float ap = 1.f, s = 0.f;
    #pragma unroll 4
    for (int l = 0; l < CLEN; l++) {
        float dl = sdel[l][j];
        float ul = su[l][j];
        float Bn = sBC[l][n];
        float a = __expf(dl * A);
        ap *= a;
        s = fmaf(a, s, (dl * ul) * Bn);
    }
    carryA[gid0 + tid] = ap;
    carryB[gid0 + tid] = s;
}

__global__ void scan_p2(const float* __restrict__ carryA, const float* __restrict__ carryB,
                        float* __restrict__ sin_) {
    int gid = blockIdx.x * blockDim.x + threadIdx.x;
    float s = 0.f;
    #pragma unroll
    for (int c = 0; c < NCHUNK; c++) {
        sin_[c * DN + gid] = s;
        s = fmaf(carryA[c * DN + gid], s, carryB[c * DN + gid]);
    }
}

__global__ void __launch_bounds__(256)
scan_p3(const float* __restrict__ delta, const float* __restrict__ u,
        const float* __restrict__ proj, const float* __restrict__ gres,
        const float* __restrict__ A_log, const float* __restrict__ Dv,
        const float* __restrict__ sin_, __half* __restrict__ yh) {
    __shared__ float sdel[CLEN][20];
    __shared__ float su[CLEN][20];
    __shared__ float sBC[CLEN][36];
    __shared__ float sres[CLEN][20];
    int tid = threadIdx.x;
    int gid0 = blockIdx.x * 256;
    int c = gid0 / DN;
    int r0 = gid0 - c * DN;
    int d0 = r0 >> 4;
    int l0 = c * CLEN;
    {
        int l = tid >> 2, seg = (tid & 3) * 4;
        *(float4*)&sdel[l][seg] = *(const float4*)(delta + (size_t)(l0 + l) * DI + d0 + seg);
        *(float4*)&su[l][seg]   = *(const float4*)(u     + (size_t)(l0 + l) * DI + d0 + seg);
        *(float4*)&sres[l][seg] = *(const float4*)(gres  + (size_t)(l0 + l) * DI + d0 + seg);
    }
    #pragma unroll
    for (int i = 0; i < 2; i++) {
        int q = tid + i * 256;
        int l = q >> 3, seg = (q & 7) * 4;
        *(float4*)&sBC[l][seg] = *(const float4*)(proj + (size_t)(l0 + l) * PROJW + DTR + seg);
    }
    __syncthreads();
    int j = tid >> 4, n = tid & 15;
    float A = -__expf(A_log[(d0 + j) * DS + n]);
    float Dd = Dv[d0 + j];
    float s = sin_[gid0 + tid];
    for (int l = 0; l < CLEN; l++) {
        float dl = sdel[l][j];
        float ul = su[l][j];
        float Bn = sBC[l][n];
        float Cn = sBC[l][16 + n];
        float a = __expf(dl * A);
        s = fmaf(a, s, (dl * ul) * Bn);
        float v = s * Cn;
        v += __shfl_xor_sync(0xffffffffu, v, 8, 16);
        v += __shfl_xor_sync(0xffffffffu, v, 4, 16);
        v += __shfl_xor_sync(0xffffffffu, v, 2, 16);
        v += __shfl_xor_sync(0xffffffffu, v, 1, 16);
        if (n == 0) {
            float res = sres[l][j];
            float g = res / (1.f + __expf(-res));
            yh[(size_t)(l0 + l) * DI + d0 + j] = __float2half((v + ul * Dd) * g);
        }
    }
}

// ---------------- host orchestration ----------------
extern "C" void kernel_launch(void* const* d_in, const int* in_sizes, int n_in,
                              void* d_out, int out_size) {
    const float* x_in      = (const float*)d_in[0];
    const float* in_proj_w = (const float*)d_in[1];
    const float* conv_w    = (const float*)d_in[2];
    const float* conv_b    = (const float*)d_in[3];
    const float* x_proj_w  = (const float*)d_in[4];
    const float* dt_proj_w = (const float*)d_in[5];
    const float* dt_proj_b = (const float*)d_in[6];
    const float* A_log     = (const float*)d_in[7];
    const float* Dv        = (const float*)d_in[8];
    const float* out_proj_w= (const float*)d_in[9];
    const float* norm_w    = (const float*)d_in[10];
    const float* norm_f_w  = (const float*)d_in[11];
    const float* head_w    = (const float*)d_in[12];
    float* out = (float*)d_out;

    float *gx, *gipp, *gxc, *gres, *gproj, *gprojp, *gdelta, *gyp, *gheadp, *gcA, *gcB, *gsin;
    __half *ipw16, *xpw16, *dtw16, *opw16, *hw16, *xn16, *xch, *projh, *yh;
    cudaGetSymbolAddress((void**)&gx,     g_x);
    cudaGetSymbolAddress((void**)&gipp,   g_ipp);
    cudaGetSymbolAddress((void**)&gxc,    g_xc);
    cudaGetSymbolAddress((void**)&gres,   g_res);
    cudaGetSymbolAddress((void**)&gproj,  g_proj);
    cudaGetSymbolAddress((void**)&gprojp, g_projp);
    cudaGetSymbolAddress((void**)&gdelta, g_delta);
    cudaGetSymbolAddress((void**)&gyp,    g_yp);
    cudaGetSymbolAddress((void**)&gheadp, g_headp);
    cudaGetSymbolAddress((void**)&gcA,    g_carryA);
    cudaGetSymbolAddress((void**)&gcB,    g_carryB);
    cudaGetSymbolAddress((void**)&gsin,   g_sin);
    cudaGetSymbolAddress((void**)&ipw16,  g_ipw16);
    cudaGetSymbolAddress((void**)&xpw16,  g_xpw16);
    cudaGetSymbolAddress((void**)&dtw16,  g_dtw16);
    cudaGetSymbolAddress((void**)&opw16,  g_opw16);
    cudaGetSymbolAddress((void**)&hw16,   g_hw16);
    cudaGetSymbolAddress((void**)&xn16,   g_xn16);
    cudaGetSymbolAddress((void**)&xch,    g_xch);
    cudaGetSymbolAddress((void**)&projh,  g_projh);
    cudaGetSymbolAddress((void**)&yh,     g_yh);

    cudaFuncSetAttribute(gemm_f16, cudaFuncAttributeMaxDynamicSharedMemorySize, GSMEM);

    {
        int n;
        n = NLAYER * 2 * DI * DM; f32tof16<<<(n/2 + 255)/256, 256>>>(in_proj_w, ipw16, n);
        n = NLAYER * PROJW * DI;  f32tof16<<<(n/2 + 255)/256, 256>>>(x_proj_w, xpw16, n);
        n = NLAYER * DI * DTR;    f32tof16<<<(n/2 + 255)/256, 256>>>(dt_proj_w, dtw16, n);
        n = NLAYER * DM * DI;     f32tof16<<<(n/2 + 255)/256, 256>>>(out_proj_w, opw16, n);
        n = OUTD * DM;            f32tof16<<<(n/2 + 255)/256, 256>>>(head_w, hw16, n);
    }

    copy_kernel<<<(LSEQ * DM + 255) / 256, 256>>>(x_in, gx, LSEQ * DM);
    resnorm16<<<LSEQ, 256>>>(nullptr, 0, 0, gx, norm_w, xn16);

    for (int i = 0; i < NLAYER; i++) {
        const __half* ipw = ipw16 + (size_t)i * 2 * DI * DM;
        const float*  cw  = conv_w     + (size_t)i * DI * DCONV;
        const float*  cb  = conv_b     + (size_t)i * DI;
        const __half* xpw = xpw16 + (size_t)i * PROJW * DI;
        const __half* dtw = dtw16 + (size_t)i * DI * DTR;
        const float*  dtb = dt_proj_b  + (size_t)i * DI;
        const float*  al  = A_log      + (size_t)i * DI * DS;
        const float*  dv  = Dv         + (size_t)i * DI;
        const __half* opw = opw16 + (size_t)i * DM * DI;

        // in_proj split-K x2 -> partials
        gemm_f16<<<dim3(2 * DI / TBN, LSEQ / TBM, ISPLIT), 256, GSMEM>>>(
            xn16, DM, ipw, DM, gipp, 2 * DI, 2 * DI, DM, nullptr, 0,
            DM / ISPLIT, (size_t)LSEQ * 2 * DI);
        // fused reduce + conv + silu + res extract
        fuse_conv<<<(LSEQ * DI + 255) / 256, 256>>>(gipp, cw, cb, gxc, xch, gres);

        // x_proj split-K x16
        gemm_f16<<<dim3(1, LSEQ / TBM, XSPLIT), 256, GSMEM>>>(
            xch, DI, xpw, DI, gprojp, PROJW, PROJW, DI, nullptr, 0,
            DI / XSPLIT, (size_t)LSEQ * PROJW);
        reduce_k_h<<<(LSEQ * PROJW + 255) / 256, 256>>>(
            gprojp, gproj, projh, LSEQ * PROJW, XSPLIT, (size_t)LSEQ * PROJW);

        // dt_proj + bias + softplus (K=48)
        gemm_f16<<<dim3(DI / TBN, LSEQ / TBM), 256, GSMEM>>>(
            projh, PROJW, dtw, DTR, gdelta, DI, DI, DTR, dtb, 1, 0, 0);

        // 3-phase parallel scan
        scan_p1<<<NCHUNK * DN / 256, 256>>>(gdelta, gxc, gproj, al, gcA, gcB);
        scan_p2<<<DN / 256, 256>>>(gcA, gcB, gsin);
        scan_p3<<<NCHUNK * DN / 256, 256>>>(gdelta, gxc, gproj, gres, al, dv, gsin, yh);

        // out_proj split-K x3 -> partials
        gemm_f16<<<dim3(DM / TBN, LSEQ / TBM, OSPLIT), 256, GSMEM>>>(
            yh, DI, opw, DI, gyp, DM, DM, DI, nullptr, 0,
            DI / OSPLIT, (size_t)LSEQ * DM);
        // fused residual-reduce + rmsnorm for next stage
        const float* nextw = (i + 1 < NLAYER) ? (norm_w + (size_t)(i + 1) * DM) : norm_f_w;
        resnorm16<<<LSEQ, 256>>>(gyp, OSPLIT, (size_t)LSEQ * DM, gx, nextw, xn16);
    }

    // head split-K x12
    gemm_f16<<<dim3(OUTD / TBN, LSEQ / TBM, HSPLIT), 256, GSMEM>>>(
        xn16, DM, hw16, DM, gheadp, OUTD, OUTD, DM, nullptr, 0,
        DM / HSPLIT, (size_t)LSEQ * OUTD);
    reduce_k<<<(LSEQ * OUTD + 255) / 256, 256>>>(
        gheadp, out, LSEQ * OUTD, HSPLIT, (size_t)LSEQ * OUTD);
}

// round 13
// speedup vs baseline: 7.3663x; 1.0099x over previous
#include <cuda_runtime.h>
#include <cuda_fp16.h>
#include <math.h>
#include <stdint.h>

#define LSEQ 2048
#define DM 768
#define DI 1536
#define DS 16
#define DTR 48
#define DCONV 4
#define OUTD 128
#define PROJW (DTR + 2*DS)   // 80
#define NLAYER 2
#define ISPLIT 2
#define XSPLIT 16
#define OSPLIT 3
#define HSPLIT 12
#define NCHUNK 32
#define CLEN (LSEQ / NCHUNK)   // 64
#define DN (DI * DS)           // 24576

// ---------------- scratch ----------------
__device__ float g_x[LSEQ*DM];
__device__ float g_ipp[ISPLIT*LSEQ*2*DI];
__device__ float g_xc[LSEQ*DI];
__device__ float g_res[LSEQ*DI];
__device__ float g_proj[LSEQ*PROJW];
__device__ float g_projp[XSPLIT*LSEQ*PROJW];
__device__ float g_delta[LSEQ*DI];
__device__ float g_yp[OSPLIT*LSEQ*DM];
__device__ float g_headp[HSPLIT*LSEQ*OUTD];
__device__ float g_carryA[NCHUNK*DN];
__device__ float g_carryB[NCHUNK*DN];
// fp16 weights + activations
__device__ __half g_ipw16[NLAYER*2*DI*DM];
__device__ __half g_xpw16[NLAYER*PROJW*DI];
__device__ __half g_dtw16[NLAYER*DI*DTR];
__device__ __half g_opw16[NLAYER*DM*DI];
__device__ __half g_hw16[OUTD*DM];
__device__ __half g_xn16[LSEQ*DM];
__device__ __half g_xch[LSEQ*DI];
__device__ __half g_projh[LSEQ*PROJW];
__device__ __half g_yh[LSEQ*DI];

__device__ __forceinline__ uint32_t smem_u32(const void* p) {
    uint32_t a;
    asm("{ .reg .u64 t; cvta.to.shared.u64 t, %1; cvt.u32.u64 %0, t; }" : "=r"(a) : "l"(p));
    return a;
}
__device__ __forceinline__ void ldsm_x4(uint32_t& r0, uint32_t& r1, uint32_t& r2, uint32_t& r3, uint32_t addr) {
    asm volatile("ldmatrix.sync.aligned.m8n8.x4.shared.b16 {%0,%1,%2,%3}, [%4];"
                 : "=r"(r0), "=r"(r1), "=r"(r2), "=r"(r3) : "r"(addr));
}
__device__ __forceinline__ void mma16816(float* c, const uint32_t* a, uint32_t b0, uint32_t b1) {
    asm volatile("mma.sync.aligned.m16n8k16.row.col.f32.f16.f16.f32 "
                 "{%0,%1,%2,%3}, {%4,%5,%6,%7}, {%8,%9}, {%0,%1,%2,%3};"
                 : "+f"(c[0]), "+f"(c[1]), "+f"(c[2]), "+f"(c[3])
                 : "r"(a[0]), "r"(a[1]), "r"(a[2]), "r"(a[3]), "r"(b0), "r"(b1));
}
__device__ __forceinline__ void cpasync16(uint32_t dst, const void* src, int sz) {
    asm volatile("cp.async.cg.shared.global [%0], [%1], 16, %2;"
                 :: "r"(dst), "l"(src), "r"(sz) : "memory");
}

// ---------------- fp16 cp.async tensor-core GEMM ----------------
#define TBM 128
#define TBN 128
#define TBK 32
#define APAD 40
#define ASTAGE (TBM * APAD * 2)
#define NSTAGE 4
#define GSMEM (NSTAGE * 2 * ASTAGE)   // 81920 B -> 2 CTAs/SM

__global__ void __launch_bounds__(256, 2)
gemm_f16(const __half* __restrict__ A, int lda,
         const __half* __restrict__ B, int ldb,
         float* __restrict__ C, int ldc,
         int N, int K, const float* __restrict__ bias, int mode,
         int kchunk, size_t czstride) {
    extern __shared__ __align__(16) char smem[];
    uint32_t sA = smem_u32(smem);
    uint32_t sB = sA + NSTAGE * ASTAGE;

    int t = threadIdx.x;
    int m0 = blockIdx.y * TBM, n0 = blockIdx.x * TBN;
    int wid = t >> 5, lane = t & 31;
    int wm = (wid & 1) * 64;
    int wn = (wid >> 1) * 32;

    int kbeg = 0, kend = K;
    if (kchunk > 0) {
        kbeg = blockIdx.z * kchunk;
        kend = min(kbeg + kchunk, K);
        C += (size_t)blockIdx.z * czstride;
    }
    int Klocal = kend - kbeg;
    int nk = (Klocal + TBK - 1) / TBK;

    int a_row = wm + (lane & 15);
    int a_koff = (lane >> 4) << 3;
    int b_row = wn + ((lane >> 4) << 3) + (lane & 7);
    int b_koff = lane & 8;

    float acc[4][4][4];
    #pragma unroll
    for (int i = 0; i < 4; i++)
        #pragma unroll
        for (int j = 0; j < 4; j++)
            #pragma unroll
            for (int q = 0; q < 4; q++) acc[i][j][q] = 0.f;

    auto issue = [&](int kt) {
        if (kt < nk) {
            int buf = kt & (NSTAGE - 1);
            #pragma unroll
            for (int i = 0; i < 2; i++) {
                int idx = t + i * 256;
                int row = idx >> 2, ch = idx & 3;
                int kOff = kt * TBK + ch * 8;
                int szA = (Klocal - kOff) * 2;
                szA = szA < 0 ? 0 : (szA > 16 ? 16 : szA);
                uint32_t doff = (uint32_t)buf * ASTAGE + (uint32_t)(row * APAD + ch * 8) * 2;
                const __half* srcA = (szA > 0) ? (A + (size_t)(m0 + row) * lda + kbeg + kOff) : A;
                cpasync16(sA + doff, srcA, szA);
                int brow = n0 + row;
                int szB = (brow < N) ? szA : 0;
                const __half* srcB = (szB > 0) ? (B + (size_t)brow * ldb + kbeg + kOff) : B;
                cpasync16(sB + doff, srcB, szB);
            }
        }
        asm volatile("cp.async.commit_group;" ::: "memory");
    };

    issue(0);
    issue(1);
    issue(2);

    for (int kt = 0; kt < nk; kt++) {
        int buf = kt & (NSTAGE - 1);
        asm volatile("cp.async.wait_group 2;" ::: "memory");
        __syncthreads();
        uint32_t aBase = sA + buf * ASTAGE;
        uint32_t bBase = sB + buf * ASTAGE;
        #pragma unroll
        for (int k16 = 0; k16 < 2; k16++) {
            uint32_t af[4][4];
            #pragma unroll
            for (int mt = 0; mt < 4; mt++) {
                uint32_t addr = aBase + ((a_row + mt * 16) * APAD + k16 * 16 + a_koff) * 2;
                ldsm_x4(af[mt][0], af[mt][1], af[mt][2], af[mt][3], addr);
            }
            uint32_t bf[4][2];
            #pragma unroll
            for (int np = 0; np < 2; np++) {
                uint32_t addr = bBase + ((b_row + np * 16) * APAD + k16 * 16 + b_koff) * 2;
                uint32_t r0, r1, r2, r3;
                ldsm_x4(r0, r1, r2, r3, addr);
                bf[np * 2 + 0][0] = r0; bf[np * 2 + 0][1] = r1;
                bf[np * 2 + 1][0] = r2; bf[np * 2 + 1][1] = r3;
            }
            #pragma unroll
            for (int mt = 0; mt < 4; mt++)
                #pragma unroll
                for (int nt = 0; nt < 4; nt++)
                    mma16816(acc[mt][nt], af[mt], bf[nt][0], bf[nt][1]);
        }
        issue(kt + 3);
    }

    int qr = lane >> 2;
    int qc = (lane & 3) * 2;
    #pragma unroll
    for (int mt = 0; mt < 4; mt++) {
        #pragma unroll
        for (int nt = 0; nt < 4; nt++) {
            int cb = n0 + wn + nt * 8;
            if (cb >= N) continue;
            int c = cb + qc;
            int r0 = m0 + wm + mt * 16 + qr;
            float* p0 = C + (size_t)r0 * ldc + c;
            float* p1 = C + (size_t)(r0 + 8) * ldc + c;
            float v0 = acc[mt][nt][0], v1 = acc[mt][nt][1];
            float v2 = acc[mt][nt][2], v3 = acc[mt][nt][3];
            if (mode == 1) {
                float b0 = bias[c], b1 = bias[c + 1];
                v0 += b0; v1 += b1; v2 += b0; v3 += b1;
                v0 = (v0 > 20.f) ? v0 : log1pf(__expf(v0));
                v1 = (v1 > 20.f) ? v1 : log1pf(__expf(v1));
                v2 = (v2 > 20.f) ? v2 : log1pf(__expf(v2));
                v3 = (v3 > 20.f) ? v3 : log1pf(__expf(v3));
            }
            p0[0] = v0; p0[1] = v1;
            p1[0] = v2; p1[1] = v3;
        }
    }
}

// ---------------- fused kernels ----------------
// all 5 weight conversions in one launch
__global__ void convert_all(const float* __restrict__ s1, int n1,
                            const float* __restrict__ s2, int n2,
                            const float* __restrict__ s3, int n3,
                            const float* __restrict__ s4, int n4,
                            const float* __restrict__ s5, int n5,
                            __half* __restrict__ d1, __half* __restrict__ d2,
                            __half* __restrict__ d3, __half* __restrict__ d4,
                            __half* __restrict__ d5) {
    int i = (blockIdx.x * blockDim.x + threadIdx.x) * 2;
    const float* s; __half* d;
    if (i < n1) { s = s1; d = d1; }
    else if ((i -= n1) < n2) { s = s2; d = d2; }
    else if ((i -= n2) < n3) { s = s3; d = d3; }
    else if ((i -= n3) < n4) { s = s4; d = d4; }
    else if ((i -= n4) < n5) { s = s5; d = d5; }
    else return;
    float2 v = *(const float2*)(s + i);
    *(__half2*)(d + i) = __floats2half2_rn(v.x, v.y);
}

__global__ void reduce_k(const float* __restrict__ part, float* __restrict__ out,
                         int n, int nz, size_t stride) {
    int i = blockIdx.x * blockDim.x + threadIdx.x;
    if (i >= n) return;
    float s = 0.f;
    for (int z = 0; z < nz; z++) s += part[(size_t)z * stride + i];
    out[i] = s;
}
__global__ void reduce_k_h(const float* __restrict__ part, float* __restrict__ out,
                           __half* __restrict__ outh, int n, int nz, size_t stride) {
    int i = blockIdx.x * blockDim.x + threadIdx.x;
    if (i >= n) return;
    float s = 0.f;
    for (int z = 0; z < nz; z++) s += part[(size_t)z * stride + i];
    out[i] = s;
    outh[i] = __float2half(s);
}

// fused: residual += split-K partials (or initial copy from src when nz==0),
// then rmsnorm -> fp16 normed row. Always (re)writes gx.
__global__ void __launch_bounds__(256)
resnorm16(const float* __restrict__ part, int nz, size_t stride,
          const float* __restrict__ src,
          float* __restrict__ gx, const float* __restrict__ w,
          __half* __restrict__ out) {
    int l = blockIdx.x;
    int tid = threadIdx.x;
    __shared__ float red[8];
    __shared__ float s_r;
    float vals[3];
    float ss = 0.f;
    #pragma unroll
    for (int i = 0; i < 3; i++) {
        int c = tid + i * 256;
        size_t o = (size_t)l * DM + c;
        float s;
        if (nz == 0) {
            s = src[o];
        } else {
            s = gx[o];
            for (int z = 0; z < nz; z++) s += part[(size_t)z * stride + o];
        }
        vals[i] = s;
        ss += s * s;
    }
    #pragma unroll
    for (int o = 16; o; o >>= 1) ss += __shfl_xor_sync(0xffffffffu, ss, o);
    if ((tid & 31) == 0) red[tid >> 5] = ss;
    __syncthreads();
    if (tid == 0) {
        float tt = 0.f;
        #pragma unroll
        for (int i = 0; i < 8; i++) tt += red[i];
        s_r = rsqrtf(tt / DM + 1e-5f);
    }
    __syncthreads();
    float r = s_r;
    #pragma unroll
    for (int i = 0; i < 3; i++) {
        int c = tid + i * 256;
        size_t o = (size_t)l * DM + c;
        gx[o] = vals[i];
        out[o] = __float2half(vals[i] * r * w[c]);
    }
}

// fused + tiled: in_proj partial-sum + causal conv + silu + res extraction
// block: 256 channels x 32 l-steps; stages summed partials in smem
#define CT_L 32
#define CT_C 256
__global__ void __launch_bounds__(256)
fuse_conv(const float* __restrict__ p, const float* __restrict__ w,
          const float* __restrict__ b, float* __restrict__ gxc,
          __half* __restrict__ xch, float* __restrict__ gres) {
    __shared__ float xs[CT_L + 3][CT_C];
    int tid = threadIdx.x;
    int cblk = blockIdx.x % (DI / CT_C);
    int lblk = blockIdx.x / (DI / CT_C);
    int c0 = cblk * CT_C;
    int l0 = lblk * CT_L;
    const size_t S = (size_t)LSEQ * 2 * DI;
    // stage rows l0-3 .. l0+CT_L-1 (summed partials, conv-input half)
    #pragma unroll 5
    for (int r = 0; r < CT_L + 3; r++) {
        int l = l0 - 3 + r;
        float v = 0.f;
        if (l >= 0) {
            size_t o = (size_t)l * 2 * DI + c0 + tid;
            v = p[o] + p[S + o];
        }
        xs[r][tid] = v;
    }
    __syncthreads();
    int c = c0 + tid;
    float w0 = w[c * 4], w1 = w[c * 4 + 1], w2 = w[c * 4 + 2], w3 = w[c * 4 + 3];
    float bc = b[c];
    #pragma unroll 4
    for (int i = 0; i < CT_L; i++) {
        int l = l0 + i;
        // same order as reference loop: b + w0*x[l-3] + w1*x[l-2] + w2*x[l-1] + w3*x[l]
        float acc = bc;
        acc += w0 * xs[i][tid];
        acc += w1 * xs[i + 1][tid];
        acc += w2 * xs[i + 2][tid];
        acc += w3 * xs[i + 3][tid];
        float v = acc / (1.f + __expf(-acc));
        size_t o = (size_t)l * DI + c;
        gxc[o] = v;
        xch[o] = __float2half(v);
        size_t ro = (size_t)l * 2 * DI + DI + c;
        gres[o] = p[ro] + p[S + ro];
    }
}

// ---------------- parallel scan (p1 + self-prefix p3) ----------------
__global__ void __launch_bounds__(256)
scan_p1(const float* __restrict__ delta, const float* __restrict__ u,
        const float* __restrict__ proj, const float* __restrict__ A_log,
        float* __restrict__ carryA, float* __restrict__ carryB) {
    __shared__ float sdel[CLEN][20];
    __shared__ float su[CLEN][20];
    __shared__ float sBC[CLEN][36];
    int tid = threadIdx.x;
    int gid0 = blockIdx.x * 256;
    int c = gid0 / DN;
    int r0 = gid0 - c * DN;
    int d0 = r0 >> 4;
    int l0 = c * CLEN;
    {
        int l = tid >> 2, seg = (tid & 3) * 4;
        *(float4*)&sdel[l][seg] = *(const float4*)(delta + (size_t)(l0 + l) * DI + d0 + seg);
        *(float4*)&su[l][seg]   = *(const float4*)(u     + (size_t)(l0 + l) * DI + d0 + seg);
    }
    #pragma unroll
    for (int i = 0; i < 2; i++) {
        int q = tid + i * 256;
        int l = q >> 3, seg = (q & 7) * 4;
        *(float4*)&sBC[l][seg] = *(const float4*)(proj + (size_t)(l0 + l) * PROJW + DTR + seg);
    }
    __syncthreads();
    int j = tid >> 4, n = tid & 15;
    float A = -__expf(A_log[(d0 + j) * DS + n]);
    float ap = 1.f, s = 0.f;
    #pragma unroll 4
    for (int l = 0; l < CLEN; l++) {
        float dl = sdel[l][j];
        float ul = su[l][j];
        float Bn = sBC[l][n];
        float a = __expf(dl * A);
        ap *= a;
        s = fmaf(a, s, (dl * ul) * Bn);
    }
    carryA[gid0 + tid] = ap;
    carryB[gid0 + tid] = s;
}

__global__ void __launch_bounds__(256)
scan_p3(const float* __restrict__ delta, const float* __restrict__ u,
        const float* __restrict__ proj, const float* __restrict__ gres,
        const float* __restrict__ A_log, const float* __restrict__ Dv,
        const float* __restrict__ carryA, const float* __restrict__ carryB,
        __half* __restrict__ yh) {
    __shared__ float sdel[CLEN][20];
    __shared__ float su[CLEN][20];
    __shared__ float sBC[CLEN][36];
    __shared__ float sres[CLEN][20];
    int tid = threadIdx.x;
    int gid0 = blockIdx.x * 256;
    int c = gid0 / DN;
    int r0 = gid0 - c * DN;
    int d0 = r0 >> 4;
    int l0 = c * CLEN;
    // self-computed prefix over chunks [0, c)
    float s = 0.f;
    for (int z = 0; z < c; z++) {
        int o = z * DN + r0 + tid;
        s = fmaf(carryA[o], s, carryB[o]);
    }
    {
        int l = tid >> 2, seg = (tid & 3) * 4;
        *(float4*)&sdel[l][seg] = *(const float4*)(delta + (size_t)(l0 + l) * DI + d0 + seg);
        *(float4*)&su[l][seg]   = *(const float4*)(u     + (size_t)(l0 + l) * DI + d0 + seg);
        *(float4*)&sres[l][seg] = *(const float4*)(gres  + (size_t)(l0 + l) * DI + d0 + seg);
    }
    #pragma unroll
    for (int i = 0; i < 2; i++) {
        int q = tid + i * 256;
        int l = q >> 3, seg = (q & 7) * 4;
        *(float4*)&sBC[l][seg] = *(const float4*)(proj + (size_t)(l0 + l) * PROJW + DTR + seg);
    }
    __syncthreads();
    int j = tid >> 4, n = tid & 15;
    float A = -__expf(A_log[(d0 + j) * DS + n]);
    float Dd = Dv[d0 + j];
    for (int l = 0; l < CLEN; l++) {
        float dl = sdel[l][j];
        float ul = su[l][j];
        float Bn = sBC[l][n];
        float Cn = sBC[l][16 + n];
        float a = __expf(dl * A);
        s = fmaf(a, s, (dl * ul) * Bn);
        float v = s * Cn;
        v += __shfl_xor_sync(0xffffffffu, v, 8, 16);
        v += __shfl_xor_sync(0xffffffffu, v, 4, 16);
        v += __shfl_xor_sync(0xffffffffu, v, 2, 16);
        v += __shfl_xor_sync(0xffffffffu, v, 1, 16);
        if (n == 0) {
            float res = sres[l][j];
            float g = res / (1.f + __expf(-res));
            yh[(size_t)(l0 + l) * DI + d0 + j] = __float2half((v + ul * Dd) * g);
        }
    }
}

// ---------------- host orchestration ----------------
extern "C" void kernel_launch(void* const* d_in, const int* in_sizes, int n_in,
                              void* d_out, int out_size) {
    const float* x_in      = (const float*)d_in[0];
    const float* in_proj_w = (const float*)d_in[1];
    const float* conv_w    = (const float*)d_in[2];
    const float* conv_b    = (const float*)d_in[3];
    const float* x_proj_w  = (const float*)d_in[4];
    const float* dt_proj_w = (const float*)d_in[5];
    const float* dt_proj_b = (const float*)d_in[6];
    const float* A_log     = (const float*)d_in[7];
    const float* Dv        = (const float*)d_in[8];
    const float* out_proj_w= (const float*)d_in[9];
    const float* norm_w    = (const float*)d_in[10];
    const float* norm_f_w  = (const float*)d_in[11];
    const float* head_w    = (const float*)d_in[12];
    float* out = (float*)d_out;

    float *gx, *gipp, *gxc, *gres, *gproj, *gprojp, *gdelta, *gyp, *gheadp, *gcA, *gcB;
    __half *ipw16, *xpw16, *dtw16, *opw16, *hw16, *xn16, *xch, *projh, *yh;
    cudaGetSymbolAddress((void**)&gx,     g_x);
    cudaGetSymbolAddress((void**)&gipp,   g_ipp);
    cudaGetSymbolAddress((void**)&gxc,    g_xc);
    cudaGetSymbolAddress((void**)&gres,   g_res);
    cudaGetSymbolAddress((void**)&gproj,  g_proj);
    cudaGetSymbolAddress((void**)&gprojp, g_projp);
    cudaGetSymbolAddress((void**)&gdelta, g_delta);
    cudaGetSymbolAddress((void**)&gyp,    g_yp);
    cudaGetSymbolAddress((void**)&gheadp, g_headp);
    cudaGetSymbolAddress((void**)&gcA,    g_carryA);
    cudaGetSymbolAddress((void**)&gcB,    g_carryB);
    cudaGetSymbolAddress((void**)&ipw16,  g_ipw16);
    cudaGetSymbolAddress((void**)&xpw16,  g_xpw16);
    cudaGetSymbolAddress((void**)&dtw16,  g_dtw16);
    cudaGetSymbolAddress((void**)&opw16,  g_opw16);
    cudaGetSymbolAddress((void**)&hw16,   g_hw16);
    cudaGetSymbolAddress((void**)&xn16,   g_xn16);
    cudaGetSymbolAddress((void**)&xch,    g_xch);
    cudaGetSymbolAddress((void**)&projh,  g_projh);
    cudaGetSymbolAddress((void**)&yh,     g_yh);

    cudaFuncSetAttribute(gemm_f16, cudaFuncAttributeMaxDynamicSharedMemorySize, GSMEM);

    // all weight conversions in one launch
    {
        int n1 = NLAYER * 2 * DI * DM;
        int n2 = NLAYER * PROJW * DI;
        int n3 = NLAYER * DI * DTR;
        int n4 = NLAYER * DM * DI;
        int n5 = OUTD * DM;
        int total = n1 + n2 + n3 + n4 + n5;
        convert_all<<<(total / 2 + 255) / 256, 256>>>(
            in_proj_w, n1, x_proj_w, n2, dt_proj_w, n3, out_proj_w, n4, head_w, n5,
            ipw16, xpw16, dtw16, opw16, hw16);
    }

    // initial: copy x_in into gx + rmsnorm -> xn16 (one kernel)
    resnorm16<<<LSEQ, 256>>>(nullptr, 0, 0, x_in, gx, norm_w, xn16);

    for (int i = 0; i < NLAYER; i++) {
        const __half* ipw = ipw16 + (size_t)i * 2 * DI * DM;
        const float*  cw  = conv_w     + (size_t)i * DI * DCONV;
        const float*  cb  = conv_b     + (size_t)i * DI;
        const __half* xpw = xpw16 + (size_t)i * PROJW * DI;
        const __half* dtw = dtw16 + (size_t)i * DI * DTR;
        const float*  dtb = dt_proj_b  + (size_t)i * DI;
        const float*  al  = A_log      + (size_t)i * DI * DS;
        const float*  dv  = Dv         + (size_t)i * DI;
        const __half* opw = opw16 + (size_t)i * DM * DI;

        // in_proj split-K x2 -> partials
        gemm_f16<<<dim3(2 * DI / TBN, LSEQ / TBM, ISPLIT), 256, GSMEM>>>(
            xn16, DM, ipw, DM, gipp, 2 * DI, 2 * DI, DM, nullptr, 0,
            DM / ISPLIT, (size_t)LSEQ * 2 * DI);
        // fused tiled reduce + conv + silu + res extract
        fuse_conv<<<(DI / CT_C) * (LSEQ / CT_L), 256>>>(gipp, cw, cb, gxc, xch, gres);

        // x_proj split-K x16
        gemm_f16<<<dim3(1, LSEQ / TBM, XSPLIT), 256, GSMEM>>>(
            xch, DI, xpw, DI, gprojp, PROJW, PROJW, DI, nullptr, 0,
            DI / XSPLIT, (size_t)LSEQ * PROJW);
        reduce_k_h<<<(LSEQ * PROJW + 255) / 256, 256>>>(
            gprojp, gproj, projh, LSEQ * PROJW, XSPLIT, (size_t)LSEQ * PROJW);

        // dt_proj + bias + softplus (K=48)
        gemm_f16<<<dim3(DI / TBN, LSEQ / TBM), 256, GSMEM>>>(
            projh, PROJW, dtw, DTR, gdelta, DI, DI, DTR, dtb, 1, 0, 0);

        // parallel scan: p1 then p3 (p3 self-computes its chunk prefix)
        scan_p1<<<NCHUNK * DN / 256, 256>>>(gdelta, gxc, gproj, al, gcA, gcB);
        scan_p3<<<NCHUNK * DN / 256, 256>>>(gdelta, gxc, gproj, gres, al, dv, gcA, gcB, yh);

        // out_proj split-K x3 -> partials
        gemm_f16<<<dim3(DM / TBN, LSEQ / TBM, OSPLIT), 256, GSMEM>>>(
            yh, DI, opw, DI, gyp, DM, DM, DI, nullptr, 0,
            DI / OSPLIT, (size_t)LSEQ * DM);
        // fused residual-reduce + rmsnorm for next stage
        const float* nextw = (i + 1 < NLAYER) ? (norm_w + (size_t)(i + 1) * DM) : norm_f_w;
        resnorm16<<<LSEQ, 256>>>(gyp, OSPLIT, (size_t)LSEQ * DM, nullptr, gx, nextw, xn16);
    }

    // head split-K x12
    gemm_f16<<<dim3(OUTD / TBN, LSEQ / TBM, HSPLIT), 256, GSMEM>>>(
        xn16, DM, hw16, DM, gheadp, OUTD, OUTD, DM, nullptr, 0,
        DM / HSPLIT, (size_t)LSEQ * OUTD);
    reduce_k<<<(LSEQ * OUTD + 255) / 256, 256>>>(
        gheadp, out, LSEQ * OUTD, HSPLIT, (size_t)LSEQ * OUTD);
}